// round 4
// baseline (speedup 1.0000x reference)
#include <cuda_runtime.h>
#include <cuda_bf16.h>
#include <math.h>
#include <stdint.h>

// Swin-V2 shifted-window MHA, fused per-window kernel with split-bf16 MMA GEMMs.
// B=512, HIMG=WIMG=16, D=256, HEADS=8, HD=32, WIN=8, N=64, NW=4, SHIFT=4.
// One CTA (256 threads = 8 warps) per window; 2048 CTAs.

#define XSTR 132   // u32 (bf16-pair) row stride for split tiles (bank = lane, conflict-free)
#define FSTR 260   // fp32 row stride for Q/K/V/O tiles
#define WSTR 12    // u32 row stride for staged weight tiles (8 data + 4 pad)

// SMEM layout in 4-byte units
#define OFF_XH   0            // x hi pairs  64x132          (8448)   } R0: later V fp32 (16640)
#define OFF_XL   8448         // x lo pairs                  (8448)   }
#define OFF_Q    16896        // Q fp32 -> O fp32            (16640)
#define OFF_K    33536        // K fp32                      (16640)  } R2: later OH/OL
#define OFF_OH   33536        //   O hi pairs (8448)
#define OFF_OL   41984        //   O lo pairs (8448)
#define OFF_WTH  50432        // staged W hi tile 256x12     (3072)  / bias table (1800)
#define OFF_WTL  53504        // staged W lo tile            (3072)
#define OFF_GID  56576        // token group ids             (64)
#define SMEM_U32 56640        // 226560 bytes

__device__ uint32_t g_wh[4 * 256 * 128];  // pre-split weights: hi bf16 pairs, [w][n][kpair]
__device__ uint32_t g_wl[4 * 256 * 128];  // lo bf16 pairs
__device__ float    g_tab[225 * 8];       // 16*sigmoid(CPB-MLP table), [cell][head]

// ---------------------------------------------------------------------------
__device__ __forceinline__ uint32_t pack2(__nv_bfloat16 a, __nv_bfloat16 b) {
    return (uint32_t)__bfloat16_as_ushort(a) | ((uint32_t)__bfloat16_as_ushort(b) << 16);
}
__device__ __forceinline__ void split2(float x, float y, uint32_t& h, uint32_t& l) {
    __nv_bfloat16 hx = __float2bfloat16_rn(x), hy = __float2bfloat16_rn(y);
    float rx = x - __bfloat162float(hx), ry = y - __bfloat162float(hy);
    h = pack2(hx, hy);
    l = pack2(__float2bfloat16_rn(rx), __float2bfloat16_rn(ry));
}

#define MMA16816(C, A0, A1, A2, A3, B0, B1)                                   \
    asm volatile("mma.sync.aligned.m16n8k16.row.col.f32.bf16.bf16.f32 "       \
                 "{%0,%1,%2,%3}, {%4,%5,%6,%7}, {%8,%9}, {%0,%1,%2,%3};"      \
                 : "+f"(C[0]), "+f"(C[1]), "+f"(C[2]), "+f"(C[3])             \
                 : "r"(A0), "r"(A1), "r"(A2), "r"(A3), "r"(B0), "r"(B1))

// ---------------------------------------------------------------------------
// Kernel 1: continuous position bias table. 225 blocks x 256 threads.
// ---------------------------------------------------------------------------
__global__ void cpb_kernel(const float* __restrict__ w1,   // [512,2]
                           const float* __restrict__ b1,   // [512]
                           const float* __restrict__ w2)   // [8,512]
{
    int t = threadIdx.x;
    int cell = blockIdx.x;            // 0..224
    int a = cell / 15, b = cell % 15;
    float ra = (a - 7) * (8.0f / 7.0f);
    float rb = (b - 7) * (8.0f / 7.0f);
    float va = (ra >= 0.f ? 1.f : -1.f) * log2f(fabsf(ra) + 1.f) * (1.f / 3.f);
    float vb = (rb >= 0.f ? 1.f : -1.f) * log2f(fabsf(rb) + 1.f) * (1.f / 3.f);

    int j1 = t, j2 = t + 256;
    float h1 = fmaxf(va * w1[j1 * 2] + vb * w1[j1 * 2 + 1] + b1[j1], 0.f);
    float h2 = fmaxf(va * w1[j2 * 2] + vb * w1[j2 * 2 + 1] + b1[j2], 0.f);

    float p[8];
#pragma unroll
    for (int h = 0; h < 8; h++)
        p[h] = h1 * w2[h * 512 + j1] + h2 * w2[h * 512 + j2];
#pragma unroll
    for (int h = 0; h < 8; h++)
#pragma unroll
        for (int off = 16; off; off >>= 1)
            p[h] += __shfl_xor_sync(0xffffffffu, p[h], off);

    __shared__ float ws[8][8];
    int warp = t >> 5, lane = t & 31;
    if (lane == 0) {
#pragma unroll
        for (int h = 0; h < 8; h++) ws[warp][h] = p[h];
    }
    __syncthreads();
    if (t < 8) {
        float s = 0.f;
#pragma unroll
        for (int w = 0; w < 8; w++) s += ws[w][t];
        g_tab[cell * 8 + t] = 16.f / (1.f + expf(-s));
    }
}

// ---------------------------------------------------------------------------
// Kernel 2: pre-split weights into bf16 hi/lo pair tables.
// grid = 64 (4 weights x 16 segments), 256 threads.
// ---------------------------------------------------------------------------
__global__ void wsplit_kernel(const float* __restrict__ wq,
                              const float* __restrict__ wk,
                              const float* __restrict__ wv,
                              const float* __restrict__ wo)
{
    const float* ws[4] = {wq, wk, wv, wo};
    int t = threadIdx.x;
    int wsel = blockIdx.x >> 4;
    int seg  = blockIdx.x & 15;
    const float* w = ws[wsel];
    uint32_t* gh = g_wh + wsel * 32768;
    uint32_t* gl = g_wl + wsel * 32768;
#pragma unroll
    for (int i = 0; i < 4; i++) {
        int f4 = seg * 1024 + i * 256 + t;    // float4 index in [0,16384)
        int n = f4 >> 6, q = f4 & 63;
        float4 v = *reinterpret_cast<const float4*>(&w[n * 256 + q * 4]);
        uint32_t h0, l0, h1, l1;
        split2(v.x, v.y, h0, l0);
        split2(v.z, v.w, h1, l1);
        gh[n * 128 + 2 * q]     = h0;
        gh[n * 128 + 2 * q + 1] = h1;
        gl[n * 128 + 2 * q]     = l0;
        gl[n * 128 + 2 * q + 1] = l1;
    }
}

// ---------------------------------------------------------------------------
// Split-bf16 64x256 @ 256x256^T GEMM via mma.sync m16n8k16.
// A (split pairs) in smem at xh/xl; W pre-split in global gwh/gwl; staged per
// 16-wide k-chunk into wtH/wtL. acc[16][4] = 16x128 per warp
// (rows warpM*16 + gid/+8, cols warpN*128 + nf*8 + 2*tg/+1).
// Ends with __syncthreads (A reads and WT reads complete).
// ---------------------------------------------------------------------------
__device__ __forceinline__ void gemm_mma(
    const uint32_t* __restrict__ xh, const uint32_t* __restrict__ xl,
    const uint32_t* __restrict__ gwh, const uint32_t* __restrict__ gwl,
    uint32_t* __restrict__ wtH, uint32_t* __restrict__ wtL,
    float acc[16][4], int warpM, int warpN, int lane, int t)
{
#pragma unroll
    for (int nf = 0; nf < 16; nf++)
#pragma unroll
        for (int j = 0; j < 4; j++) acc[nf][j] = 0.f;

    const int gid = lane >> 2, tg = lane & 3;
    const uint32_t* xha = xh + (warpM * 16 + gid) * XSTR + tg;
    const uint32_t* xla = xl + (warpM * 16 + gid) * XSTR + tg;

    // per-thread staging registers (software pipeline over k-chunks)
    uint4 rh[2], rl[2];
    const int n0 = (t + 0)   >> 1, q0 = (t + 0)   & 1;
    const int n1 = (t + 256) >> 1, q1 = (t + 256) & 1;
    rh[0] = *reinterpret_cast<const uint4*>(gwh + n0 * 128 + q0 * 4);
    rh[1] = *reinterpret_cast<const uint4*>(gwh + n1 * 128 + q1 * 4);
    rl[0] = *reinterpret_cast<const uint4*>(gwl + n0 * 128 + q0 * 4);
    rl[1] = *reinterpret_cast<const uint4*>(gwl + n1 * 128 + q1 * 4);

#pragma unroll 1
    for (int kc = 0; kc < 16; kc++) {
        __syncthreads();   // WT free (previous chunk consumed / prior user done)
        *reinterpret_cast<uint4*>(wtH + n0 * WSTR + q0 * 4) = rh[0];
        *reinterpret_cast<uint4*>(wtH + n1 * WSTR + q1 * 4) = rh[1];
        *reinterpret_cast<uint4*>(wtL + n0 * WSTR + q0 * 4) = rl[0];
        *reinterpret_cast<uint4*>(wtL + n1 * WSTR + q1 * 4) = rl[1];
        __syncthreads();   // WT ready

        // prefetch next chunk (overlaps with MMAs below)
        int kn = (kc < 15) ? kc + 1 : 15;
        rh[0] = *reinterpret_cast<const uint4*>(gwh + n0 * 128 + kn * 8 + q0 * 4);
        rh[1] = *reinterpret_cast<const uint4*>(gwh + n1 * 128 + kn * 8 + q1 * 4);
        rl[0] = *reinterpret_cast<const uint4*>(gwl + n0 * 128 + kn * 8 + q0 * 4);
        rl[1] = *reinterpret_cast<const uint4*>(gwl + n1 * 128 + kn * 8 + q1 * 4);

        uint32_t a0 = xha[kc * 8],                 a1 = xha[kc * 8 + 8 * XSTR];
        uint32_t a2 = xha[kc * 8 + 4],             a3 = xha[kc * 8 + 4 + 8 * XSTR];
        uint32_t l0 = xla[kc * 8],                 l1 = xla[kc * 8 + 8 * XSTR];
        uint32_t l2 = xla[kc * 8 + 4],             l3 = xla[kc * 8 + 4 + 8 * XSTR];

#pragma unroll
        for (int nf = 0; nf < 16; nf++) {
            int nb = (warpN * 128 + nf * 8 + gid) * WSTR + tg;
            uint32_t b0 = wtH[nb], b1 = wtH[nb + 4];
            uint32_t c0 = wtL[nb], c1 = wtL[nb + 4];
            MMA16816(acc[nf], a0, a1, a2, a3, b0, b1);   // Ah * Bh
            MMA16816(acc[nf], l0, l1, l2, l3, b0, b1);   // Al * Bh
            MMA16816(acc[nf], a0, a1, a2, a3, c0, c1);   // Ah * Bl
        }
    }
    __syncthreads();
}

// ---------------------------------------------------------------------------
// Main fused kernel. grid = 2048 (b*4 + wh*2 + ww), block = 256.
// ---------------------------------------------------------------------------
__global__ __launch_bounds__(256, 1)
void swin_kernel(const float* __restrict__ img,
                 const float* __restrict__ bq, const float* __restrict__ bk,
                 const float* __restrict__ bv, const float* __restrict__ bo,
                 const float* __restrict__ logit_scale,
                 float* __restrict__ out)
{
    extern __shared__ float sm[];
    uint32_t* XH = (uint32_t*)(sm + OFF_XH);
    uint32_t* XL = (uint32_t*)(sm + OFF_XL);
    float*    V  = sm + OFF_XH;           // V fp32 overlays XH/XL
    float*    Q  = sm + OFF_Q;            // Q -> O fp32
    float*    K  = sm + OFF_K;
    uint32_t* OH = (uint32_t*)(sm + OFF_OH);   // overlays K
    uint32_t* OL = (uint32_t*)(sm + OFF_OL);
    uint32_t* WTH = (uint32_t*)(sm + OFF_WTH);
    uint32_t* WTL = (uint32_t*)(sm + OFF_WTL);
    float*    TAB = sm + OFF_WTH;         // bias table overlays WT during attention
    int*      GID = (int*)(sm + OFF_GID);

    const int t    = threadIdx.x;
    const int lane = t & 31;
    const int warp = t >> 5;
    const int warpM = warp & 3, warpN = warp >> 2;
    const int gid = lane >> 2, tg = lane & 3;
    const int blk = blockIdx.x;
    const int b   = blk >> 2;
    const int wh  = (blk >> 1) & 1, ww = blk & 1;

    // ---- load shifted window and split to bf16 hi/lo pairs
    const float* imgb = img + (size_t)b * (16 * 16 * 256);
#pragma unroll
    for (int i = 0; i < 16; i++) {
        int f = i * 256 + t;            // float4 index
        int tok = f >> 6, c4 = f & 63;
        int r = tok >> 3, c = tok & 7;
        int ih = (wh * 8 + r + 12) & 15;
        int iw = (ww * 8 + c + 12) & 15;
        float4 v = *reinterpret_cast<const float4*>(&imgb[(ih * 16 + iw) * 256 + c4 * 4]);
        uint32_t h0, l0, h1, l1;
        split2(v.x, v.y, h0, l0);
        split2(v.z, v.w, h1, l1);
        XH[tok * XSTR + 2 * c4]     = h0;
        XH[tok * XSTR + 2 * c4 + 1] = h1;
        XL[tok * XSTR + 2 * c4]     = l0;
        XL[tok * XSTR + 2 * c4 + 1] = l1;
    }
    if (t < 64) {  // token shift-mask group ids
        int r = t >> 3, c = t & 7;
        int gh = wh * 8 + r, gw = ww * 8 + c;
        int hg = (gh < 8) ? 0 : (gh < 12 ? 1 : 2);
        int wg = (gw < 8) ? 0 : (gw < 12 ? 1 : 2);
        GID[t] = hg * 3 + wg;
    }
    // no explicit sync needed: gemm_mma's internal barriers precede A-frag reads

    float acc[16][4];

    // ---- Q = x @ wq^T + bq
    gemm_mma(XH, XL, g_wh + 0 * 32768, g_wl + 0 * 32768, WTH, WTL, acc, warpM, warpN, lane, t);
    {
        int r = warpM * 16 + gid;
#pragma unroll
        for (int nf = 0; nf < 16; nf++) {
            int c = warpN * 128 + nf * 8 + 2 * tg;
            Q[r * FSTR + c]           = acc[nf][0] + bq[c];
            Q[r * FSTR + c + 1]       = acc[nf][1] + bq[c + 1];
            Q[(r + 8) * FSTR + c]     = acc[nf][2] + bq[c];
            Q[(r + 8) * FSTR + c + 1] = acc[nf][3] + bq[c + 1];
        }
    }

    // ---- K = x @ wk^T + bk
    gemm_mma(XH, XL, g_wh + 1 * 32768, g_wl + 1 * 32768, WTH, WTL, acc, warpM, warpN, lane, t);
    {
        int r = warpM * 16 + gid;
#pragma unroll
        for (int nf = 0; nf < 16; nf++) {
            int c = warpN * 128 + nf * 8 + 2 * tg;
            K[r * FSTR + c]           = acc[nf][0] + bk[c];
            K[r * FSTR + c + 1]       = acc[nf][1] + bk[c + 1];
            K[(r + 8) * FSTR + c]     = acc[nf][2] + bk[c];
            K[(r + 8) * FSTR + c + 1] = acc[nf][3] + bk[c + 1];
        }
    }

    // ---- V = x @ wv^T + bv  (overwrites XH/XL region; gemm ends with sync)
    gemm_mma(XH, XL, g_wh + 2 * 32768, g_wl + 2 * 32768, WTH, WTL, acc, warpM, warpN, lane, t);
    {
        int r = warpM * 16 + gid;
#pragma unroll
        for (int nf = 0; nf < 16; nf++) {
            int c = warpN * 128 + nf * 8 + 2 * tg;
            V[r * FSTR + c]           = acc[nf][0] + bv[c];
            V[r * FSTR + c + 1]       = acc[nf][1] + bv[c + 1];
            V[(r + 8) * FSTR + c]     = acc[nf][2] + bv[c];
            V[(r + 8) * FSTR + c + 1] = acc[nf][3] + bv[c + 1];
        }
    }
    __syncthreads();

    // ---- normalize Q (fold per-head scale) and K; copy bias table into WT
#pragma unroll 1
    for (int p = t; p < 1024; p += 256) {
        int mat = p >> 9;           // 0 = Q, 1 = K
        int h   = (p >> 6) & 7;
        int n   = p & 63;
        float* row = (mat ? K : Q) + n * FSTR + h * 32;
        float ss = 0.f;
#pragma unroll
        for (int k = 0; k < 32; k++) ss += row[k] * row[k];
        float sc = 1.f / fmaxf(sqrtf(ss), 1e-12f);
        if (mat == 0) sc *= expf(fminf(logit_scale[h], 4.6051702f)); // ln(100)
#pragma unroll
        for (int k = 0; k < 32; k++) row[k] *= sc;
    }
    for (int i = t; i < 1800; i += 256) TAB[i] = g_tab[i];
    __syncthreads();

    // ---- attention, register-resident probs, no block barriers in head loop.
    // thread (n, mg): row n, key subset m = mg + 4*mm.
    {
        const int n  = t >> 2;
        const int mg = t & 3;
        const int rn = n >> 3, cn = n & 7;
        const int gidn = GID[n];
        const float NEG_INF = __int_as_float(0xff800000);

#pragma unroll 1
        for (int h = 0; h < 8; h++) {
            float4 qv[8];
            const float4* qrow = reinterpret_cast<const float4*>(Q + n * FSTR + h * 32);
#pragma unroll
            for (int i = 0; i < 8; i++) qv[i] = qrow[i];

            float p[16];
#pragma unroll
            for (int mm = 0; mm < 16; mm++) {
                int m = mg + 4 * mm;
                const float4* krow = reinterpret_cast<const float4*>(K + m * FSTR + h * 32);
                float d = 0.f;
#pragma unroll
                for (int i = 0; i < 8; i++) {
                    float4 kv = krow[i];
                    d = fmaf(qv[i].x, kv.x, d);
                    d = fmaf(qv[i].y, kv.y, d);
                    d = fmaf(qv[i].z, kv.z, d);
                    d = fmaf(qv[i].w, kv.w, d);
                }
                int rm = m >> 3, cm = m & 7;
                int tix = ((rn - rm + 7) * 15 + (cn - cm + 7)) * 8 + h;
                p[mm] = (gidn == GID[m]) ? (d + TAB[tix]) : NEG_INF;
            }
            float mx = NEG_INF;
#pragma unroll
            for (int mm = 0; mm < 16; mm++) mx = fmaxf(mx, p[mm]);
            mx = fmaxf(mx, __shfl_xor_sync(0xffffffffu, mx, 1));
            mx = fmaxf(mx, __shfl_xor_sync(0xffffffffu, mx, 2));
            float s = 0.f;
#pragma unroll
            for (int mm = 0; mm < 16; mm++) { p[mm] = expf(p[mm] - mx); s += p[mm]; }
            s += __shfl_xor_sync(0xffffffffu, s, 1);
            s += __shfl_xor_sync(0xffffffffu, s, 2);
            float inv = 1.f / s;

            // partial P*V over this thread's 16 keys, all 32 head-cols
            float o[32];
#pragma unroll
            for (int c = 0; c < 32; c++) o[c] = 0.f;
#pragma unroll
            for (int mm = 0; mm < 16; mm++) {
                int m = mg + 4 * mm;
                float pm = p[mm];
                const float4* vrow = reinterpret_cast<const float4*>(V + m * FSTR + h * 32);
#pragma unroll
                for (int i = 0; i < 8; i++) {
                    float4 vv = vrow[i];
                    o[4 * i + 0] = fmaf(pm, vv.x, o[4 * i + 0]);
                    o[4 * i + 1] = fmaf(pm, vv.y, o[4 * i + 1]);
                    o[4 * i + 2] = fmaf(pm, vv.z, o[4 * i + 2]);
                    o[4 * i + 3] = fmaf(pm, vv.w, o[4 * i + 3]);
                }
            }
            // quad butterfly reduction -> full sums in all 4 lanes
#pragma unroll
            for (int c = 0; c < 32; c++) {
                o[c] += __shfl_xor_sync(0xffffffffu, o[c], 1);
                o[c] += __shfl_xor_sync(0xffffffffu, o[c], 2);
            }
            __syncwarp();   // quad-mates' Q-col reads complete before overwrite
#pragma unroll
            for (int j = 0; j < 8; j++)
                Q[n * FSTR + h * 32 + mg * 8 + j] = o[mg * 8 + j] * inv;  // Q becomes O
        }
    }
    __syncthreads();

    // ---- split O to bf16 hi/lo (into dead K region)
#pragma unroll
    for (int i = 0; i < 16; i++) {
        int f = i * 256 + t;
        int tok = f >> 6, c4 = f & 63;
        float4 v = *reinterpret_cast<const float4*>(&Q[tok * FSTR + c4 * 4]);
        uint32_t h0, l0, h1, l1;
        split2(v.x, v.y, h0, l0);
        split2(v.z, v.w, h1, l1);
        OH[tok * XSTR + 2 * c4]     = h0;
        OH[tok * XSTR + 2 * c4 + 1] = h1;
        OL[tok * XSTR + 2 * c4]     = l0;
        OL[tok * XSTR + 2 * c4 + 1] = l1;
    }

    // ---- Z = O @ wo^T + bo, scattered to output with inverse cyclic shift
    gemm_mma(OH, OL, g_wh + 3 * 32768, g_wl + 3 * 32768, WTH, WTL, acc, warpM, warpN, lane, t);
    {
        int r0 = warpM * 16 + gid;
        int r1 = r0 + 8;
        int rr0 = r0 >> 3, cc0 = r0 & 7;
        int rr1 = r1 >> 3, cc1 = r1 & 7;
        int oh0 = (wh * 8 + rr0 + 12) & 15, ow0 = (ww * 8 + cc0 + 12) & 15;
        int oh1 = (wh * 8 + rr1 + 12) & 15, ow1 = (ww * 8 + cc1 + 12) & 15;
        float* d0 = out + ((size_t)(b * 16 + oh0) * 16 + ow0) * 256;
        float* d1 = out + ((size_t)(b * 16 + oh1) * 16 + ow1) * 256;
#pragma unroll
        for (int nf = 0; nf < 16; nf++) {
            int c = warpN * 128 + nf * 8 + 2 * tg;
            float2 z0 = {acc[nf][0] + bo[c], acc[nf][1] + bo[c + 1]};
            float2 z1 = {acc[nf][2] + bo[c], acc[nf][3] + bo[c + 1]};
            *reinterpret_cast<float2*>(&d0[c]) = z0;
            *reinterpret_cast<float2*>(&d1[c]) = z1;
        }
    }
}

// ---------------------------------------------------------------------------
extern "C" void kernel_launch(void* const* d_in, const int* in_sizes, int n_in,
                              void* d_out, int out_size)
{
    const float* img = (const float*)d_in[0];
    const float* wq  = (const float*)d_in[1];
    const float* bq  = (const float*)d_in[2];
    const float* wk  = (const float*)d_in[3];
    const float* bk  = (const float*)d_in[4];
    const float* wv  = (const float*)d_in[5];
    const float* bv  = (const float*)d_in[6];
    const float* wo  = (const float*)d_in[7];
    const float* bo  = (const float*)d_in[8];
    const float* ls  = (const float*)d_in[9];
    const float* cw1 = (const float*)d_in[10];
    const float* cb1 = (const float*)d_in[11];
    const float* cw2 = (const float*)d_in[12];
    (void)in_sizes; (void)n_in; (void)out_size;

    cudaFuncSetAttribute(swin_kernel,
                         cudaFuncAttributeMaxDynamicSharedMemorySize,
                         SMEM_U32 * 4);

    cpb_kernel<<<225, 256>>>(cw1, cb1, cw2);
    wsplit_kernel<<<64, 256>>>(wq, wk, wv, wo);
    swin_kernel<<<2048, 256, SMEM_U32 * 4>>>(img, bq, bk, bv, bo, ls,
                                             (float*)d_out);
}

// round 5
// speedup vs baseline: 1.5756x; 1.5756x over previous
#include <cuda_runtime.h>
#include <cuda_bf16.h>
#include <math.h>
#include <stdint.h>

// Swin-V2 shifted-window MHA: fully tensor-core (split-bf16 mma.m16n8k16).
// One CTA (256 thr = 8 warps) per window; 2048 CTAs. Warp = head in attention.
//
// "F4" layout (x, Q, K, O): u32 rows of XSTR; for k-chunk g (16 wide), group tg:
//   uint4 at row*XSTR + g*16 + tg*4 = {hi(pair g8+tg), hi(pair g8+tg+4), lo, lo}
// One LDS.128 = a full B-fragment {b0,b1,c0,c1} or A-half {a0,a2,l0,l2}.

#define XSTR 272   // 272 % 32 == 16 -> LDS.128 phases tile all banks
#define WSTR 16    // weight tile rows; slot XOR-swizzled by (tg+row)&3
#define VSTR 64

#define OFF_X   0        // x F4 (17408); VT F4 (16384) overlays after V gemm
#define OFF_Q   17408    // Q F4 -> O F4
#define OFF_K   34816    // K F4
#define OFF_WT  52224    // staged weight chunk 256x16 (4096); TAB overlays
#define OFF_GID 56320    // 64
#define SMEM_U32 56384   // 225536 bytes

__device__ uint32_t g_w4[4 * 65536];  // [w][kc16][n256][tg4][{h0,h1,l0,l1}]
__device__ float    g_tab[225 * 8];   // 16*sigmoid(CPB-MLP), [cell][head]

__device__ __forceinline__ uint32_t pack2(__nv_bfloat16 a, __nv_bfloat16 b) {
    return (uint32_t)__bfloat16_as_ushort(a) | ((uint32_t)__bfloat16_as_ushort(b) << 16);
}
__device__ __forceinline__ void split2(float x, float y, uint32_t& h, uint32_t& l) {
    __nv_bfloat16 hx = __float2bfloat16_rn(x), hy = __float2bfloat16_rn(y);
    float rx = x - __bfloat162float(hx), ry = y - __bfloat162float(hy);
    h = pack2(hx, hy);
    l = pack2(__float2bfloat16_rn(rx), __float2bfloat16_rn(ry));
}

#define MMA16816(C, A0, A1, A2, A3, B0, B1)                                   \
    asm volatile("mma.sync.aligned.m16n8k16.row.col.f32.bf16.bf16.f32 "       \
                 "{%0,%1,%2,%3}, {%4,%5,%6,%7}, {%8,%9}, {%0,%1,%2,%3};"      \
                 : "+f"(C[0]), "+f"(C[1]), "+f"(C[2]), "+f"(C[3])             \
                 : "r"(A0), "r"(A1), "r"(A2), "r"(A3), "r"(B0), "r"(B1))

// 3-term split product: Ah*Bh + Al*Bh + Ah*Bl
#define MMA3(C, A0, A1, B)                                                    \
    do {                                                                      \
        MMA16816(C, (A0).x, (A1).x, (A0).y, (A1).y, (B).x, (B).y);            \
        MMA16816(C, (A0).z, (A1).z, (A0).w, (A1).w, (B).x, (B).y);            \
        MMA16816(C, (A0).x, (A1).x, (A0).y, (A1).y, (B).z, (B).w);            \
    } while (0)

// ---------------------------------------------------------------------------
__global__ void cpb_kernel(const float* __restrict__ w1,
                           const float* __restrict__ b1,
                           const float* __restrict__ w2)
{
    int t = threadIdx.x;
    int cell = blockIdx.x;
    int a = cell / 15, b = cell % 15;
    float ra = (a - 7) * (8.0f / 7.0f);
    float rb = (b - 7) * (8.0f / 7.0f);
    float va = (ra >= 0.f ? 1.f : -1.f) * log2f(fabsf(ra) + 1.f) * (1.f / 3.f);
    float vb = (rb >= 0.f ? 1.f : -1.f) * log2f(fabsf(rb) + 1.f) * (1.f / 3.f);

    int j1 = t, j2 = t + 256;
    float h1 = fmaxf(va * w1[j1 * 2] + vb * w1[j1 * 2 + 1] + b1[j1], 0.f);
    float h2 = fmaxf(va * w1[j2 * 2] + vb * w1[j2 * 2 + 1] + b1[j2], 0.f);

    float p[8];
#pragma unroll
    for (int h = 0; h < 8; h++)
        p[h] = h1 * w2[h * 512 + j1] + h2 * w2[h * 512 + j2];
#pragma unroll
    for (int h = 0; h < 8; h++)
#pragma unroll
        for (int off = 16; off; off >>= 1)
            p[h] += __shfl_xor_sync(0xffffffffu, p[h], off);

    __shared__ float ws[8][8];
    int warp = t >> 5, lane = t & 31;
    if (lane == 0) {
#pragma unroll
        for (int h = 0; h < 8; h++) ws[warp][h] = p[h];
    }
    __syncthreads();
    if (t < 8) {
        float s = 0.f;
#pragma unroll
        for (int w = 0; w < 8; w++) s += ws[w][t];
        g_tab[cell * 8 + t] = 16.f / (1.f + expf(-s));
    }
}

// ---------------------------------------------------------------------------
// Pre-split weights, fragment-ordered. grid = 64 (w*16 + kc); thread t = row n.
// ---------------------------------------------------------------------------
__global__ void wsplit_kernel(const float* __restrict__ wq,
                              const float* __restrict__ wk,
                              const float* __restrict__ wv,
                              const float* __restrict__ wo)
{
    const float* ws[4] = {wq, wk, wv, wo};
    int t = threadIdx.x;
    int wsel = blockIdx.x >> 4;
    int kc   = blockIdx.x & 15;
    const float* w = ws[wsel] + t * 256 + kc * 16;
    uint32_t* dst = g_w4 + wsel * 65536 + kc * 4096 + t * 16;

    float k0[16];
#pragma unroll
    for (int i = 0; i < 4; i++) {
        float4 v = *reinterpret_cast<const float4*>(w + i * 4);
        k0[4*i] = v.x; k0[4*i+1] = v.y; k0[4*i+2] = v.z; k0[4*i+3] = v.w;
    }
#pragma unroll
    for (int tg = 0; tg < 4; tg++) {
        uint32_t h0, l0, h1, l1;
        split2(k0[2*tg], k0[2*tg+1], h0, l0);         // pair tg
        split2(k0[8+2*tg], k0[9+2*tg], h1, l1);       // pair tg+4
        *reinterpret_cast<uint4*>(dst + tg * 4) = make_uint4(h0, h1, l0, l1);
    }
}

// ---------------------------------------------------------------------------
// Stage one 16-wide k-chunk of W into wt (rows 256 x WSTR, slot-swizzled).
// ---------------------------------------------------------------------------
__device__ __forceinline__ void stage_wt(uint32_t* wt, int t,
                                         uint4 r0, uint4 r1, uint4 r2, uint4 r3)
{
    uint4* wt4 = reinterpret_cast<uint4*>(wt + t * WSTR);
    int rot = t & 3;
    wt4[rot] = r0;
    wt4[(rot + 1) & 3] = r1;
    wt4[(rot + 2) & 3] = r2;
    wt4[(rot + 3) & 3] = r3;
}

// ---------------------------------------------------------------------------
// Projection GEMM: out(64x256) = A(64x256 F4 smem) @ W^T. Warp tile 16x128.
// ---------------------------------------------------------------------------
__device__ __forceinline__ void gemm_proj(
    const uint32_t* __restrict__ src, const uint32_t* __restrict__ gw,
    uint32_t* __restrict__ wt, float acc[16][4],
    int warpM, int warpN, int gid, int tg, int t)
{
#pragma unroll
    for (int nf = 0; nf < 16; nf++)
#pragma unroll
        for (int j = 0; j < 4; j++) acc[nf][j] = 0.f;

    const uint4* g4 = reinterpret_cast<const uint4*>(gw) + t * 4;
    uint4 r0 = g4[0], r1 = g4[1], r2 = g4[2], r3 = g4[3];

    const uint32_t* a0p = src + (warpM * 16 + gid) * XSTR + tg * 4;
    const uint32_t* a1p = a0p + 8 * XSTR;
    const uint32_t* bbase = wt + (warpN * 128 + gid) * WSTR + ((tg + gid) & 3) * 4;

#pragma unroll 1
    for (int kc = 0; kc < 16; kc++) {
        __syncthreads();
        stage_wt(wt, t, r0, r1, r2, r3);
        __syncthreads();
        if (kc < 15) {
            const uint4* gn = g4 + (kc + 1) * 1024;
            r0 = gn[0]; r1 = gn[1]; r2 = gn[2]; r3 = gn[3];
        }
        const uint4 A0 = *reinterpret_cast<const uint4*>(a0p + kc * 16);
        const uint4 A1 = *reinterpret_cast<const uint4*>(a1p + kc * 16);
#pragma unroll
        for (int nf = 0; nf < 16; nf++) {
            const uint4 Bv = *reinterpret_cast<const uint4*>(bbase + nf * 8 * WSTR);
            MMA3(acc[nf], A0, A1, Bv);
        }
    }
    __syncthreads();
}

// ---------------------------------------------------------------------------
// VT GEMM: VT(256x64) = Wv (A, staged) @ x^T (B = x F4). Warp: 32 d-rows.
// ---------------------------------------------------------------------------
__device__ __forceinline__ void gemm_vt(
    const uint32_t* __restrict__ x, const uint32_t* __restrict__ gw,
    uint32_t* __restrict__ wt, float av[2][8][4],
    int warp, int gid, int tg, int t)
{
#pragma unroll
    for (int s = 0; s < 2; s++)
#pragma unroll
        for (int nf = 0; nf < 8; nf++)
#pragma unroll
            for (int j = 0; j < 4; j++) av[s][nf][j] = 0.f;

    const uint4* g4 = reinterpret_cast<const uint4*>(gw) + t * 4;
    uint4 r0 = g4[0], r1 = g4[1], r2 = g4[2], r3 = g4[3];

    const uint32_t* wa = wt + (warp * 32 + gid) * WSTR + ((tg + gid) & 3) * 4;
    const uint32_t* bb = x + gid * XSTR + tg * 4;

#pragma unroll 1
    for (int kc = 0; kc < 16; kc++) {
        __syncthreads();
        stage_wt(wt, t, r0, r1, r2, r3);
        __syncthreads();
        if (kc < 15) {
            const uint4* gn = g4 + (kc + 1) * 1024;
            r0 = gn[0]; r1 = gn[1]; r2 = gn[2]; r3 = gn[3];
        }
        const uint4 Aa0 = *reinterpret_cast<const uint4*>(wa);
        const uint4 Aa1 = *reinterpret_cast<const uint4*>(wa + 8 * WSTR);
        const uint4 Ab0 = *reinterpret_cast<const uint4*>(wa + 16 * WSTR);
        const uint4 Ab1 = *reinterpret_cast<const uint4*>(wa + 24 * WSTR);
#pragma unroll
        for (int nf = 0; nf < 8; nf++) {
            const uint4 Bv = *reinterpret_cast<const uint4*>(bb + nf * 8 * XSTR + kc * 16);
            MMA3(av[0][nf], Aa0, Aa1, Bv);
            MMA3(av[1][nf], Ab0, Ab1, Bv);
        }
    }
    __syncthreads();
}

// ---------------------------------------------------------------------------
__global__ __launch_bounds__(256, 1)
void swin_kernel(const float* __restrict__ img,
                 const float* __restrict__ bq, const float* __restrict__ bk,
                 const float* __restrict__ bv, const float* __restrict__ bo,
                 const float* __restrict__ ls,
                 float* __restrict__ out)
{
    extern __shared__ uint32_t smu[];
    uint32_t* X   = smu + OFF_X;
    uint32_t* QS  = smu + OFF_Q;
    uint32_t* KS  = smu + OFF_K;
    uint32_t* VTS = smu + OFF_X;        // overlays X after V gemm
    uint32_t* WT  = smu + OFF_WT;
    float*    TAB = (float*)(smu + OFF_WT);
    int*      GID = (int*)(smu + OFF_GID);

    const int t    = threadIdx.x;
    const int lane = t & 31;
    const int warp = t >> 5;
    const int warpM = warp & 3, warpN = warp >> 2;
    const int gid = lane >> 2, tg = lane & 3;
    const int blk = blockIdx.x;
    const int b   = blk >> 2;
    const int wh  = (blk >> 1) & 1, ww = blk & 1;

    // ---- load shifted window -> x F4 split
    const float* imgb = img + (size_t)b * (16 * 16 * 256);
#pragma unroll
    for (int i = 0; i < 16; i++) {
        int f = i * 256 + t;            // float4 index
        int tok = f >> 6, c4 = f & 63;
        int r = tok >> 3, c = tok & 7;
        int ih = (wh * 8 + r + 12) & 15;
        int iw = (ww * 8 + c + 12) & 15;
        float4 v = *reinterpret_cast<const float4*>(&imgb[(ih * 16 + iw) * 256 + c4 * 4]);
        uint32_t h0, l0, h1, l1;
        split2(v.x, v.y, h0, l0);       // pair 2*c4
        split2(v.z, v.w, h1, l1);       // pair 2*c4+1
        int p0 = 2 * c4;
        int g = p0 >> 3, pos = p0 & 7;
        int tgs = pos & 3, slot = pos >> 2;
        uint32_t* base = X + tok * XSTR + g * 16 + slot;
        base[tgs * 4]           = h0;
        base[(tgs + 1) * 4]     = h1;
        base[tgs * 4 + 2]       = l0;
        base[(tgs + 1) * 4 + 2] = l1;
    }
    if (t < 64) {
        int r = t >> 3, c = t & 7;
        int gh = wh * 8 + r, gw = ww * 8 + c;
        int hg = (gh < 8) ? 0 : (gh < 12 ? 1 : 2);
        int wg = (gw < 8) ? 0 : (gw < 12 ? 1 : 2);
        GID[t] = hg * 3 + wg;
    }
    // gemm's internal barriers order these stores before any read

    float acc[16][4];
    const int r0w = warpM * 16 + gid, r1w = r0w + 8;

    // ---- Q = x wq^T + bq, cosine-normalize * scale, split -> QS
    gemm_proj(X, g_w4 + 0 * 65536, WT, acc, warpM, warpN, gid, tg, t);
    {
        float scl[4];
#pragma unroll
        for (int j = 0; j < 4; j++)
            scl[j] = expf(fminf(ls[warpN * 4 + j], 4.6051702f));
#pragma unroll
        for (int nf = 0; nf < 16; nf++) {
            float2 bb = *reinterpret_cast<const float2*>(bq + warpN * 128 + nf * 8 + 2 * tg);
            acc[nf][0] += bb.x; acc[nf][1] += bb.y;
            acc[nf][2] += bb.x; acc[nf][3] += bb.y;
        }
#pragma unroll
        for (int j = 0; j < 4; j++) {
            float ss0 = 0.f, ss1 = 0.f;
#pragma unroll
            for (int p = 0; p < 4; p++) {
                ss0 += acc[4*j+p][0]*acc[4*j+p][0] + acc[4*j+p][1]*acc[4*j+p][1];
                ss1 += acc[4*j+p][2]*acc[4*j+p][2] + acc[4*j+p][3]*acc[4*j+p][3];
            }
            ss0 += __shfl_xor_sync(0xffffffffu, ss0, 1);
            ss0 += __shfl_xor_sync(0xffffffffu, ss0, 2);
            ss1 += __shfl_xor_sync(0xffffffffu, ss1, 1);
            ss1 += __shfl_xor_sync(0xffffffffu, ss1, 2);
            float k0 = scl[j] / fmaxf(sqrtf(ss0), 1e-12f);
            float k1 = scl[j] / fmaxf(sqrtf(ss1), 1e-12f);
            uint32_t H[4], L[4];
#pragma unroll
            for (int p = 0; p < 4; p++) split2(acc[4*j+p][0]*k0, acc[4*j+p][1]*k0, H[p], L[p]);
            *reinterpret_cast<uint4*>(QS + r0w*XSTR + (warpN*8 + 2*j)*16 + tg*4)     = make_uint4(H[0],H[1],L[0],L[1]);
            *reinterpret_cast<uint4*>(QS + r0w*XSTR + (warpN*8 + 2*j + 1)*16 + tg*4) = make_uint4(H[2],H[3],L[2],L[3]);
#pragma unroll
            for (int p = 0; p < 4; p++) split2(acc[4*j+p][2]*k1, acc[4*j+p][3]*k1, H[p], L[p]);
            *reinterpret_cast<uint4*>(QS + r1w*XSTR + (warpN*8 + 2*j)*16 + tg*4)     = make_uint4(H[0],H[1],L[0],L[1]);
            *reinterpret_cast<uint4*>(QS + r1w*XSTR + (warpN*8 + 2*j + 1)*16 + tg*4) = make_uint4(H[2],H[3],L[2],L[3]);
        }
    }

    // ---- K = x wk^T + bk, normalize, split -> KS
    gemm_proj(X, g_w4 + 1 * 65536, WT, acc, warpM, warpN, gid, tg, t);
    {
#pragma unroll
        for (int nf = 0; nf < 16; nf++) {
            float2 bb = *reinterpret_cast<const float2*>(bk + warpN * 128 + nf * 8 + 2 * tg);
            acc[nf][0] += bb.x; acc[nf][1] += bb.y;
            acc[nf][2] += bb.x; acc[nf][3] += bb.y;
        }
#pragma unroll
        for (int j = 0; j < 4; j++) {
            float ss0 = 0.f, ss1 = 0.f;
#pragma unroll
            for (int p = 0; p < 4; p++) {
                ss0 += acc[4*j+p][0]*acc[4*j+p][0] + acc[4*j+p][1]*acc[4*j+p][1];
                ss1 += acc[4*j+p][2]*acc[4*j+p][2] + acc[4*j+p][3]*acc[4*j+p][3];
            }
            ss0 += __shfl_xor_sync(0xffffffffu, ss0, 1);
            ss0 += __shfl_xor_sync(0xffffffffu, ss0, 2);
            ss1 += __shfl_xor_sync(0xffffffffu, ss1, 1);
            ss1 += __shfl_xor_sync(0xffffffffu, ss1, 2);
            float k0 = 1.f / fmaxf(sqrtf(ss0), 1e-12f);
            float k1 = 1.f / fmaxf(sqrtf(ss1), 1e-12f);
            uint32_t H[4], L[4];
#pragma unroll
            for (int p = 0; p < 4; p++) split2(acc[4*j+p][0]*k0, acc[4*j+p][1]*k0, H[p], L[p]);
            *reinterpret_cast<uint4*>(KS + r0w*XSTR + (warpN*8 + 2*j)*16 + tg*4)     = make_uint4(H[0],H[1],L[0],L[1]);
            *reinterpret_cast<uint4*>(KS + r0w*XSTR + (warpN*8 + 2*j + 1)*16 + tg*4) = make_uint4(H[2],H[3],L[2],L[3]);
#pragma unroll
            for (int p = 0; p < 4; p++) split2(acc[4*j+p][2]*k1, acc[4*j+p][3]*k1, H[p], L[p]);
            *reinterpret_cast<uint4*>(KS + r1w*XSTR + (warpN*8 + 2*j)*16 + tg*4)     = make_uint4(H[0],H[1],L[0],L[1]);
            *reinterpret_cast<uint4*>(KS + r1w*XSTR + (warpN*8 + 2*j + 1)*16 + tg*4) = make_uint4(H[2],H[3],L[2],L[3]);
        }
    }

    // ---- VT = wv x^T + bv (transposed V), F4 split -> VTS (overlays X)
    {
        float av[2][8][4];
        gemm_vt(X, g_w4 + 2 * 65536, WT, av, warp, gid, tg, t);
        // gemm_vt ends with barrier: all x reads complete, safe to overwrite
#pragma unroll
        for (int sub = 0; sub < 2; sub++) {
            int d0 = warp * 32 + sub * 16 + gid, d1 = d0 + 8;
            float bv0 = bv[d0], bv1 = bv[d1];
#pragma unroll
            for (int kp = 0; kp < 4; kp++) {
                int ne = 2 * kp, no = ne + 1;
                uint32_t e0, f0, e1, f1;
                split2(av[sub][ne][0] + bv0, av[sub][ne][1] + bv0, e0, f0);
                split2(av[sub][no][0] + bv0, av[sub][no][1] + bv0, e1, f1);
                *reinterpret_cast<uint4*>(VTS + d0 * VSTR + ((kp + d0) & 3) * 16 + tg * 4) =
                    make_uint4(e0, e1, f0, f1);
                split2(av[sub][ne][2] + bv1, av[sub][ne][3] + bv1, e0, f0);
                split2(av[sub][no][2] + bv1, av[sub][no][3] + bv1, e1, f1);
                *reinterpret_cast<uint4*>(VTS + d1 * VSTR + ((kp + d1) & 3) * 16 + tg * 4) =
                    make_uint4(e0, e1, f0, f1);
            }
        }
    }
    for (int i = t; i < 1800; i += 256) TAB[i] = g_tab[i];
    __syncthreads();

    // ---- attention: warp = head h. S via MMA; softmax in regs; P chains to PV MMA.
    {
        const int h = warp;
        const float NEG_INF = __int_as_float(0xff800000);
        int gmA[8], gmB[8];
#pragma unroll
        for (int nt = 0; nt < 8; nt++) {
            gmA[nt] = GID[nt * 8 + 2 * tg];
            gmB[nt] = GID[nt * 8 + 2 * tg + 1];
        }
#pragma unroll 1
        for (int mt = 0; mt < 4; mt++) {
            float S[8][4];
#pragma unroll
            for (int nt = 0; nt < 8; nt++)
#pragma unroll
                for (int j = 0; j < 4; j++) S[nt][j] = 0.f;
#pragma unroll
            for (int kc = 0; kc < 2; kc++) {
                const uint4 A0 = *reinterpret_cast<const uint4*>(
                    QS + (mt * 16 + gid) * XSTR + (2 * h + kc) * 16 + tg * 4);
                const uint4 A1 = *reinterpret_cast<const uint4*>(
                    QS + (mt * 16 + gid + 8) * XSTR + (2 * h + kc) * 16 + tg * 4);
#pragma unroll
                for (int nt = 0; nt < 8; nt++) {
                    const uint4 Bv = *reinterpret_cast<const uint4*>(
                        KS + (nt * 8 + gid) * XSTR + (2 * h + kc) * 16 + tg * 4);
                    MMA3(S[nt], A0, A1, Bv);
                }
            }
            int r0 = mt * 16 + gid, r1 = r0 + 8;
            int gn0 = GID[r0], gn1 = GID[r1];
            int rn0 = r0 >> 3, cn0 = r0 & 7, rn1 = r1 >> 3, cn1 = r1 & 7;
            float mx0 = NEG_INF, mx1 = NEG_INF;
#pragma unroll
            for (int nt = 0; nt < 8; nt++) {
                int mA = nt * 8 + 2 * tg, mB = mA + 1;
                int rmA = mA >> 3, cmA = mA & 7, rmB = mB >> 3, cmB = mB & 7;
                S[nt][0] = (gn0 == gmA[nt]) ? S[nt][0] + TAB[((rn0-rmA+7)*15 + cn0-cmA+7)*8 + h] : NEG_INF;
                S[nt][1] = (gn0 == gmB[nt]) ? S[nt][1] + TAB[((rn0-rmB+7)*15 + cn0-cmB+7)*8 + h] : NEG_INF;
                S[nt][2] = (gn1 == gmA[nt]) ? S[nt][2] + TAB[((rn1-rmA+7)*15 + cn1-cmA+7)*8 + h] : NEG_INF;
                S[nt][3] = (gn1 == gmB[nt]) ? S[nt][3] + TAB[((rn1-rmB+7)*15 + cn1-cmB+7)*8 + h] : NEG_INF;
                mx0 = fmaxf(mx0, fmaxf(S[nt][0], S[nt][1]));
                mx1 = fmaxf(mx1, fmaxf(S[nt][2], S[nt][3]));
            }
            mx0 = fmaxf(mx0, __shfl_xor_sync(0xffffffffu, mx0, 1));
            mx0 = fmaxf(mx0, __shfl_xor_sync(0xffffffffu, mx0, 2));
            mx1 = fmaxf(mx1, __shfl_xor_sync(0xffffffffu, mx1, 1));
            mx1 = fmaxf(mx1, __shfl_xor_sync(0xffffffffu, mx1, 2));
            float s0 = 0.f, s1 = 0.f;
#pragma unroll
            for (int nt = 0; nt < 8; nt++) {
                S[nt][0] = __expf(S[nt][0] - mx0); s0 += S[nt][0];
                S[nt][1] = __expf(S[nt][1] - mx0); s0 += S[nt][1];
                S[nt][2] = __expf(S[nt][2] - mx1); s1 += S[nt][2];
                S[nt][3] = __expf(S[nt][3] - mx1); s1 += S[nt][3];
            }
            s0 += __shfl_xor_sync(0xffffffffu, s0, 1);
            s0 += __shfl_xor_sync(0xffffffffu, s0, 2);
            s1 += __shfl_xor_sync(0xffffffffu, s1, 1);
            s1 += __shfl_xor_sync(0xffffffffu, s1, 2);
            float inv0 = 1.f / s0, inv1 = 1.f / s1;
            uint32_t ph0[8], ph1[8], pl0[8], pl1[8];
#pragma unroll
            for (int nt = 0; nt < 8; nt++) {
                split2(S[nt][0] * inv0, S[nt][1] * inv0, ph0[nt], pl0[nt]);
                split2(S[nt][2] * inv1, S[nt][3] * inv1, ph1[nt], pl1[nt]);
            }
            float O[4][4];
#pragma unroll
            for (int dt = 0; dt < 4; dt++)
#pragma unroll
                for (int j = 0; j < 4; j++) O[dt][j] = 0.f;
#pragma unroll
            for (int kp = 0; kp < 4; kp++) {
                uint32_t ah0 = ph0[2*kp], ah1 = ph1[2*kp], ah2 = ph0[2*kp+1], ah3 = ph1[2*kp+1];
                uint32_t al0 = pl0[2*kp], al1 = pl1[2*kp], al2 = pl0[2*kp+1], al3 = pl1[2*kp+1];
#pragma unroll
                for (int dt = 0; dt < 4; dt++) {
                    int d = h * 32 + dt * 8 + gid;
                    const uint4 Bv = *reinterpret_cast<const uint4*>(
                        VTS + d * VSTR + ((kp + d) & 3) * 16 + tg * 4);
                    MMA16816(O[dt], ah0, ah1, ah2, ah3, Bv.x, Bv.y);
                    MMA16816(O[dt], al0, al1, al2, al3, Bv.x, Bv.y);
                    MMA16816(O[dt], ah0, ah1, ah2, ah3, Bv.z, Bv.w);
                }
            }
            // store O (F4) into QS chunks 2h/2h+1 (this warp's private cols)
#pragma unroll
            for (int gg = 0; gg < 2; gg++) {
                uint32_t e0, f0, e1, f1;
                split2(O[2*gg][0], O[2*gg][1], e0, f0);
                split2(O[2*gg+1][0], O[2*gg+1][1], e1, f1);
                *reinterpret_cast<uint4*>(QS + r0 * XSTR + (2*h + gg) * 16 + tg * 4) =
                    make_uint4(e0, e1, f0, f1);
                split2(O[2*gg][2], O[2*gg][3], e0, f0);
                split2(O[2*gg+1][2], O[2*gg+1][3], e1, f1);
                *reinterpret_cast<uint4*>(QS + r1 * XSTR + (2*h + gg) * 16 + tg * 4) =
                    make_uint4(e0, e1, f0, f1);
            }
        }
    }

    // ---- Z = O wo^T + bo -> global with inverse cyclic shift
    gemm_proj(QS, g_w4 + 3 * 65536, WT, acc, warpM, warpN, gid, tg, t);
    {
        int rr0 = r0w >> 3, cc0 = r0w & 7;
        int rr1 = r1w >> 3, cc1 = r1w & 7;
        int oh0 = (wh * 8 + rr0 + 12) & 15, ow0 = (ww * 8 + cc0 + 12) & 15;
        int oh1 = (wh * 8 + rr1 + 12) & 15, ow1 = (ww * 8 + cc1 + 12) & 15;
        float* d0 = out + ((size_t)(b * 16 + oh0) * 16 + ow0) * 256;
        float* d1 = out + ((size_t)(b * 16 + oh1) * 16 + ow1) * 256;
#pragma unroll
        for (int nf = 0; nf < 16; nf++) {
            int c = warpN * 128 + nf * 8 + 2 * tg;
            float2 bb = *reinterpret_cast<const float2*>(bo + c);
            float2 z0 = {acc[nf][0] + bb.x, acc[nf][1] + bb.y};
            float2 z1 = {acc[nf][2] + bb.x, acc[nf][3] + bb.y};
            *reinterpret_cast<float2*>(&d0[c]) = z0;
            *reinterpret_cast<float2*>(&d1[c]) = z1;
        }
    }
}

// ---------------------------------------------------------------------------
extern "C" void kernel_launch(void* const* d_in, const int* in_sizes, int n_in,
                              void* d_out, int out_size)
{
    const float* img = (const float*)d_in[0];
    const float* wq  = (const float*)d_in[1];
    const float* bq  = (const float*)d_in[2];
    const float* wk  = (const float*)d_in[3];
    const float* bk  = (const float*)d_in[4];
    const float* wv  = (const float*)d_in[5];
    const float* bv  = (const float*)d_in[6];
    const float* wo  = (const float*)d_in[7];
    const float* bo  = (const float*)d_in[8];
    const float* ls  = (const float*)d_in[9];
    const float* cw1 = (const float*)d_in[10];
    const float* cb1 = (const float*)d_in[11];
    const float* cw2 = (const float*)d_in[12];
    (void)in_sizes; (void)n_in; (void)out_size;

    cudaFuncSetAttribute(swin_kernel,
                         cudaFuncAttributeMaxDynamicSharedMemorySize,
                         SMEM_U32 * 4);

    cpb_kernel<<<225, 256>>>(cw1, cb1, cw2);
    wsplit_kernel<<<64, 256>>>(wq, wk, wv, wo);
    swin_kernel<<<2048, 256, SMEM_U32 * 4>>>(img, bq, bk, bv, bo, ls,
                                             (float*)d_out);
}

// round 6
// speedup vs baseline: 2.1742x; 1.3800x over previous
#include <cuda_runtime.h>
#include <cuda_fp16.h>
#include <math.h>
#include <stdint.h>

// Swin-V2 shifted-window MHA: split-fp16 tensor-core (mma.m16n8k16.f16).
// One CTA (256 thr = 8 warps) per window; 2048 CTAs. Warp = head in attention.
//
// Projections: 2-term split (Ah*Bh + Al*Bh), W hi-only (error ~2^-13).
// Attention S and P*V: 3-term split (error ~2^-24).
//
// "F4" layout (x, Q, K, O): u32 rows of XSTR; k-chunk g (16 wide), group tg:
//   uint4 at row*XSTR + g*16 + tg*4 = {hi(pair g8+tg), hi(pair g8+tg+4), lo, lo}
// Weight tile "W2" layout: superchunk (32-wide k) rows of 16 u32; uint4 at
//   row*16 + slot((tg+row)&3)*4 = {kc0 hi(tg), kc0 hi(tg+4), kc1 hi(tg), kc1 hi(tg+4)}

#define XSTR 272
#define VSTR 64

#define OFF_X   0        // x F4 (17408); VT F4 (16384) overlays after V gemm
#define OFF_Q   17408    // Q F4 -> O F4
#define OFF_K   34816    // K F4
#define OFF_WT  52224    // staged weight superchunk 256x16 (4096); TAB overlays
#define OFF_GID 56320    // 64
#define SMEM_U32 56384   // 225536 bytes

__device__ uint32_t g_w4[4 * 32768];  // [w][kp8][n256][tg4] = {kc0 h,h, kc1 h,h}
__device__ float    g_tab[225 * 8];   // 16*sigmoid(CPB-MLP), [cell][head]

__device__ __forceinline__ uint32_t pack2h(float x, float y) {
    __half hx = __float2half_rn(x), hy = __float2half_rn(y);
    return (uint32_t)__half_as_ushort(hx) | ((uint32_t)__half_as_ushort(hy) << 16);
}
__device__ __forceinline__ void split2h(float x, float y, uint32_t& h, uint32_t& l) {
    __half hx = __float2half_rn(x), hy = __float2half_rn(y);
    float rx = x - __half2float(hx), ry = y - __half2float(hy);
    h = (uint32_t)__half_as_ushort(hx) | ((uint32_t)__half_as_ushort(hy) << 16);
    l = pack2h(rx, ry);
}

#define MMAH(C, A0, A1, A2, A3, B0, B1)                                       \
    asm volatile("mma.sync.aligned.m16n8k16.row.col.f32.f16.f16.f32 "         \
                 "{%0,%1,%2,%3}, {%4,%5,%6,%7}, {%8,%9}, {%0,%1,%2,%3};"      \
                 : "+f"(C[0]), "+f"(C[1]), "+f"(C[2]), "+f"(C[3])             \
                 : "r"(A0), "r"(A1), "r"(A2), "r"(A3), "r"(B0), "r"(B1))

// 3-term split product (attention): Ah*Bh + Al*Bh + Ah*Bl
#define MMA3(C, A0, A1, B)                                                    \
    do {                                                                      \
        MMAH(C, (A0).x, (A1).x, (A0).y, (A1).y, (B).x, (B).y);                \
        MMAH(C, (A0).z, (A1).z, (A0).w, (A1).w, (B).x, (B).y);                \
        MMAH(C, (A0).x, (A1).x, (A0).y, (A1).y, (B).z, (B).w);                \
    } while (0)

// ---------------------------------------------------------------------------
// Prep kernel: blocks 0..224 = CPB bias table; blocks 225..256 = weight split.
// ---------------------------------------------------------------------------
__global__ void prep_kernel(const float* __restrict__ w1,
                            const float* __restrict__ b1,
                            const float* __restrict__ w2,
                            const float* __restrict__ wq,
                            const float* __restrict__ wk,
                            const float* __restrict__ wv,
                            const float* __restrict__ wo)
{
    int t = threadIdx.x;
    if (blockIdx.x < 225) {
        int cell = blockIdx.x;
        int a = cell / 15, b = cell % 15;
        float ra = (a - 7) * (8.0f / 7.0f);
        float rb = (b - 7) * (8.0f / 7.0f);
        float va = (ra >= 0.f ? 1.f : -1.f) * log2f(fabsf(ra) + 1.f) * (1.f / 3.f);
        float vb = (rb >= 0.f ? 1.f : -1.f) * log2f(fabsf(rb) + 1.f) * (1.f / 3.f);

        int j1 = t, j2 = t + 256;
        float h1 = fmaxf(va * w1[j1 * 2] + vb * w1[j1 * 2 + 1] + b1[j1], 0.f);
        float h2 = fmaxf(va * w1[j2 * 2] + vb * w1[j2 * 2 + 1] + b1[j2], 0.f);

        float p[8];
#pragma unroll
        for (int h = 0; h < 8; h++)
            p[h] = h1 * w2[h * 512 + j1] + h2 * w2[h * 512 + j2];
#pragma unroll
        for (int h = 0; h < 8; h++)
#pragma unroll
            for (int off = 16; off; off >>= 1)
                p[h] += __shfl_xor_sync(0xffffffffu, p[h], off);

        __shared__ float ws[8][8];
        int warp = t >> 5, lane = t & 31;
        if (lane == 0) {
#pragma unroll
            for (int h = 0; h < 8; h++) ws[warp][h] = p[h];
        }
        __syncthreads();
        if (t < 8) {
            float s = 0.f;
#pragma unroll
            for (int w = 0; w < 8; w++) s += ws[w][t];
            g_tab[cell * 8 + t] = 16.f / (1.f + expf(-s));
        }
    } else {
        const float* wsrc[4] = {wq, wk, wv, wo};
        int blk = blockIdx.x - 225;       // 0..31
        int wsel = blk >> 3, kp = blk & 7;
        const float* w = wsrc[wsel] + t * 256 + kp * 32;
        uint32_t* dst = g_w4 + wsel * 32768 + kp * 4096 + t * 16;

        float v[32];
#pragma unroll
        for (int i = 0; i < 8; i++) {
            float4 q = *reinterpret_cast<const float4*>(w + i * 4);
            v[4*i] = q.x; v[4*i+1] = q.y; v[4*i+2] = q.z; v[4*i+3] = q.w;
        }
#pragma unroll
        for (int tg = 0; tg < 4; tg++) {
            uint4 u;
            u.x = pack2h(v[2*tg],      v[2*tg+1]);        // kc0 pair tg
            u.y = pack2h(v[2*tg+8],    v[2*tg+9]);        // kc0 pair tg+4
            u.z = pack2h(v[16+2*tg],   v[16+2*tg+1]);     // kc1 pair tg
            u.w = pack2h(v[16+2*tg+8], v[16+2*tg+9]);     // kc1 pair tg+4
            *reinterpret_cast<uint4*>(dst + tg * 4) = u;
        }
    }
}

// ---------------------------------------------------------------------------
// Projection GEMM (2-term): out(64x256) = A(F4 smem) @ Whi^T. Warp 16x128.
// 8 superchunks (k32 each); per superchunk: stage WT, then MMAs.
// ---------------------------------------------------------------------------
__device__ __forceinline__ void gemm_proj(
    const uint32_t* __restrict__ src, const uint32_t* __restrict__ gw,
    uint32_t* __restrict__ wt, float acc[16][4],
    int warpM, int warpN, int gid, int tg, int t)
{
#pragma unroll
    for (int nf = 0; nf < 16; nf++)
#pragma unroll
        for (int j = 0; j < 4; j++) acc[nf][j] = 0.f;

    const uint4* g4 = reinterpret_cast<const uint4*>(gw) + t * 4;
    uint4 r0 = g4[0], r1 = g4[1], r2 = g4[2], r3 = g4[3];

    const uint32_t* a0p = src + (warpM * 16 + gid) * XSTR + tg * 4;
    const uint32_t* a1p = a0p + 8 * XSTR;

#pragma unroll 1
    for (int kp = 0; kp < 8; kp++) {
        __syncthreads();
        {
            uint4* wt4 = reinterpret_cast<uint4*>(wt + t * 16);
            wt4[t & 3] = r0;
            wt4[(t + 1) & 3] = r1;
            wt4[(t + 2) & 3] = r2;
            wt4[(t + 3) & 3] = r3;
        }
        __syncthreads();
        if (kp < 7) {
            const uint4* gn = g4 + (kp + 1) * 1024;
            r0 = gn[0]; r1 = gn[1]; r2 = gn[2]; r3 = gn[3];
        }
        const uint4 A00 = *reinterpret_cast<const uint4*>(a0p + (2*kp) * 16);
        const uint4 A10 = *reinterpret_cast<const uint4*>(a1p + (2*kp) * 16);
        const uint4 A01 = *reinterpret_cast<const uint4*>(a0p + (2*kp+1) * 16);
        const uint4 A11 = *reinterpret_cast<const uint4*>(a1p + (2*kp+1) * 16);
#pragma unroll
        for (int nf = 0; nf < 16; nf++) {
            int n = warpN * 128 + nf * 8 + gid;
            const uint4 Bv = *reinterpret_cast<const uint4*>(
                wt + n * 16 + ((tg + n) & 3) * 4);
            MMAH(acc[nf], A00.x, A10.x, A00.y, A10.y, Bv.x, Bv.y);  // kc0 hi*hi
            MMAH(acc[nf], A00.z, A10.z, A00.w, A10.w, Bv.x, Bv.y);  // kc0 lo*hi
            MMAH(acc[nf], A01.x, A11.x, A01.y, A11.y, Bv.z, Bv.w);  // kc1 hi*hi
            MMAH(acc[nf], A01.z, A11.z, A01.w, A11.w, Bv.z, Bv.w);  // kc1 lo*hi
        }
    }
    __syncthreads();
}

// ---------------------------------------------------------------------------
// VT GEMM (2-term): VT(256x64) = Wv_hi (A, staged) @ x^T (B = x F4, hi+lo).
// Warp: 32 d-rows (2 sub-tiles of 16).
// ---------------------------------------------------------------------------
__device__ __forceinline__ void gemm_vt(
    const uint32_t* __restrict__ x, const uint32_t* __restrict__ gw,
    uint32_t* __restrict__ wt, float av[2][8][4],
    int warp, int gid, int tg, int t)
{
#pragma unroll
    for (int s = 0; s < 2; s++)
#pragma unroll
        for (int nf = 0; nf < 8; nf++)
#pragma unroll
            for (int j = 0; j < 4; j++) av[s][nf][j] = 0.f;

    const uint4* g4 = reinterpret_cast<const uint4*>(gw) + t * 4;
    uint4 r0 = g4[0], r1 = g4[1], r2 = g4[2], r3 = g4[3];

    const uint32_t* bb = x + gid * XSTR + tg * 4;

#pragma unroll 1
    for (int kp = 0; kp < 8; kp++) {
        __syncthreads();
        {
            uint4* wt4 = reinterpret_cast<uint4*>(wt + t * 16);
            wt4[t & 3] = r0;
            wt4[(t + 1) & 3] = r1;
            wt4[(t + 2) & 3] = r2;
            wt4[(t + 3) & 3] = r3;
        }
        __syncthreads();
        if (kp < 7) {
            const uint4* gn = g4 + (kp + 1) * 1024;
            r0 = gn[0]; r1 = gn[1]; r2 = gn[2]; r3 = gn[3];
        }
        // A rows for both sub-tiles: warp*32 + {gid, gid+8, gid+16, gid+24}
        uint4 u[4];
#pragma unroll
        for (int i = 0; i < 4; i++) {
            int n = warp * 32 + i * 8 + gid;
            u[i] = *reinterpret_cast<const uint4*>(wt + n * 16 + ((tg + n) & 3) * 4);
        }
#pragma unroll
        for (int nf = 0; nf < 8; nf++) {
            const uint4 B0 = *reinterpret_cast<const uint4*>(bb + nf * 8 * XSTR + (2*kp) * 16);
            const uint4 B1 = *reinterpret_cast<const uint4*>(bb + nf * 8 * XSTR + (2*kp+1) * 16);
            // sub 0 (rows gid, gid+8): kc0 then kc1; B hi then B lo
            MMAH(av[0][nf], u[0].x, u[1].x, u[0].y, u[1].y, B0.x, B0.y);
            MMAH(av[0][nf], u[0].x, u[1].x, u[0].y, u[1].y, B0.z, B0.w);
            MMAH(av[0][nf], u[0].z, u[1].z, u[0].w, u[1].w, B1.x, B1.y);
            MMAH(av[0][nf], u[0].z, u[1].z, u[0].w, u[1].w, B1.z, B1.w);
            // sub 1 (rows gid+16, gid+24)
            MMAH(av[1][nf], u[2].x, u[3].x, u[2].y, u[3].y, B0.x, B0.y);
            MMAH(av[1][nf], u[2].x, u[3].x, u[2].y, u[3].y, B0.z, B0.w);
            MMAH(av[1][nf], u[2].z, u[3].z, u[2].w, u[3].w, B1.x, B1.y);
            MMAH(av[1][nf], u[2].z, u[3].z, u[2].w, u[3].w, B1.z, B1.w);
        }
    }
    __syncthreads();
}

// ---------------------------------------------------------------------------
__global__ __launch_bounds__(256, 1)
void swin_kernel(const float* __restrict__ img,
                 const float* __restrict__ bq, const float* __restrict__ bk,
                 const float* __restrict__ bv, const float* __restrict__ bo,
                 const float* __restrict__ ls,
                 float* __restrict__ out)
{
    extern __shared__ uint32_t smu[];
    uint32_t* X   = smu + OFF_X;
    uint32_t* QS  = smu + OFF_Q;
    uint32_t* KS  = smu + OFF_K;
    uint32_t* VTS = smu + OFF_X;        // overlays X after V gemm
    uint32_t* WT  = smu + OFF_WT;
    float*    TAB = (float*)(smu + OFF_WT);
    int*      GID = (int*)(smu + OFF_GID);

    const int t    = threadIdx.x;
    const int lane = t & 31;
    const int warp = t >> 5;
    const int warpM = warp & 3, warpN = warp >> 2;
    const int gid = lane >> 2, tg = lane & 3;
    const int blk = blockIdx.x;
    const int b   = blk >> 2;
    const int wh  = (blk >> 1) & 1, ww = blk & 1;

    // ---- load shifted window -> x F4 split (fp16 hi/lo)
    const float* imgb = img + (size_t)b * (16 * 16 * 256);
#pragma unroll
    for (int i = 0; i < 16; i++) {
        int f = i * 256 + t;            // float4 index
        int tok = f >> 6, c4 = f & 63;
        int r = tok >> 3, c = tok & 7;
        int ih = (wh * 8 + r + 12) & 15;
        int iw = (ww * 8 + c + 12) & 15;
        float4 v = *reinterpret_cast<const float4*>(&imgb[(ih * 16 + iw) * 256 + c4 * 4]);
        uint32_t h0, l0, h1, l1;
        split2h(v.x, v.y, h0, l0);      // pair 2*c4
        split2h(v.z, v.w, h1, l1);      // pair 2*c4+1
        int p0 = 2 * c4;
        int g = p0 >> 3, pos = p0 & 7;
        int tgs = pos & 3, slot = pos >> 2;
        uint32_t* base = X + tok * XSTR + g * 16 + slot;
        base[tgs * 4]           = h0;
        base[(tgs + 1) * 4]     = h1;
        base[tgs * 4 + 2]       = l0;
        base[(tgs + 1) * 4 + 2] = l1;
    }
    if (t < 64) {
        int r = t >> 3, c = t & 7;
        int gh = wh * 8 + r, gw = ww * 8 + c;
        int hg = (gh < 8) ? 0 : (gh < 12 ? 1 : 2);
        int wg = (gw < 8) ? 0 : (gw < 12 ? 1 : 2);
        GID[t] = hg * 3 + wg;
    }
    // gemm's internal barriers order these stores before any read

    float acc[16][4];
    const int r0w = warpM * 16 + gid, r1w = r0w + 8;

    // ---- Q = x wq^T + bq, cosine-normalize * scale, split -> QS
    gemm_proj(X, g_w4 + 0 * 32768, WT, acc, warpM, warpN, gid, tg, t);
    {
        float scl[4];
#pragma unroll
        for (int j = 0; j < 4; j++)
            scl[j] = expf(fminf(ls[warpN * 4 + j], 4.6051702f));
#pragma unroll
        for (int nf = 0; nf < 16; nf++) {
            float2 bb = *reinterpret_cast<const float2*>(bq + warpN * 128 + nf * 8 + 2 * tg);
            acc[nf][0] += bb.x; acc[nf][1] += bb.y;
            acc[nf][2] += bb.x; acc[nf][3] += bb.y;
        }
#pragma unroll
        for (int j = 0; j < 4; j++) {
            float ss0 = 0.f, ss1 = 0.f;
#pragma unroll
            for (int p = 0; p < 4; p++) {
                ss0 += acc[4*j+p][0]*acc[4*j+p][0] + acc[4*j+p][1]*acc[4*j+p][1];
                ss1 += acc[4*j+p][2]*acc[4*j+p][2] + acc[4*j+p][3]*acc[4*j+p][3];
            }
            ss0 += __shfl_xor_sync(0xffffffffu, ss0, 1);
            ss0 += __shfl_xor_sync(0xffffffffu, ss0, 2);
            ss1 += __shfl_xor_sync(0xffffffffu, ss1, 1);
            ss1 += __shfl_xor_sync(0xffffffffu, ss1, 2);
            float k0 = scl[j] / fmaxf(sqrtf(ss0), 1e-12f);
            float k1 = scl[j] / fmaxf(sqrtf(ss1), 1e-12f);
            uint32_t H[4], L[4];
#pragma unroll
            for (int p = 0; p < 4; p++) split2h(acc[4*j+p][0]*k0, acc[4*j+p][1]*k0, H[p], L[p]);
            *reinterpret_cast<uint4*>(QS + r0w*XSTR + (warpN*8 + 2*j)*16 + tg*4)     = make_uint4(H[0],H[1],L[0],L[1]);
            *reinterpret_cast<uint4*>(QS + r0w*XSTR + (warpN*8 + 2*j + 1)*16 + tg*4) = make_uint4(H[2],H[3],L[2],L[3]);
#pragma unroll
            for (int p = 0; p < 4; p++) split2h(acc[4*j+p][2]*k1, acc[4*j+p][3]*k1, H[p], L[p]);
            *reinterpret_cast<uint4*>(QS + r1w*XSTR + (warpN*8 + 2*j)*16 + tg*4)     = make_uint4(H[0],H[1],L[0],L[1]);
            *reinterpret_cast<uint4*>(QS + r1w*XSTR + (warpN*8 + 2*j + 1)*16 + tg*4) = make_uint4(H[2],H[3],L[2],L[3]);
        }
    }

    // ---- K = x wk^T + bk, normalize, split -> KS
    gemm_proj(X, g_w4 + 1 * 32768, WT, acc, warpM, warpN, gid, tg, t);
    {
#pragma unroll
        for (int nf = 0; nf < 16; nf++) {
            float2 bb = *reinterpret_cast<const float2*>(bk + warpN * 128 + nf * 8 + 2 * tg);
            acc[nf][0] += bb.x; acc[nf][1] += bb.y;
            acc[nf][2] += bb.x; acc[nf][3] += bb.y;
        }
#pragma unroll
        for (int j = 0; j < 4; j++) {
            float ss0 = 0.f, ss1 = 0.f;
#pragma unroll
            for (int p = 0; p < 4; p++) {
                ss0 += acc[4*j+p][0]*acc[4*j+p][0] + acc[4*j+p][1]*acc[4*j+p][1];
                ss1 += acc[4*j+p][2]*acc[4*j+p][2] + acc[4*j+p][3]*acc[4*j+p][3];
            }
            ss0 += __shfl_xor_sync(0xffffffffu, ss0, 1);
            ss0 += __shfl_xor_sync(0xffffffffu, ss0, 2);
            ss1 += __shfl_xor_sync(0xffffffffu, ss1, 1);
            ss1 += __shfl_xor_sync(0xffffffffu, ss1, 2);
            float k0 = 1.f / fmaxf(sqrtf(ss0), 1e-12f);
            float k1 = 1.f / fmaxf(sqrtf(ss1), 1e-12f);
            uint32_t H[4], L[4];
#pragma unroll
            for (int p = 0; p < 4; p++) split2h(acc[4*j+p][0]*k0, acc[4*j+p][1]*k0, H[p], L[p]);
            *reinterpret_cast<uint4*>(KS + r0w*XSTR + (warpN*8 + 2*j)*16 + tg*4)     = make_uint4(H[0],H[1],L[0],L[1]);
            *reinterpret_cast<uint4*>(KS + r0w*XSTR + (warpN*8 + 2*j + 1)*16 + tg*4) = make_uint4(H[2],H[3],L[2],L[3]);
#pragma unroll
            for (int p = 0; p < 4; p++) split2h(acc[4*j+p][2]*k1, acc[4*j+p][3]*k1, H[p], L[p]);
            *reinterpret_cast<uint4*>(KS + r1w*XSTR + (warpN*8 + 2*j)*16 + tg*4)     = make_uint4(H[0],H[1],L[0],L[1]);
            *reinterpret_cast<uint4*>(KS + r1w*XSTR + (warpN*8 + 2*j + 1)*16 + tg*4) = make_uint4(H[2],H[3],L[2],L[3]);
        }
    }

    // ---- VT = wv x^T + bv (transposed V), F4 split -> VTS (overlays X)
    {
        float av[2][8][4];
        gemm_vt(X, g_w4 + 2 * 32768, WT, av, warp, gid, tg, t);
        // gemm_vt ends with barrier: all x reads complete, safe to overwrite
#pragma unroll
        for (int sub = 0; sub < 2; sub++) {
            int d0 = warp * 32 + sub * 16 + gid, d1 = d0 + 8;
            float bv0 = bv[d0], bv1 = bv[d1];
#pragma unroll
            for (int kp = 0; kp < 4; kp++) {
                int ne = 2 * kp, no = ne + 1;
                uint32_t e0, f0, e1, f1;
                split2h(av[sub][ne][0] + bv0, av[sub][ne][1] + bv0, e0, f0);
                split2h(av[sub][no][0] + bv0, av[sub][no][1] + bv0, e1, f1);
                *reinterpret_cast<uint4*>(VTS + d0 * VSTR + ((kp + d0) & 3) * 16 + tg * 4) =
                    make_uint4(e0, e1, f0, f1);
                split2h(av[sub][ne][2] + bv1, av[sub][ne][3] + bv1, e0, f0);
                split2h(av[sub][no][2] + bv1, av[sub][no][3] + bv1, e1, f1);
                *reinterpret_cast<uint4*>(VTS + d1 * VSTR + ((kp + d1) & 3) * 16 + tg * 4) =
                    make_uint4(e0, e1, f0, f1);
            }
        }
    }
    for (int i = t; i < 1800; i += 256) TAB[i] = g_tab[i];
    __syncthreads();

    // ---- attention: warp = head h. S via MMA (3-term); softmax in regs;
    //      P (split) chains into PV MMA (3-term).
    {
        const int h = warp;
        const float NEG_INF = __int_as_float(0xff800000);
        int gmA[8], gmB[8];
#pragma unroll
        for (int nt = 0; nt < 8; nt++) {
            gmA[nt] = GID[nt * 8 + 2 * tg];
            gmB[nt] = GID[nt * 8 + 2 * tg + 1];
        }
#pragma unroll 1
        for (int mt = 0; mt < 4; mt++) {
            float S[8][4];
#pragma unroll
            for (int nt = 0; nt < 8; nt++)
#pragma unroll
                for (int j = 0; j < 4; j++) S[nt][j] = 0.f;
#pragma unroll
            for (int kc = 0; kc < 2; kc++) {
                const uint4 A0 = *reinterpret_cast<const uint4*>(
                    QS + (mt * 16 + gid) * XSTR + (2 * h + kc) * 16 + tg * 4);
                const uint4 A1 = *reinterpret_cast<const uint4*>(
                    QS + (mt * 16 + gid + 8) * XSTR + (2 * h + kc) * 16 + tg * 4);
#pragma unroll
                for (int nt = 0; nt < 8; nt++) {
                    const uint4 Bv = *reinterpret_cast<const uint4*>(
                        KS + (nt * 8 + gid) * XSTR + (2 * h + kc) * 16 + tg * 4);
                    MMA3(S[nt], A0, A1, Bv);
                }
            }
            int r0 = mt * 16 + gid, r1 = r0 + 8;
            int gn0 = GID[r0], gn1 = GID[r1];
            int rn0 = r0 >> 3, cn0 = r0 & 7, rn1 = r1 >> 3, cn1 = r1 & 7;
            float mx0 = NEG_INF, mx1 = NEG_INF;
#pragma unroll
            for (int nt = 0; nt < 8; nt++) {
                int mA = nt * 8 + 2 * tg, mB = mA + 1;
                int rmA = mA >> 3, cmA = mA & 7, rmB = mB >> 3, cmB = mB & 7;
                S[nt][0] = (gn0 == gmA[nt]) ? S[nt][0] + TAB[((rn0-rmA+7)*15 + cn0-cmA+7)*8 + h] : NEG_INF;
                S[nt][1] = (gn0 == gmB[nt]) ? S[nt][1] + TAB[((rn0-rmB+7)*15 + cn0-cmB+7)*8 + h] : NEG_INF;
                S[nt][2] = (gn1 == gmA[nt]) ? S[nt][2] + TAB[((rn1-rmA+7)*15 + cn1-cmA+7)*8 + h] : NEG_INF;
                S[nt][3] = (gn1 == gmB[nt]) ? S[nt][3] + TAB[((rn1-rmB+7)*15 + cn1-cmB+7)*8 + h] : NEG_INF;
                mx0 = fmaxf(mx0, fmaxf(S[nt][0], S[nt][1]));
                mx1 = fmaxf(mx1, fmaxf(S[nt][2], S[nt][3]));
            }
            mx0 = fmaxf(mx0, __shfl_xor_sync(0xffffffffu, mx0, 1));
            mx0 = fmaxf(mx0, __shfl_xor_sync(0xffffffffu, mx0, 2));
            mx1 = fmaxf(mx1, __shfl_xor_sync(0xffffffffu, mx1, 1));
            mx1 = fmaxf(mx1, __shfl_xor_sync(0xffffffffu, mx1, 2));
            float s0 = 0.f, s1 = 0.f;
#pragma unroll
            for (int nt = 0; nt < 8; nt++) {
                S[nt][0] = __expf(S[nt][0] - mx0); s0 += S[nt][0];
                S[nt][1] = __expf(S[nt][1] - mx0); s0 += S[nt][1];
                S[nt][2] = __expf(S[nt][2] - mx1); s1 += S[nt][2];
                S[nt][3] = __expf(S[nt][3] - mx1); s1 += S[nt][3];
            }
            s0 += __shfl_xor_sync(0xffffffffu, s0, 1);
            s0 += __shfl_xor_sync(0xffffffffu, s0, 2);
            s1 += __shfl_xor_sync(0xffffffffu, s1, 1);
            s1 += __shfl_xor_sync(0xffffffffu, s1, 2);
            float inv0 = 1.f / s0, inv1 = 1.f / s1;
            uint32_t ph0[8], ph1[8], pl0[8], pl1[8];
#pragma unroll
            for (int nt = 0; nt < 8; nt++) {
                split2h(S[nt][0] * inv0, S[nt][1] * inv0, ph0[nt], pl0[nt]);
                split2h(S[nt][2] * inv1, S[nt][3] * inv1, ph1[nt], pl1[nt]);
            }
            float O[4][4];
#pragma unroll
            for (int dt = 0; dt < 4; dt++)
#pragma unroll
                for (int j = 0; j < 4; j++) O[dt][j] = 0.f;
#pragma unroll
            for (int kp = 0; kp < 4; kp++) {
                uint32_t ah0 = ph0[2*kp], ah1 = ph1[2*kp], ah2 = ph0[2*kp+1], ah3 = ph1[2*kp+1];
                uint32_t al0 = pl0[2*kp], al1 = pl1[2*kp], al2 = pl0[2*kp+1], al3 = pl1[2*kp+1];
#pragma unroll
                for (int dt = 0; dt < 4; dt++) {
                    int d = h * 32 + dt * 8 + gid;
                    const uint4 Bv = *reinterpret_cast<const uint4*>(
                        VTS + d * VSTR + ((kp + d) & 3) * 16 + tg * 4);
                    MMAH(O[dt], ah0, ah1, ah2, ah3, Bv.x, Bv.y);
                    MMAH(O[dt], al0, al1, al2, al3, Bv.x, Bv.y);
                    MMAH(O[dt], ah0, ah1, ah2, ah3, Bv.z, Bv.w);
                }
            }
            // store O (F4) into QS chunks 2h/2h+1 (this warp's private cols)
#pragma unroll
            for (int gg = 0; gg < 2; gg++) {
                uint32_t e0, f0, e1, f1;
                split2h(O[2*gg][0], O[2*gg][1], e0, f0);
                split2h(O[2*gg+1][0], O[2*gg+1][1], e1, f1);
                *reinterpret_cast<uint4*>(QS + r0 * XSTR + (2*h + gg) * 16 + tg * 4) =
                    make_uint4(e0, e1, f0, f1);
                split2h(O[2*gg][2], O[2*gg][3], e0, f0);
                split2h(O[2*gg+1][2], O[2*gg+1][3], e1, f1);
                *reinterpret_cast<uint4*>(QS + r1 * XSTR + (2*h + gg) * 16 + tg * 4) =
                    make_uint4(e0, e1, f0, f1);
            }
        }
    }

    // ---- Z = O wo^T + bo -> global with inverse cyclic shift
    gemm_proj(QS, g_w4 + 3 * 32768, WT, acc, warpM, warpN, gid, tg, t);
    {
        int rr0 = r0w >> 3, cc0 = r0w & 7;
        int rr1 = r1w >> 3, cc1 = r1w & 7;
        int oh0 = (wh * 8 + rr0 + 12) & 15, ow0 = (ww * 8 + cc0 + 12) & 15;
        int oh1 = (wh * 8 + rr1 + 12) & 15, ow1 = (ww * 8 + cc1 + 12) & 15;
        float* d0 = out + ((size_t)(b * 16 + oh0) * 16 + ow0) * 256;
        float* d1 = out + ((size_t)(b * 16 + oh1) * 16 + ow1) * 256;
#pragma unroll
        for (int nf = 0; nf < 16; nf++) {
            int c = warpN * 128 + nf * 8 + 2 * tg;
            float2 bb = *reinterpret_cast<const float2*>(bo + c);
            float2 z0 = {acc[nf][0] + bb.x, acc[nf][1] + bb.y};
            float2 z1 = {acc[nf][2] + bb.x, acc[nf][3] + bb.y};
            *reinterpret_cast<float2*>(&d0[c]) = z0;
            *reinterpret_cast<float2*>(&d1[c]) = z1;
        }
    }
}

// ---------------------------------------------------------------------------
extern "C" void kernel_launch(void* const* d_in, const int* in_sizes, int n_in,
                              void* d_out, int out_size)
{
    const float* img = (const float*)d_in[0];
    const float* wq  = (const float*)d_in[1];
    const float* bq  = (const float*)d_in[2];
    const float* wk  = (const float*)d_in[3];
    const float* bk  = (const float*)d_in[4];
    const float* wv  = (const float*)d_in[5];
    const float* bv  = (const float*)d_in[6];
    const float* wo  = (const float*)d_in[7];
    const float* bo  = (const float*)d_in[8];
    const float* ls  = (const float*)d_in[9];
    const float* cw1 = (const float*)d_in[10];
    const float* cb1 = (const float*)d_in[11];
    const float* cw2 = (const float*)d_in[12];
    (void)in_sizes; (void)n_in; (void)out_size;

    cudaFuncSetAttribute(swin_kernel,
                         cudaFuncAttributeMaxDynamicSharedMemorySize,
                         SMEM_U32 * 4);

    prep_kernel<<<257, 256>>>(cw1, cb1, cw2, wq, wk, wv, wo);
    swin_kernel<<<2048, 256, SMEM_U32 * 4>>>(img, bq, bk, bv, bo, ls,
                                             (float*)d_out);
}

// round 7
// speedup vs baseline: 2.3450x; 1.0785x over previous
#include <cuda_runtime.h>
#include <cuda_fp16.h>
#include <math.h>
#include <stdint.h>

// Swin-V2 shifted-window MHA: split-fp16 tensor-core (mma.m16n8k16.f16).
// One CTA (256 thr = 8 warps) per window; 2048 CTAs. Warp = head in attention.
// Projections: 2-term split (Ah*Bh + Al*Bh), W hi-only. Attention: 3-term.
//
// "F4" layout (x, Q, K, O): u32 rows of XSTR; chunk g (16 values), group tg:
//   uint4 at row*XSTR + g*16 + tg*4 = {hi(pair g8+tg), hi(pair g8+tg+4), lo, lo}
// Weight chunk layout (global + staged): per 16-wide chunk, row n = 8 u32:
//   u32[tg*2] = hi pair tg, u32[tg*2+1] = hi pair tg+4; uint4-slot XOR swizzle
//   by (n>>2)&1 in SMEM (conflict-free STS.128 staging + LDS.64 reads).

#define XSTR 272
#define VSTR 64

#define OFF_X   0        // x F4 (17408); VT F4 (16384) overlays after V gemm
#define OFF_Q   17408    // Q F4 -> O F4
#define OFF_K   34816    // K F4
#define OFF_WT  52224    // 2 x 2048 u32 double-buffered weight chunk
#define SMEM_U32 56320   // 225280 bytes

__device__ uint32_t g_wh[4 * 16 * 256 * 8];   // [w][kc][n][8] fp16-hi pairs
__device__ float    g_bias[4 * 8 * 64 * 64];  // [wtype][h][n][m], masked=-1e30

__device__ __forceinline__ uint32_t pack2h(float x, float y) {
    __half hx = __float2half_rn(x), hy = __float2half_rn(y);
    return (uint32_t)__half_as_ushort(hx) | ((uint32_t)__half_as_ushort(hy) << 16);
}
__device__ __forceinline__ void split2h(float x, float y, uint32_t& h, uint32_t& l) {
    __half hx = __float2half_rn(x), hy = __float2half_rn(y);
    float rx = x - __half2float(hx), ry = y - __half2float(hy);
    h = (uint32_t)__half_as_ushort(hx) | ((uint32_t)__half_as_ushort(hy) << 16);
    l = pack2h(rx, ry);
}

#define MMAH(C, A0, A1, A2, A3, B0, B1)                                       \
    asm volatile("mma.sync.aligned.m16n8k16.row.col.f32.f16.f16.f32 "         \
                 "{%0,%1,%2,%3}, {%4,%5,%6,%7}, {%8,%9}, {%0,%1,%2,%3};"      \
                 : "+f"(C[0]), "+f"(C[1]), "+f"(C[2]), "+f"(C[3])             \
                 : "r"(A0), "r"(A1), "r"(A2), "r"(A3), "r"(B0), "r"(B1))

// 3-term split (attention): Ah*Bh + Al*Bh + Ah*Bl
#define MMA3(C, A0, A1, B)                                                    \
    do {                                                                      \
        MMAH(C, (A0).x, (A1).x, (A0).y, (A1).y, (B).x, (B).y);                \
        MMAH(C, (A0).z, (A1).z, (A0).w, (A1).w, (B).x, (B).y);                \
        MMAH(C, (A0).x, (A1).x, (A0).y, (A1).y, (B).z, (B).w);                \
    } while (0)

// ---------------------------------------------------------------------------
// Prep: blocks 0..63 = weight split; blocks 64..288 = masked bias table.
// ---------------------------------------------------------------------------
__global__ void prep_kernel(const float* __restrict__ w1,
                            const float* __restrict__ b1,
                            const float* __restrict__ w2,
                            const float* __restrict__ wq,
                            const float* __restrict__ wk,
                            const float* __restrict__ wv,
                            const float* __restrict__ wo)
{
    __shared__ float ws[8][8];
    __shared__ float bv[8];
    int t = threadIdx.x;

    if (blockIdx.x < 64) {
        const float* wsrc[4] = {wq, wk, wv, wo};
        int w = blockIdx.x >> 4, kc = blockIdx.x & 15;
        const float* src = wsrc[w] + t * 256 + kc * 16;
        float v[16];
#pragma unroll
        for (int i = 0; i < 4; i++) {
            float4 q = *reinterpret_cast<const float4*>(src + i * 4);
            v[4*i] = q.x; v[4*i+1] = q.y; v[4*i+2] = q.z; v[4*i+3] = q.w;
        }
        uint32_t u[8];
#pragma unroll
        for (int tg = 0; tg < 4; tg++) {
            u[tg*2]   = pack2h(v[2*tg],   v[2*tg+1]);
            u[tg*2+1] = pack2h(v[8+2*tg], v[9+2*tg]);
        }
        uint32_t* dst = g_wh + (blockIdx.x * 256 + t) * 8;
        *reinterpret_cast<uint4*>(dst)     = make_uint4(u[0], u[1], u[2], u[3]);
        *reinterpret_cast<uint4*>(dst + 4) = make_uint4(u[4], u[5], u[6], u[7]);
        return;
    }

    // ---- bias cell: CPB MLP for one relative-position cell, scatter masked
    int cell = blockIdx.x - 64;           // 0..224
    int a = cell / 15, bcol = cell % 15;
    float ra = (a - 7) * (8.0f / 7.0f);
    float rb = (bcol - 7) * (8.0f / 7.0f);
    float va = (ra >= 0.f ? 1.f : -1.f) * log2f(fabsf(ra) + 1.f) * (1.f / 3.f);
    float vb = (rb >= 0.f ? 1.f : -1.f) * log2f(fabsf(rb) + 1.f) * (1.f / 3.f);

    int j1 = t, j2 = t + 256;
    float h1 = fmaxf(va * w1[j1 * 2] + vb * w1[j1 * 2 + 1] + b1[j1], 0.f);
    float h2 = fmaxf(va * w1[j2 * 2] + vb * w1[j2 * 2 + 1] + b1[j2], 0.f);

    float p[8];
#pragma unroll
    for (int h = 0; h < 8; h++)
        p[h] = h1 * w2[h * 512 + j1] + h2 * w2[h * 512 + j2];
#pragma unroll
    for (int h = 0; h < 8; h++)
#pragma unroll
        for (int off = 16; off; off >>= 1)
            p[h] += __shfl_xor_sync(0xffffffffu, p[h], off);

    int warp = t >> 5, lane = t & 31;
    if (lane == 0) {
#pragma unroll
        for (int h = 0; h < 8; h++) ws[warp][h] = p[h];
    }
    __syncthreads();
    if (t < 8) {
        float s = 0.f;
#pragma unroll
        for (int w = 0; w < 8; w++) s += ws[w][t];
        bv[t] = 16.f / (1.f + expf(-s));
    }
    __syncthreads();

    int da = a - 7, db = bcol - 7;
    int cntA = 8 - abs(da), cntB = 8 - abs(db);
    int rn0 = da > 0 ? da : 0, cn0 = db > 0 ? db : 0;
    int total = cntA * cntB * 32;
    for (int idx = t; idx < total; idx += 256) {
        int tmp = idx;
        int h = tmp & 7; tmp >>= 3;
        int wt_ = tmp & 3; tmp >>= 2;
        int pa = tmp / cntB, pb = tmp - pa * cntB;
        int rn = rn0 + pa, cn = cn0 + pb;
        int rm = rn - da, cm = cn - db;
        int wh = wt_ >> 1, ww = wt_ & 1;
        int ghn = wh * 8 + rn, gwn = ww * 8 + cn;
        int ghm = wh * 8 + rm, gwm = ww * 8 + cm;
        int gn = ((ghn < 8) ? 0 : (ghn < 12 ? 1 : 2)) * 3 + ((gwn < 8) ? 0 : (gwn < 12 ? 1 : 2));
        int gm = ((ghm < 8) ? 0 : (ghm < 12 ? 1 : 2)) * 3 + ((gwm < 8) ? 0 : (gwm < 12 ? 1 : 2));
        float val = (gn == gm) ? bv[h] : -1e30f;
        g_bias[((wt_ * 8 + h) * 64 + rn * 8 + cn) * 64 + rm * 8 + cm] = val;
    }
}

// ---------------------------------------------------------------------------
// Projection GEMM (2-term): out(64x256) = A(F4 smem) @ Whi^T.
// Warp tile 32x64: rows rbase+{gid,+8,+16,+24}, cols warpN*64 + nf*8 + 2tg.
// Double-buffered chunk staging; one barrier per 16-wide chunk.
// ---------------------------------------------------------------------------
__device__ __forceinline__ void gemm_proj(
    const uint32_t* __restrict__ src, const uint32_t* __restrict__ gw,
    uint32_t* __restrict__ wt, float acc[2][8][4],
    int rbase, int warpN, int gid, int tg, int bslot, int t)
{
#pragma unroll
    for (int s = 0; s < 2; s++)
#pragma unroll
        for (int nf = 0; nf < 8; nf++)
#pragma unroll
            for (int j = 0; j < 4; j++) acc[s][nf][j] = 0.f;

    const uint4* g4 = reinterpret_cast<const uint4*>(gw) + t * 2;
    uint4 c0 = g4[0], c1 = g4[1];
    const int sw = (t >> 2) & 1;
    const uint32_t* a0p = src + (rbase + gid) * XSTR + tg * 4;

#pragma unroll 1
    for (int kc = 0; kc < 16; kc++) {
        uint32_t* buf = wt + (kc & 1) * 2048;
        uint4* s4 = reinterpret_cast<uint4*>(buf + t * 8);
        s4[sw] = c0; s4[sw ^ 1] = c1;
        if (kc < 15) { const uint4* gn = g4 + (kc + 1) * 512; c0 = gn[0]; c1 = gn[1]; }
        __syncthreads();
        const uint4 A0 = *reinterpret_cast<const uint4*>(a0p + kc * 16);
        const uint4 A1 = *reinterpret_cast<const uint4*>(a0p + kc * 16 + 8 * XSTR);
        const uint4 A2 = *reinterpret_cast<const uint4*>(a0p + kc * 16 + 16 * XSTR);
        const uint4 A3 = *reinterpret_cast<const uint4*>(a0p + kc * 16 + 24 * XSTR);
        const uint32_t* bp = buf + (warpN * 64 + gid) * 8 + bslot;
#pragma unroll
        for (int nf = 0; nf < 8; nf++) {
            uint2 Bv = *reinterpret_cast<const uint2*>(bp + nf * 64);
            MMAH(acc[0][nf], A0.x, A1.x, A0.y, A1.y, Bv.x, Bv.y);
            MMAH(acc[0][nf], A0.z, A1.z, A0.w, A1.w, Bv.x, Bv.y);
            MMAH(acc[1][nf], A2.x, A3.x, A2.y, A3.y, Bv.x, Bv.y);
            MMAH(acc[1][nf], A2.z, A3.z, A2.w, A3.w, Bv.x, Bv.y);
        }
    }
}

// ---------------------------------------------------------------------------
// VT GEMM (2-term): VT(256x64) = Wv_hi (staged, A) @ x^T (B = x F4 hi+lo).
// Warp: 32 d-rows. Ends with a barrier (X overwrite safety).
// ---------------------------------------------------------------------------
__device__ __forceinline__ void gemm_vt(
    const uint32_t* __restrict__ x, const uint32_t* __restrict__ gw,
    uint32_t* __restrict__ wt, float av[2][8][4],
    int warp, int gid, int tg, int bslot, int t)
{
#pragma unroll
    for (int s = 0; s < 2; s++)
#pragma unroll
        for (int nf = 0; nf < 8; nf++)
#pragma unroll
            for (int j = 0; j < 4; j++) av[s][nf][j] = 0.f;

    const uint4* g4 = reinterpret_cast<const uint4*>(gw) + t * 2;
    uint4 c0 = g4[0], c1 = g4[1];
    const int sw = (t >> 2) & 1;
    const uint32_t* xp0 = x + gid * XSTR + tg * 4;

#pragma unroll 1
    for (int kc = 0; kc < 16; kc++) {
        uint32_t* buf = wt + (kc & 1) * 2048;
        uint4* s4 = reinterpret_cast<uint4*>(buf + t * 8);
        s4[sw] = c0; s4[sw ^ 1] = c1;
        if (kc < 15) { const uint4* gn = g4 + (kc + 1) * 512; c0 = gn[0]; c1 = gn[1]; }
        __syncthreads();
        const uint32_t* wrow = buf + (warp * 32 + gid) * 8 + bslot;
        uint2 Wa0 = *reinterpret_cast<const uint2*>(wrow);
        uint2 Wa1 = *reinterpret_cast<const uint2*>(wrow + 64);
        uint2 Wb0 = *reinterpret_cast<const uint2*>(wrow + 128);
        uint2 Wb1 = *reinterpret_cast<const uint2*>(wrow + 192);
        const uint32_t* xp = xp0 + kc * 16;
#pragma unroll
        for (int nf = 0; nf < 8; nf++) {
            uint4 Xv = *reinterpret_cast<const uint4*>(xp + nf * 8 * XSTR);
            MMAH(av[0][nf], Wa0.x, Wa1.x, Wa0.y, Wa1.y, Xv.x, Xv.y);
            MMAH(av[0][nf], Wa0.x, Wa1.x, Wa0.y, Wa1.y, Xv.z, Xv.w);
            MMAH(av[1][nf], Wb0.x, Wb1.x, Wb0.y, Wb1.y, Xv.x, Xv.y);
            MMAH(av[1][nf], Wb0.x, Wb1.x, Wb0.y, Wb1.y, Xv.z, Xv.w);
        }
    }
    __syncthreads();   // all X reads complete before VTS overwrite
}

// ---------------------------------------------------------------------------
__global__ __launch_bounds__(256, 1)
void swin_kernel(const float* __restrict__ img,
                 const float* __restrict__ bq, const float* __restrict__ bk,
                 const float* __restrict__ bv, const float* __restrict__ bo,
                 const float* __restrict__ ls,
                 float* __restrict__ out)
{
    extern __shared__ uint32_t smu[];
    uint32_t* X   = smu + OFF_X;
    uint32_t* QS  = smu + OFF_Q;
    uint32_t* KS  = smu + OFF_K;
    uint32_t* VTS = smu + OFF_X;        // overlays X after V gemm
    uint32_t* WT  = smu + OFF_WT;

    const int t    = threadIdx.x;
    const int lane = t & 31;
    const int warp = t >> 5;
    const int warpM = warp & 1, warpN = warp >> 1;
    const int gid = lane >> 2, tg = lane & 3;
    const int bslot = ((((tg >> 1) ^ ((gid >> 2) & 1)) << 2) | ((tg & 1) << 1));
    const int blk = blockIdx.x;
    const int b   = blk >> 2;
    const int wh  = (blk >> 1) & 1, ww = blk & 1;
    const int wtype = blk & 3;

    // ---- load shifted window -> x F4 split (fp16 hi/lo)
    const float* imgb = img + (size_t)b * (16 * 16 * 256);
#pragma unroll
    for (int i = 0; i < 16; i++) {
        int f = i * 256 + t;            // float4 index
        int tok = f >> 6, c4 = f & 63;
        int r = tok >> 3, c = tok & 7;
        int ih = (wh * 8 + r + 12) & 15;
        int iw = (ww * 8 + c + 12) & 15;
        float4 v = *reinterpret_cast<const float4*>(&imgb[(ih * 16 + iw) * 256 + c4 * 4]);
        uint32_t h0, l0, h1, l1;
        split2h(v.x, v.y, h0, l0);
        split2h(v.z, v.w, h1, l1);
        int p0 = 2 * c4;
        int g = p0 >> 3, pos = p0 & 7;
        int tgs = pos & 3, slot = pos >> 2;
        uint32_t* base = X + tok * XSTR + g * 16 + slot;
        base[tgs * 4]           = h0;
        base[(tgs + 1) * 4]     = h1;
        base[tgs * 4 + 2]       = l0;
        base[(tgs + 1) * 4 + 2] = l1;
    }
    // gemm's first internal barrier orders these stores before any A read

    float acc[2][8][4];
    const int rbase = warpM * 32;

    // ---- Q = x wq^T + bq, cosine-normalize * scale, split -> QS
    gemm_proj(X, g_wh + 0 * 32768, WT, acc, rbase, warpN, gid, tg, bslot, t);
    {
#pragma unroll
        for (int sub = 0; sub < 2; sub++)
#pragma unroll
            for (int nf = 0; nf < 8; nf++) {
                float2 bb = *reinterpret_cast<const float2*>(bq + warpN * 64 + nf * 8 + 2 * tg);
                acc[sub][nf][0] += bb.x; acc[sub][nf][1] += bb.y;
                acc[sub][nf][2] += bb.x; acc[sub][nf][3] += bb.y;
            }
#pragma unroll
        for (int sub = 0; sub < 2; sub++) {
            int r0 = rbase + sub * 16 + gid, r1 = r0 + 8;
#pragma unroll
            for (int g = 0; g < 2; g++) {
                float ss0 = 0.f, ss1 = 0.f;
#pragma unroll
                for (int i = 0; i < 4; i++) {
                    float* C = acc[sub][4*g+i];
                    ss0 += C[0]*C[0] + C[1]*C[1];
                    ss1 += C[2]*C[2] + C[3]*C[3];
                }
                ss0 += __shfl_xor_sync(0xffffffffu, ss0, 1);
                ss0 += __shfl_xor_sync(0xffffffffu, ss0, 2);
                ss1 += __shfl_xor_sync(0xffffffffu, ss1, 1);
                ss1 += __shfl_xor_sync(0xffffffffu, ss1, 2);
                float sc = __expf(fminf(ls[warpN * 2 + g], 4.6051702f));
                float k0 = sc / fmaxf(sqrtf(ss0), 1e-12f);
                float k1 = sc / fmaxf(sqrtf(ss1), 1e-12f);
#pragma unroll
                for (int u = 0; u < 2; u++) {
                    int ne = 4*g + 2*u, no = ne + 1;
                    int ch = warpN * 4 + 2*g + u;
                    uint32_t He, Le, Ho, Lo;
                    split2h(acc[sub][ne][0]*k0, acc[sub][ne][1]*k0, He, Le);
                    split2h(acc[sub][no][0]*k0, acc[sub][no][1]*k0, Ho, Lo);
                    *reinterpret_cast<uint4*>(QS + r0*XSTR + ch*16 + tg*4) = make_uint4(He, Ho, Le, Lo);
                    split2h(acc[sub][ne][2]*k1, acc[sub][ne][3]*k1, He, Le);
                    split2h(acc[sub][no][2]*k1, acc[sub][no][3]*k1, Ho, Lo);
                    *reinterpret_cast<uint4*>(QS + r1*XSTR + ch*16 + tg*4) = make_uint4(He, Ho, Le, Lo);
                }
            }
        }
    }

    // ---- K = x wk^T + bk, normalize, split -> KS
    gemm_proj(X, g_wh + 1 * 32768, WT, acc, rbase, warpN, gid, tg, bslot, t);
    {
#pragma unroll
        for (int sub = 0; sub < 2; sub++)
#pragma unroll
            for (int nf = 0; nf < 8; nf++) {
                float2 bb = *reinterpret_cast<const float2*>(bk + warpN * 64 + nf * 8 + 2 * tg);
                acc[sub][nf][0] += bb.x; acc[sub][nf][1] += bb.y;
                acc[sub][nf][2] += bb.x; acc[sub][nf][3] += bb.y;
            }
#pragma unroll
        for (int sub = 0; sub < 2; sub++) {
            int r0 = rbase + sub * 16 + gid, r1 = r0 + 8;
#pragma unroll
            for (int g = 0; g < 2; g++) {
                float ss0 = 0.f, ss1 = 0.f;
#pragma unroll
                for (int i = 0; i < 4; i++) {
                    float* C = acc[sub][4*g+i];
                    ss0 += C[0]*C[0] + C[1]*C[1];
                    ss1 += C[2]*C[2] + C[3]*C[3];
                }
                ss0 += __shfl_xor_sync(0xffffffffu, ss0, 1);
                ss0 += __shfl_xor_sync(0xffffffffu, ss0, 2);
                ss1 += __shfl_xor_sync(0xffffffffu, ss1, 1);
                ss1 += __shfl_xor_sync(0xffffffffu, ss1, 2);
                float k0 = 1.f / fmaxf(sqrtf(ss0), 1e-12f);
                float k1 = 1.f / fmaxf(sqrtf(ss1), 1e-12f);
#pragma unroll
                for (int u = 0; u < 2; u++) {
                    int ne = 4*g + 2*u, no = ne + 1;
                    int ch = warpN * 4 + 2*g + u;
                    uint32_t He, Le, Ho, Lo;
                    split2h(acc[sub][ne][0]*k0, acc[sub][ne][1]*k0, He, Le);
                    split2h(acc[sub][no][0]*k0, acc[sub][no][1]*k0, Ho, Lo);
                    *reinterpret_cast<uint4*>(KS + r0*XSTR + ch*16 + tg*4) = make_uint4(He, Ho, Le, Lo);
                    split2h(acc[sub][ne][2]*k1, acc[sub][ne][3]*k1, He, Le);
                    split2h(acc[sub][no][2]*k1, acc[sub][no][3]*k1, Ho, Lo);
                    *reinterpret_cast<uint4*>(KS + r1*XSTR + ch*16 + tg*4) = make_uint4(He, Ho, Le, Lo);
                }
            }
        }
    }

    // ---- VT = wv x^T + bv (transposed V), F4 split -> VTS (overlays X)
    {
        float av[2][8][4];
        gemm_vt(X, g_wh + 2 * 32768, WT, av, warp, gid, tg, bslot, t);
#pragma unroll
        for (int sub = 0; sub < 2; sub++) {
            int d0 = warp * 32 + sub * 16 + gid, d1 = d0 + 8;
            float bv0 = bv[d0], bv1 = bv[d1];
#pragma unroll
            for (int kp = 0; kp < 4; kp++) {
                int ne = 2 * kp, no = ne + 1;
                uint32_t e0, f0, e1, f1;
                split2h(av[sub][ne][0] + bv0, av[sub][ne][1] + bv0, e0, f0);
                split2h(av[sub][no][0] + bv0, av[sub][no][1] + bv0, e1, f1);
                *reinterpret_cast<uint4*>(VTS + d0 * VSTR + ((kp + d0) & 3) * 16 + tg * 4) =
                    make_uint4(e0, e1, f0, f1);
                split2h(av[sub][ne][2] + bv1, av[sub][ne][3] + bv1, e0, f0);
                split2h(av[sub][no][2] + bv1, av[sub][no][3] + bv1, e1, f1);
                *reinterpret_cast<uint4*>(VTS + d1 * VSTR + ((kp + d1) & 3) * 16 + tg * 4) =
                    make_uint4(e0, e1, f0, f1);
            }
        }
    }
    __syncthreads();   // Q/K/VT all visible before attention

    // ---- attention: warp = head h. S via MMA (3-term); precomputed masked
    //      bias via LDG; softmax in regs; P (split) chains into PV MMA.
    {
        const int h = warp;
        const float NEG_INF = __int_as_float(0xff800000);
        const float* bias = g_bias + (wtype * 8 + h) * 4096;
#pragma unroll 1
        for (int mt = 0; mt < 4; mt++) {
            int r0 = mt * 16 + gid, r1 = r0 + 8;
            float2 B0[8], B1[8];
#pragma unroll
            for (int nt = 0; nt < 8; nt++) {
                B0[nt] = *reinterpret_cast<const float2*>(bias + r0 * 64 + nt * 8 + 2 * tg);
                B1[nt] = *reinterpret_cast<const float2*>(bias + r1 * 64 + nt * 8 + 2 * tg);
            }
            float S[8][4];
#pragma unroll
            for (int nt = 0; nt < 8; nt++)
#pragma unroll
                for (int j = 0; j < 4; j++) S[nt][j] = 0.f;
#pragma unroll
            for (int kc = 0; kc < 2; kc++) {
                const uint4 A0 = *reinterpret_cast<const uint4*>(
                    QS + r0 * XSTR + (2 * h + kc) * 16 + tg * 4);
                const uint4 A1 = *reinterpret_cast<const uint4*>(
                    QS + r1 * XSTR + (2 * h + kc) * 16 + tg * 4);
#pragma unroll
                for (int nt = 0; nt < 8; nt++) {
                    const uint4 Bv = *reinterpret_cast<const uint4*>(
                        KS + (nt * 8 + gid) * XSTR + (2 * h + kc) * 16 + tg * 4);
                    MMA3(S[nt], A0, A1, Bv);
                }
            }
            float mx0 = NEG_INF, mx1 = NEG_INF;
#pragma unroll
            for (int nt = 0; nt < 8; nt++) {
                S[nt][0] += B0[nt].x;
                S[nt][1] += B0[nt].y;
                S[nt][2] += B1[nt].x;
                S[nt][3] += B1[nt].y;
                mx0 = fmaxf(mx0, fmaxf(S[nt][0], S[nt][1]));
                mx1 = fmaxf(mx1, fmaxf(S[nt][2], S[nt][3]));
            }
            mx0 = fmaxf(mx0, __shfl_xor_sync(0xffffffffu, mx0, 1));
            mx0 = fmaxf(mx0, __shfl_xor_sync(0xffffffffu, mx0, 2));
            mx1 = fmaxf(mx1, __shfl_xor_sync(0xffffffffu, mx1, 1));
            mx1 = fmaxf(mx1, __shfl_xor_sync(0xffffffffu, mx1, 2));
            float s0 = 0.f, s1 = 0.f;
#pragma unroll
            for (int nt = 0; nt < 8; nt++) {
                S[nt][0] = __expf(S[nt][0] - mx0); s0 += S[nt][0];
                S[nt][1] = __expf(S[nt][1] - mx0); s0 += S[nt][1];
                S[nt][2] = __expf(S[nt][2] - mx1); s1 += S[nt][2];
                S[nt][3] = __expf(S[nt][3] - mx1); s1 += S[nt][3];
            }
            s0 += __shfl_xor_sync(0xffffffffu, s0, 1);
            s0 += __shfl_xor_sync(0xffffffffu, s0, 2);
            s1 += __shfl_xor_sync(0xffffffffu, s1, 1);
            s1 += __shfl_xor_sync(0xffffffffu, s1, 2);
            float inv0 = 1.f / s0, inv1 = 1.f / s1;
            uint32_t ph0[8], ph1[8], pl0[8], pl1[8];
#pragma unroll
            for (int nt = 0; nt < 8; nt++) {
                split2h(S[nt][0] * inv0, S[nt][1] * inv0, ph0[nt], pl0[nt]);
                split2h(S[nt][2] * inv1, S[nt][3] * inv1, ph1[nt], pl1[nt]);
            }
            float O[4][4];
#pragma unroll
            for (int dt = 0; dt < 4; dt++)
#pragma unroll
                for (int j = 0; j < 4; j++) O[dt][j] = 0.f;
#pragma unroll
            for (int kp = 0; kp < 4; kp++) {
                uint32_t ah0 = ph0[2*kp], ah1 = ph1[2*kp], ah2 = ph0[2*kp+1], ah3 = ph1[2*kp+1];
                uint32_t al0 = pl0[2*kp], al1 = pl1[2*kp], al2 = pl0[2*kp+1], al3 = pl1[2*kp+1];
#pragma unroll
                for (int dt = 0; dt < 4; dt++) {
                    int d = h * 32 + dt * 8 + gid;
                    const uint4 Bv = *reinterpret_cast<const uint4*>(
                        VTS + d * VSTR + ((kp + d) & 3) * 16 + tg * 4);
                    MMAH(O[dt], ah0, ah1, ah2, ah3, Bv.x, Bv.y);
                    MMAH(O[dt], al0, al1, al2, al3, Bv.x, Bv.y);
                    MMAH(O[dt], ah0, ah1, ah2, ah3, Bv.z, Bv.w);
                }
            }
            // store O (F4) into QS chunks 2h/2h+1 (this warp's private cols)
#pragma unroll
            for (int gg = 0; gg < 2; gg++) {
                uint32_t e0, f0, e1, f1;
                split2h(O[2*gg][0], O[2*gg][1], e0, f0);
                split2h(O[2*gg+1][0], O[2*gg+1][1], e1, f1);
                *reinterpret_cast<uint4*>(QS + r0 * XSTR + (2*h + gg) * 16 + tg * 4) =
                    make_uint4(e0, e1, f0, f1);
                split2h(O[2*gg][2], O[2*gg][3], e0, f0);
                split2h(O[2*gg+1][2], O[2*gg+1][3], e1, f1);
                *reinterpret_cast<uint4*>(QS + r1 * XSTR + (2*h + gg) * 16 + tg * 4) =
                    make_uint4(e0, e1, f0, f1);
            }
        }
    }
    // final gemm's first internal barrier orders attention stores before reads

    // ---- Z = O wo^T + bo -> global with inverse cyclic shift
    gemm_proj(QS, g_wh + 3 * 32768, WT, acc, rbase, warpN, gid, tg, bslot, t);
    {
#pragma unroll
        for (int i = 0; i < 4; i++) {
            int r = rbase + i * 8 + gid;
            int rr = r >> 3, cc = r & 7;
            int oh = (wh * 8 + rr + 12) & 15, ow = (ww * 8 + cc + 12) & 15;
            float* d = out + ((size_t)(b * 16 + oh) * 16 + ow) * 256;
            int sub = i >> 1, half = i & 1;
#pragma unroll
            for (int nf = 0; nf < 8; nf++) {
                int c = warpN * 64 + nf * 8 + 2 * tg;
                float2 bb = *reinterpret_cast<const float2*>(bo + c);
                float2 z = {acc[sub][nf][half*2] + bb.x, acc[sub][nf][half*2+1] + bb.y};
                *reinterpret_cast<float2*>(d + c) = z;
            }
        }
    }
}

// ---------------------------------------------------------------------------
extern "C" void kernel_launch(void* const* d_in, const int* in_sizes, int n_in,
                              void* d_out, int out_size)
{
    const float* img = (const float*)d_in[0];
    const float* wq  = (const float*)d_in[1];
    const float* bq  = (const float*)d_in[2];
    const float* wk  = (const float*)d_in[3];
    const float* bk  = (const float*)d_in[4];
    const float* wv  = (const float*)d_in[5];
    const float* bv  = (const float*)d_in[6];
    const float* wo  = (const float*)d_in[7];
    const float* bo  = (const float*)d_in[8];
    const float* ls  = (const float*)d_in[9];
    const float* cw1 = (const float*)d_in[10];
    const float* cb1 = (const float*)d_in[11];
    const float* cw2 = (const float*)d_in[12];
    (void)in_sizes; (void)n_in; (void)out_size;

    cudaFuncSetAttribute(swin_kernel,
                         cudaFuncAttributeMaxDynamicSharedMemorySize,
                         SMEM_U32 * 4);

    prep_kernel<<<289, 256>>>(cw1, cb1, cw2, wq, wk, wv, wo);
    swin_kernel<<<2048, 256, SMEM_U32 * 4>>>(img, bq, bk, bv, bo, ls,
                                             (float*)d_out);
}

// round 8
// speedup vs baseline: 2.5049x; 1.0682x over previous
#include <cuda_runtime.h>
#include <cuda_fp16.h>
#include <math.h>
#include <stdint.h>

// Swin-V2 shifted-window MHA: split-fp16 tensor-core (mma.m16n8k16.f16).
// One CTA (256 thr = 8 warps) per window; 2048 CTAs. Warp = head in attention.
// Projections: 2-term split (Ah*Bh + Al*Bh), W hi-only. Attention: 3-term.
// Weights are read DIRECTLY from global (L2/L1-resident, fragment-ordered,
// coalesced LDG.64, one-chunk-ahead register prefetch) -> no SMEM staging,
// no mainloop barriers; warps run decoupled.
//
// "F4" layout (x, Q, K, O): u32 rows of XSTR; chunk g (16 values), group tg:
//   uint4 at row*XSTR + g*16 + tg*4 = {hi(pair g8+tg), hi(pair g8+tg+4), lo, lo}
// Weight layout: g_wh[w][kc][n][8]: u32[tg*2] = hi pair tg, [tg*2+1] = pair tg+4.

#define XSTR 272
#define VSTR 64

#define OFF_X   0        // x F4 (17408); VT F4 (16384) overlays after V gemm
#define OFF_Q   17408    // Q F4 -> O F4
#define OFF_K   34816    // K F4
#define SMEM_U32 52224   // 208896 bytes

__device__ uint32_t g_wh[4 * 16 * 256 * 8];   // [w][kc][n][8] fp16-hi pairs
__device__ float    g_bias[4 * 8 * 64 * 64];  // [wtype][h][n][m], masked=-1e30

__device__ __forceinline__ uint32_t pack2h(float x, float y) {
    __half hx = __float2half_rn(x), hy = __float2half_rn(y);
    return (uint32_t)__half_as_ushort(hx) | ((uint32_t)__half_as_ushort(hy) << 16);
}
__device__ __forceinline__ void split2h(float x, float y, uint32_t& h, uint32_t& l) {
    __half hx = __float2half_rn(x), hy = __float2half_rn(y);
    float rx = x - __half2float(hx), ry = y - __half2float(hy);
    h = (uint32_t)__half_as_ushort(hx) | ((uint32_t)__half_as_ushort(hy) << 16);
    l = pack2h(rx, ry);
}

#define MMAH(C, A0, A1, A2, A3, B0, B1)                                       \
    asm volatile("mma.sync.aligned.m16n8k16.row.col.f32.f16.f16.f32 "         \
                 "{%0,%1,%2,%3}, {%4,%5,%6,%7}, {%8,%9}, {%0,%1,%2,%3};"      \
                 : "+f"(C[0]), "+f"(C[1]), "+f"(C[2]), "+f"(C[3])             \
                 : "r"(A0), "r"(A1), "r"(A2), "r"(A3), "r"(B0), "r"(B1))

// 3-term split (attention): Ah*Bh + Al*Bh + Ah*Bl
#define MMA3(C, A0, A1, B)                                                    \
    do {                                                                      \
        MMAH(C, (A0).x, (A1).x, (A0).y, (A1).y, (B).x, (B).y);                \
        MMAH(C, (A0).z, (A1).z, (A0).w, (A1).w, (B).x, (B).y);                \
        MMAH(C, (A0).x, (A1).x, (A0).y, (A1).y, (B).z, (B).w);                \
    } while (0)

// ---------------------------------------------------------------------------
// Prep: blocks 0..63 = weight split; blocks 64..288 = masked bias table.
// ---------------------------------------------------------------------------
__global__ void prep_kernel(const float* __restrict__ w1,
                            const float* __restrict__ b1,
                            const float* __restrict__ w2,
                            const float* __restrict__ wq,
                            const float* __restrict__ wk,
                            const float* __restrict__ wv,
                            const float* __restrict__ wo)
{
    __shared__ float ws[8][8];
    __shared__ float bv[8];
    int t = threadIdx.x;

    if (blockIdx.x < 64) {
        const float* wsrc[4] = {wq, wk, wv, wo};
        int w = blockIdx.x >> 4, kc = blockIdx.x & 15;
        const float* src = wsrc[w] + t * 256 + kc * 16;
        float v[16];
#pragma unroll
        for (int i = 0; i < 4; i++) {
            float4 q = *reinterpret_cast<const float4*>(src + i * 4);
            v[4*i] = q.x; v[4*i+1] = q.y; v[4*i+2] = q.z; v[4*i+3] = q.w;
        }
        uint32_t u[8];
#pragma unroll
        for (int tg = 0; tg < 4; tg++) {
            u[tg*2]   = pack2h(v[2*tg],   v[2*tg+1]);
            u[tg*2+1] = pack2h(v[8+2*tg], v[9+2*tg]);
        }
        uint32_t* dst = g_wh + (blockIdx.x * 256 + t) * 8;
        *reinterpret_cast<uint4*>(dst)     = make_uint4(u[0], u[1], u[2], u[3]);
        *reinterpret_cast<uint4*>(dst + 4) = make_uint4(u[4], u[5], u[6], u[7]);
        return;
    }

    // ---- bias cell: CPB MLP for one relative-position cell, scatter masked
    int cell = blockIdx.x - 64;           // 0..224
    int a = cell / 15, bcol = cell % 15;
    float ra = (a - 7) * (8.0f / 7.0f);
    float rb = (bcol - 7) * (8.0f / 7.0f);
    float va = (ra >= 0.f ? 1.f : -1.f) * log2f(fabsf(ra) + 1.f) * (1.f / 3.f);
    float vb = (rb >= 0.f ? 1.f : -1.f) * log2f(fabsf(rb) + 1.f) * (1.f / 3.f);

    int j1 = t, j2 = t + 256;
    float h1 = fmaxf(va * w1[j1 * 2] + vb * w1[j1 * 2 + 1] + b1[j1], 0.f);
    float h2 = fmaxf(va * w1[j2 * 2] + vb * w1[j2 * 2 + 1] + b1[j2], 0.f);

    float p[8];
#pragma unroll
    for (int h = 0; h < 8; h++)
        p[h] = h1 * w2[h * 512 + j1] + h2 * w2[h * 512 + j2];
#pragma unroll
    for (int h = 0; h < 8; h++)
#pragma unroll
        for (int off = 16; off; off >>= 1)
            p[h] += __shfl_xor_sync(0xffffffffu, p[h], off);

    int warp = t >> 5, lane = t & 31;
    if (lane == 0) {
#pragma unroll
        for (int h = 0; h < 8; h++) ws[warp][h] = p[h];
    }
    __syncthreads();
    if (t < 8) {
        float s = 0.f;
#pragma unroll
        for (int w = 0; w < 8; w++) s += ws[w][t];
        bv[t] = 16.f / (1.f + expf(-s));
    }
    __syncthreads();

    int da = a - 7, db = bcol - 7;
    int cntA = 8 - abs(da), cntB = 8 - abs(db);
    int rn0 = da > 0 ? da : 0, cn0 = db > 0 ? db : 0;
    int total = cntA * cntB * 32;
    for (int idx = t; idx < total; idx += 256) {
        int tmp = idx;
        int h = tmp & 7; tmp >>= 3;
        int wt_ = tmp & 3; tmp >>= 2;
        int pa = tmp / cntB, pb = tmp - pa * cntB;
        int rn = rn0 + pa, cn = cn0 + pb;
        int rm = rn - da, cm = cn - db;
        int wh = wt_ >> 1, ww = wt_ & 1;
        int ghn = wh * 8 + rn, gwn = ww * 8 + cn;
        int ghm = wh * 8 + rm, gwm = ww * 8 + cm;
        int gn = ((ghn < 8) ? 0 : (ghn < 12 ? 1 : 2)) * 3 + ((gwn < 8) ? 0 : (gwn < 12 ? 1 : 2));
        int gm = ((ghm < 8) ? 0 : (ghm < 12 ? 1 : 2)) * 3 + ((gwm < 8) ? 0 : (gwm < 12 ? 1 : 2));
        float val = (gn == gm) ? bv[h] : -1e30f;
        g_bias[((wt_ * 8 + h) * 64 + rn * 8 + cn) * 64 + rm * 8 + cm] = val;
    }
}

// ---------------------------------------------------------------------------
// Projection GEMM (2-term): out(64x256) = A(F4 smem) @ Whi^T.
// Warp tile 32x64. B fragments via direct LDG.64 (coalesced, 1-chunk-ahead
// register prefetch). NO barriers inside.
// ---------------------------------------------------------------------------
__device__ __forceinline__ void gemm_proj(
    const uint32_t* __restrict__ src, const uint32_t* __restrict__ gw,
    float acc[2][8][4], int rbase, int warpN, int gid, int tg)
{
#pragma unroll
    for (int s = 0; s < 2; s++)
#pragma unroll
        for (int nf = 0; nf < 8; nf++)
#pragma unroll
            for (int j = 0; j < 4; j++) acc[s][nf][j] = 0.f;

    const uint2* gb = reinterpret_cast<const uint2*>(gw) + (warpN * 64 + gid) * 4 + tg;
    const uint32_t* ap = src + (rbase + gid) * XSTR + tg * 4;

    uint2 B0[8], B1[8];
#pragma unroll
    for (int nf = 0; nf < 8; nf++) B0[nf] = __ldg(gb + nf * 32);

#pragma unroll 1
    for (int it = 0; it < 8; it++) {
        const uint2* g1 = gb + (2 * it + 1) * 1024;
#pragma unroll
        for (int nf = 0; nf < 8; nf++) B1[nf] = __ldg(g1 + nf * 32);
        {
            const uint32_t* a = ap + (2 * it) * 16;
            const uint4 A0 = *reinterpret_cast<const uint4*>(a);
            const uint4 A1 = *reinterpret_cast<const uint4*>(a + 8 * XSTR);
            const uint4 A2 = *reinterpret_cast<const uint4*>(a + 16 * XSTR);
            const uint4 A3 = *reinterpret_cast<const uint4*>(a + 24 * XSTR);
#pragma unroll
            for (int nf = 0; nf < 8; nf++) {
                MMAH(acc[0][nf], A0.x, A1.x, A0.y, A1.y, B0[nf].x, B0[nf].y);
                MMAH(acc[0][nf], A0.z, A1.z, A0.w, A1.w, B0[nf].x, B0[nf].y);
                MMAH(acc[1][nf], A2.x, A3.x, A2.y, A3.y, B0[nf].x, B0[nf].y);
                MMAH(acc[1][nf], A2.z, A3.z, A2.w, A3.w, B0[nf].x, B0[nf].y);
            }
        }
        if (it < 7) {
            const uint2* g0 = gb + (2 * it + 2) * 1024;
#pragma unroll
            for (int nf = 0; nf < 8; nf++) B0[nf] = __ldg(g0 + nf * 32);
        }
        {
            const uint32_t* a = ap + (2 * it + 1) * 16;
            const uint4 A0 = *reinterpret_cast<const uint4*>(a);
            const uint4 A1 = *reinterpret_cast<const uint4*>(a + 8 * XSTR);
            const uint4 A2 = *reinterpret_cast<const uint4*>(a + 16 * XSTR);
            const uint4 A3 = *reinterpret_cast<const uint4*>(a + 24 * XSTR);
#pragma unroll
            for (int nf = 0; nf < 8; nf++) {
                MMAH(acc[0][nf], A0.x, A1.x, A0.y, A1.y, B1[nf].x, B1[nf].y);
                MMAH(acc[0][nf], A0.z, A1.z, A0.w, A1.w, B1[nf].x, B1[nf].y);
                MMAH(acc[1][nf], A2.x, A3.x, A2.y, A3.y, B1[nf].x, B1[nf].y);
                MMAH(acc[1][nf], A2.z, A3.z, A2.w, A3.w, B1[nf].x, B1[nf].y);
            }
        }
    }
}

// ---------------------------------------------------------------------------
// VT GEMM (2-term): VT(256x64) = Wv_hi (A, direct LDG) @ x^T (B = x F4 hi+lo).
// Warp: 32 d-rows. Ends with a barrier (X overwrite safety).
// ---------------------------------------------------------------------------
__device__ __forceinline__ void gemm_vt(
    const uint32_t* __restrict__ x, const uint32_t* __restrict__ gw,
    float av[2][8][4], int warp, int gid, int tg)
{
#pragma unroll
    for (int s = 0; s < 2; s++)
#pragma unroll
        for (int nf = 0; nf < 8; nf++)
#pragma unroll
            for (int j = 0; j < 4; j++) av[s][nf][j] = 0.f;

    const uint2* ga = reinterpret_cast<const uint2*>(gw) + (warp * 32 + gid) * 4 + tg;
    const uint32_t* xp0 = x + gid * XSTR + tg * 4;

    uint2 W0[4], W1[4];
#pragma unroll
    for (int i = 0; i < 4; i++) W0[i] = __ldg(ga + i * 32);

#pragma unroll 1
    for (int it = 0; it < 8; it++) {
        const uint2* g1 = ga + (2 * it + 1) * 1024;
#pragma unroll
        for (int i = 0; i < 4; i++) W1[i] = __ldg(g1 + i * 32);
        {
            const uint32_t* xp = xp0 + (2 * it) * 16;
#pragma unroll
            for (int nf = 0; nf < 8; nf++) {
                const uint4 Xv = *reinterpret_cast<const uint4*>(xp + nf * 8 * XSTR);
                MMAH(av[0][nf], W0[0].x, W0[1].x, W0[0].y, W0[1].y, Xv.x, Xv.y);
                MMAH(av[0][nf], W0[0].x, W0[1].x, W0[0].y, W0[1].y, Xv.z, Xv.w);
                MMAH(av[1][nf], W0[2].x, W0[3].x, W0[2].y, W0[3].y, Xv.x, Xv.y);
                MMAH(av[1][nf], W0[2].x, W0[3].x, W0[2].y, W0[3].y, Xv.z, Xv.w);
            }
        }
        if (it < 7) {
            const uint2* g0 = ga + (2 * it + 2) * 1024;
#pragma unroll
            for (int i = 0; i < 4; i++) W0[i] = __ldg(g0 + i * 32);
        }
        {
            const uint32_t* xp = xp0 + (2 * it + 1) * 16;
#pragma unroll
            for (int nf = 0; nf < 8; nf++) {
                const uint4 Xv = *reinterpret_cast<const uint4*>(xp + nf * 8 * XSTR);
                MMAH(av[0][nf], W1[0].x, W1[1].x, W1[0].y, W1[1].y, Xv.x, Xv.y);
                MMAH(av[0][nf], W1[0].x, W1[1].x, W1[0].y, W1[1].y, Xv.z, Xv.w);
                MMAH(av[1][nf], W1[2].x, W1[3].x, W1[2].y, W1[3].y, Xv.x, Xv.y);
                MMAH(av[1][nf], W1[2].x, W1[3].x, W1[2].y, W1[3].y, Xv.z, Xv.w);
            }
        }
    }
    __syncthreads();   // all X reads complete before VTS overwrite
}

// ---------------------------------------------------------------------------
__global__ __launch_bounds__(256, 1)
void swin_kernel(const float* __restrict__ img,
                 const float* __restrict__ bq, const float* __restrict__ bk,
                 const float* __restrict__ bv, const float* __restrict__ bo,
                 const float* __restrict__ ls,
                 float* __restrict__ out)
{
    extern __shared__ uint32_t smu[];
    uint32_t* X   = smu + OFF_X;
    uint32_t* QS  = smu + OFF_Q;
    uint32_t* KS  = smu + OFF_K;
    uint32_t* VTS = smu + OFF_X;        // overlays X after V gemm

    const int t    = threadIdx.x;
    const int lane = t & 31;
    const int warp = t >> 5;
    const int warpM = warp & 1, warpN = warp >> 1;
    const int gid = lane >> 2, tg = lane & 3;
    const int blk = blockIdx.x;
    const int b   = blk >> 2;
    const int wh  = (blk >> 1) & 1, ww = blk & 1;
    const int wtype = blk & 3;

    // ---- load shifted window -> x F4 split (fp16 hi/lo)
    const float* imgb = img + (size_t)b * (16 * 16 * 256);
#pragma unroll
    for (int i = 0; i < 16; i++) {
        int f = i * 256 + t;            // float4 index
        int tok = f >> 6, c4 = f & 63;
        int r = tok >> 3, c = tok & 7;
        int ih = (wh * 8 + r + 12) & 15;
        int iw = (ww * 8 + c + 12) & 15;
        float4 v = *reinterpret_cast<const float4*>(&imgb[(ih * 16 + iw) * 256 + c4 * 4]);
        uint32_t h0, l0, h1, l1;
        split2h(v.x, v.y, h0, l0);
        split2h(v.z, v.w, h1, l1);
        int p0 = 2 * c4;
        int g = p0 >> 3, pos = p0 & 7;
        int tgs = pos & 3, slot = pos >> 2;
        uint32_t* base = X + tok * XSTR + g * 16 + slot;
        base[tgs * 4]           = h0;
        base[(tgs + 1) * 4]     = h1;
        base[tgs * 4 + 2]       = l0;
        base[(tgs + 1) * 4 + 2] = l1;
    }
    __syncthreads();   // X visible to all warps

    float acc[2][8][4];
    const int rbase = warpM * 32;

    // ---- Q = x wq^T + bq, cosine-normalize * scale, split -> QS
    gemm_proj(X, g_wh + 0 * 32768, acc, rbase, warpN, gid, tg);
    {
#pragma unroll
        for (int sub = 0; sub < 2; sub++)
#pragma unroll
            for (int nf = 0; nf < 8; nf++) {
                float2 bb = *reinterpret_cast<const float2*>(bq + warpN * 64 + nf * 8 + 2 * tg);
                acc[sub][nf][0] += bb.x; acc[sub][nf][1] += bb.y;
                acc[sub][nf][2] += bb.x; acc[sub][nf][3] += bb.y;
            }
#pragma unroll
        for (int sub = 0; sub < 2; sub++) {
            int r0 = rbase + sub * 16 + gid, r1 = r0 + 8;
#pragma unroll
            for (int g = 0; g < 2; g++) {
                float ss0 = 0.f, ss1 = 0.f;
#pragma unroll
                for (int i = 0; i < 4; i++) {
                    float* C = acc[sub][4*g+i];
                    ss0 += C[0]*C[0] + C[1]*C[1];
                    ss1 += C[2]*C[2] + C[3]*C[3];
                }
                ss0 += __shfl_xor_sync(0xffffffffu, ss0, 1);
                ss0 += __shfl_xor_sync(0xffffffffu, ss0, 2);
                ss1 += __shfl_xor_sync(0xffffffffu, ss1, 1);
                ss1 += __shfl_xor_sync(0xffffffffu, ss1, 2);
                float sc = __expf(fminf(ls[warpN * 2 + g], 4.6051702f));
                float k0 = sc / fmaxf(sqrtf(ss0), 1e-12f);
                float k1 = sc / fmaxf(sqrtf(ss1), 1e-12f);
#pragma unroll
                for (int u = 0; u < 2; u++) {
                    int ne = 4*g + 2*u, no = ne + 1;
                    int ch = warpN * 4 + 2*g + u;
                    uint32_t He, Le, Ho, Lo;
                    split2h(acc[sub][ne][0]*k0, acc[sub][ne][1]*k0, He, Le);
                    split2h(acc[sub][no][0]*k0, acc[sub][no][1]*k0, Ho, Lo);
                    *reinterpret_cast<uint4*>(QS + r0*XSTR + ch*16 + tg*4) = make_uint4(He, Ho, Le, Lo);
                    split2h(acc[sub][ne][2]*k1, acc[sub][ne][3]*k1, He, Le);
                    split2h(acc[sub][no][2]*k1, acc[sub][no][3]*k1, Ho, Lo);
                    *reinterpret_cast<uint4*>(QS + r1*XSTR + ch*16 + tg*4) = make_uint4(He, Ho, Lo == Lo ? Lo : Lo, Lo);
                }
            }
        }
    }

    // ---- K = x wk^T + bk, normalize, split -> KS
    gemm_proj(X, g_wh + 1 * 32768, acc, rbase, warpN, gid, tg);
    {
#pragma unroll
        for (int sub = 0; sub < 2; sub++)
#pragma unroll
            for (int nf = 0; nf < 8; nf++) {
                float2 bb = *reinterpret_cast<const float2*>(bk + warpN * 64 + nf * 8 + 2 * tg);
                acc[sub][nf][0] += bb.x; acc[sub][nf][1] += bb.y;
                acc[sub][nf][2] += bb.x; acc[sub][nf][3] += bb.y;
            }
#pragma unroll
        for (int sub = 0; sub < 2; sub++) {
            int r0 = rbase + sub * 16 + gid, r1 = r0 + 8;
#pragma unroll
            for (int g = 0; g < 2; g++) {
                float ss0 = 0.f, ss1 = 0.f;
#pragma unroll
                for (int i = 0; i < 4; i++) {
                    float* C = acc[sub][4*g+i];
                    ss0 += C[0]*C[0] + C[1]*C[1];
                    ss1 += C[2]*C[2] + C[3]*C[3];
                }
                ss0 += __shfl_xor_sync(0xffffffffu, ss0, 1);
                ss0 += __shfl_xor_sync(0xffffffffu, ss0, 2);
                ss1 += __shfl_xor_sync(0xffffffffu, ss1, 1);
                ss1 += __shfl_xor_sync(0xffffffffu, ss1, 2);
                float k0 = 1.f / fmaxf(sqrtf(ss0), 1e-12f);
                float k1 = 1.f / fmaxf(sqrtf(ss1), 1e-12f);
#pragma unroll
                for (int u = 0; u < 2; u++) {
                    int ne = 4*g + 2*u, no = ne + 1;
                    int ch = warpN * 4 + 2*g + u;
                    uint32_t He, Le, Ho, Lo;
                    split2h(acc[sub][ne][0]*k0, acc[sub][ne][1]*k0, He, Le);
                    split2h(acc[sub][no][0]*k0, acc[sub][no][1]*k0, Ho, Lo);
                    *reinterpret_cast<uint4*>(KS + r0*XSTR + ch*16 + tg*4) = make_uint4(He, Ho, Le, Lo);
                    split2h(acc[sub][ne][2]*k1, acc[sub][ne][3]*k1, He, Le);
                    split2h(acc[sub][no][2]*k1, acc[sub][no][3]*k1, Ho, Lo);
                    *reinterpret_cast<uint4*>(KS + r1*XSTR + ch*16 + tg*4) = make_uint4(He, Ho, Le, Lo);
                }
            }
        }
    }

    // ---- VT = wv x^T + bv (transposed V), F4 split -> VTS (overlays X)
    {
        float av[2][8][4];
        gemm_vt(X, g_wh + 2 * 32768, av, warp, gid, tg);
#pragma unroll
        for (int sub = 0; sub < 2; sub++) {
            int d0 = warp * 32 + sub * 16 + gid, d1 = d0 + 8;
            float bv0 = bv[d0], bv1 = bv[d1];
#pragma unroll
            for (int kp = 0; kp < 4; kp++) {
                int ne = 2 * kp, no = ne + 1;
                uint32_t e0, f0, e1, f1;
                split2h(av[sub][ne][0] + bv0, av[sub][ne][1] + bv0, e0, f0);
                split2h(av[sub][no][0] + bv0, av[sub][no][1] + bv0, e1, f1);
                *reinterpret_cast<uint4*>(VTS + d0 * VSTR + ((kp + d0) & 3) * 16 + tg * 4) =
                    make_uint4(e0, e1, f0, f1);
                split2h(av[sub][ne][2] + bv1, av[sub][ne][3] + bv1, e0, f0);
                split2h(av[sub][no][2] + bv1, av[sub][no][3] + bv1, e1, f1);
                *reinterpret_cast<uint4*>(VTS + d1 * VSTR + ((kp + d1) & 3) * 16 + tg * 4) =
                    make_uint4(e0, e1, f0, f1);
            }
        }
    }
    __syncthreads();   // QS/KS/VTS all visible before attention

    // ---- attention: warp = head h. S via MMA (3-term); precomputed masked
    //      bias via LDG; softmax in regs; P (split) chains into PV MMA.
    {
        const int h = warp;
        const float NEG_INF = __int_as_float(0xff800000);
        const float* bias = g_bias + (wtype * 8 + h) * 4096;
#pragma unroll 1
        for (int mt = 0; mt < 4; mt++) {
            int r0 = mt * 16 + gid, r1 = r0 + 8;
            float2 B0[8], B1[8];
#pragma unroll
            for (int nt = 0; nt < 8; nt++) {
                B0[nt] = *reinterpret_cast<const float2*>(bias + r0 * 64 + nt * 8 + 2 * tg);
                B1[nt] = *reinterpret_cast<const float2*>(bias + r1 * 64 + nt * 8 + 2 * tg);
            }
            float S[8][4];
#pragma unroll
            for (int nt = 0; nt < 8; nt++)
#pragma unroll
                for (int j = 0; j < 4; j++) S[nt][j] = 0.f;
#pragma unroll
            for (int kc = 0; kc < 2; kc++) {
                const uint4 A0 = *reinterpret_cast<const uint4*>(
                    QS + r0 * XSTR + (2 * h + kc) * 16 + tg * 4);
                const uint4 A1 = *reinterpret_cast<const uint4*>(
                    QS + r1 * XSTR + (2 * h + kc) * 16 + tg * 4);
#pragma unroll
                for (int nt = 0; nt < 8; nt++) {
                    const uint4 Bv = *reinterpret_cast<const uint4*>(
                        KS + (nt * 8 + gid) * XSTR + (2 * h + kc) * 16 + tg * 4);
                    MMA3(S[nt], A0, A1, Bv);
                }
            }
            float mx0 = NEG_INF, mx1 = NEG_INF;
#pragma unroll
            for (int nt = 0; nt < 8; nt++) {
                S[nt][0] += B0[nt].x;
                S[nt][1] += B0[nt].y;
                S[nt][2] += B1[nt].x;
                S[nt][3] += B1[nt].y;
                mx0 = fmaxf(mx0, fmaxf(S[nt][0], S[nt][1]));
                mx1 = fmaxf(mx1, fmaxf(S[nt][2], S[nt][3]));
            }
            mx0 = fmaxf(mx0, __shfl_xor_sync(0xffffffffu, mx0, 1));
            mx0 = fmaxf(mx0, __shfl_xor_sync(0xffffffffu, mx0, 2));
            mx1 = fmaxf(mx1, __shfl_xor_sync(0xffffffffu, mx1, 1));
            mx1 = fmaxf(mx1, __shfl_xor_sync(0xffffffffu, mx1, 2));
            float s0 = 0.f, s1 = 0.f;
#pragma unroll
            for (int nt = 0; nt < 8; nt++) {
                S[nt][0] = __expf(S[nt][0] - mx0); s0 += S[nt][0];
                S[nt][1] = __expf(S[nt][1] - mx0); s0 += S[nt][1];
                S[nt][2] = __expf(S[nt][2] - mx1); s1 += S[nt][2];
                S[nt][3] = __expf(S[nt][3] - mx1); s1 += S[nt][3];
            }
            s0 += __shfl_xor_sync(0xffffffffu, s0, 1);
            s0 += __shfl_xor_sync(0xffffffffu, s0, 2);
            s1 += __shfl_xor_sync(0xffffffffu, s1, 1);
            s1 += __shfl_xor_sync(0xffffffffu, s1, 2);
            float inv0 = 1.f / s0, inv1 = 1.f / s1;
            uint32_t ph0[8], ph1[8], pl0[8], pl1[8];
#pragma unroll
            for (int nt = 0; nt < 8; nt++) {
                split2h(S[nt][0] * inv0, S[nt][1] * inv0, ph0[nt], pl0[nt]);
                split2h(S[nt][2] * inv1, S[nt][3] * inv1, ph1[nt], pl1[nt]);
            }
            float O[4][4];
#pragma unroll
            for (int dt = 0; dt < 4; dt++)
#pragma unroll
                for (int j = 0; j < 4; j++) O[dt][j] = 0.f;
#pragma unroll
            for (int kp = 0; kp < 4; kp++) {
                uint32_t ah0 = ph0[2*kp], ah1 = ph1[2*kp], ah2 = ph0[2*kp+1], ah3 = ph1[2*kp+1];
                uint32_t al0 = pl0[2*kp], al1 = pl1[2*kp], al2 = pl0[2*kp+1], al3 = pl1[2*kp+1];
#pragma unroll
                for (int dt = 0; dt < 4; dt++) {
                    int d = h * 32 + dt * 8 + gid;
                    const uint4 Bv = *reinterpret_cast<const uint4*>(
                        VTS + d * VSTR + ((kp + d) & 3) * 16 + tg * 4);
                    MMAH(O[dt], ah0, ah1, ah2, ah3, Bv.x, Bv.y);
                    MMAH(O[dt], al0, al1, al2, al3, Bv.x, Bv.y);
                    MMAH(O[dt], ah0, ah1, ah2, ah3, Bv.z, Bv.w);
                }
            }
            // store O (F4) into QS chunks 2h/2h+1 (this warp's private cols)
#pragma unroll
            for (int gg = 0; gg < 2; gg++) {
                uint32_t e0, f0, e1, f1;
                split2h(O[2*gg][0], O[2*gg][1], e0, f0);
                split2h(O[2*gg+1][0], O[2*gg+1][1], e1, f1);
                *reinterpret_cast<uint4*>(QS + r0 * XSTR + (2*h + gg) * 16 + tg * 4) =
                    make_uint4(e0, e1, f0, f1);
                split2h(O[2*gg][2], O[2*gg][3], e0, f0);
                split2h(O[2*gg+1][2], O[2*gg+1][3], e1, f1);
                *reinterpret_cast<uint4*>(QS + r1 * XSTR + (2*h + gg) * 16 + tg * 4) =
                    make_uint4(e0, e1, f0, f1);
            }
        }
    }
    __syncthreads();   // O (in QS) visible before Z gemm

    // ---- Z = O wo^T + bo -> global with inverse cyclic shift
    gemm_proj(QS, g_wh + 3 * 32768, acc, rbase, warpN, gid, tg);
    {
#pragma unroll
        for (int i = 0; i < 4; i++) {
            int r = rbase + i * 8 + gid;
            int rr = r >> 3, cc = r & 7;
            int oh = (wh * 8 + rr + 12) & 15, ow = (ww * 8 + cc + 12) & 15;
            float* d = out + ((size_t)(b * 16 + oh) * 16 + ow) * 256;
            int sub = i >> 1, half = i & 1;
#pragma unroll
            for (int nf = 0; nf < 8; nf++) {
                int c = warpN * 64 + nf * 8 + 2 * tg;
                float2 bb = *reinterpret_cast<const float2*>(bo + c);
                float2 z = {acc[sub][nf][half*2] + bb.x, acc[sub][nf][half*2+1] + bb.y};
                *reinterpret_cast<float2*>(d + c) = z;
            }
        }
    }
}

// ---------------------------------------------------------------------------
extern "C" void kernel_launch(void* const* d_in, const int* in_sizes, int n_in,
                              void* d_out, int out_size)
{
    const float* img = (const float*)d_in[0];
    const float* wq  = (const float*)d_in[1];
    const float* bq  = (const float*)d_in[2];
    const float* wk  = (const float*)d_in[3];
    const float* bk  = (const float*)d_in[4];
    const float* wv  = (const float*)d_in[5];
    const float* bv  = (const float*)d_in[6];
    const float* wo  = (const float*)d_in[7];
    const float* bo  = (const float*)d_in[8];
    const float* ls  = (const float*)d_in[9];
    const float* cw1 = (const float*)d_in[10];
    const float* cb1 = (const float*)d_in[11];
    const float* cw2 = (const float*)d_in[12];
    (void)in_sizes; (void)n_in; (void)out_size;

    cudaFuncSetAttribute(swin_kernel,
                         cudaFuncAttributeMaxDynamicSharedMemorySize,
                         SMEM_U32 * 4);

    prep_kernel<<<289, 256>>>(cw1, cb1, cw2, wq, wk, wv, wo);
    swin_kernel<<<2048, 256, SMEM_U32 * 4>>>(img, bq, bk, bv, bo, ls,
                                             (float*)d_out);
}

// round 9
// speedup vs baseline: 2.9217x; 1.1664x over previous
#include <cuda_runtime.h>
#include <cuda_fp16.h>
#include <math.h>
#include <stdint.h>

// Swin-V2 shifted-window MHA: split-fp16 tensor-core (mma.m16n8k16.f16).
// One CTA (256 thr = 8 warps) per window; 2048 CTAs. Warp = head in attention.
// Projections: 2-term split (Ah*Bh + Al*Bh), W hi-only. Attention: 3-term.
// Weights read directly from global (L2-resident, fragment-ordered LDG.64,
// 1-chunk-ahead register prefetch); no mainloop barriers.
// MMA issue order is dependency-distance-maximized: all same-accumulator
// split terms are separated by >=4 independent MMAs.
//
// "F4" layout (x, Q, K, O): u32 rows of XSTR; chunk g (16 values), group tg:
//   uint4 at row*XSTR + g*16 + tg*4 = {hi(pair g8+tg), hi(pair g8+tg+4), lo, lo}

#define XSTR 272
#define VSTR 64

#define OFF_X   0        // x F4 (17408); VT F4 (16384) overlays after V gemm
#define OFF_Q   17408    // Q F4 -> O F4
#define OFF_K   34816    // K F4
#define SMEM_U32 52224   // 208896 bytes

__device__ uint32_t g_wh[4 * 16 * 256 * 8];   // [w][kc][n][8] fp16-hi pairs
__device__ float    g_bias[4 * 8 * 64 * 64];  // [wtype][h][n][m], masked=-1e30

__device__ __forceinline__ uint32_t pack2h(float x, float y) {
    uint32_t r;
    asm("cvt.rn.f16x2.f32 %0, %1, %2;" : "=r"(r) : "f"(y), "f"(x));  // y->hi, x->lo
    return r;
}
__device__ __forceinline__ void split2h(float x, float y, uint32_t& h, uint32_t& l) {
    uint32_t hh;
    asm("cvt.rn.f16x2.f32 %0, %1, %2;" : "=r"(hh) : "f"(y), "f"(x));
    __half2 h2 = *reinterpret_cast<__half2*>(&hh);
    float rx = x - __half2float(__low2half(h2));
    float ry = y - __half2float(__high2half(h2));
    uint32_t ll;
    asm("cvt.rn.f16x2.f32 %0, %1, %2;" : "=r"(ll) : "f"(ry), "f"(rx));
    h = hh; l = ll;
}

#define MMAH(C, A0, A1, A2, A3, B0, B1)                                       \
    asm volatile("mma.sync.aligned.m16n8k16.row.col.f32.f16.f16.f32 "         \
                 "{%0,%1,%2,%3}, {%4,%5,%6,%7}, {%8,%9}, {%0,%1,%2,%3};"      \
                 : "+f"(C[0]), "+f"(C[1]), "+f"(C[2]), "+f"(C[3])             \
                 : "r"(A0), "r"(A1), "r"(A2), "r"(A3), "r"(B0), "r"(B1))

// ---------------------------------------------------------------------------
// Prep: blocks 0..63 = weight split; blocks 64..288 = masked bias table.
// ---------------------------------------------------------------------------
__global__ void prep_kernel(const float* __restrict__ w1,
                            const float* __restrict__ b1,
                            const float* __restrict__ w2,
                            const float* __restrict__ wq,
                            const float* __restrict__ wk,
                            const float* __restrict__ wv,
                            const float* __restrict__ wo)
{
    __shared__ float ws[8][8];
    __shared__ float bv[8];
    int t = threadIdx.x;

    if (blockIdx.x < 64) {
        const float* wsrc[4] = {wq, wk, wv, wo};
        int w = blockIdx.x >> 4, kc = blockIdx.x & 15;
        const float* src = wsrc[w] + t * 256 + kc * 16;
        float v[16];
#pragma unroll
        for (int i = 0; i < 4; i++) {
            float4 q = *reinterpret_cast<const float4*>(src + i * 4);
            v[4*i] = q.x; v[4*i+1] = q.y; v[4*i+2] = q.z; v[4*i+3] = q.w;
        }
        uint32_t u[8];
#pragma unroll
        for (int tg = 0; tg < 4; tg++) {
            u[tg*2]   = pack2h(v[2*tg],   v[2*tg+1]);
            u[tg*2+1] = pack2h(v[8+2*tg], v[9+2*tg]);
        }
        uint32_t* dst = g_wh + (blockIdx.x * 256 + t) * 8;
        *reinterpret_cast<uint4*>(dst)     = make_uint4(u[0], u[1], u[2], u[3]);
        *reinterpret_cast<uint4*>(dst + 4) = make_uint4(u[4], u[5], u[6], u[7]);
        return;
    }

    // ---- bias cell: CPB MLP for one relative-position cell, scatter masked
    int cell = blockIdx.x - 64;           // 0..224
    int a = cell / 15, bcol = cell % 15;
    float ra = (a - 7) * (8.0f / 7.0f);
    float rb = (bcol - 7) * (8.0f / 7.0f);
    float va = (ra >= 0.f ? 1.f : -1.f) * log2f(fabsf(ra) + 1.f) * (1.f / 3.f);
    float vb = (rb >= 0.f ? 1.f : -1.f) * log2f(fabsf(rb) + 1.f) * (1.f / 3.f);

    int j1 = t, j2 = t + 256;
    float h1 = fmaxf(va * w1[j1 * 2] + vb * w1[j1 * 2 + 1] + b1[j1], 0.f);
    float h2 = fmaxf(va * w1[j2 * 2] + vb * w1[j2 * 2 + 1] + b1[j2], 0.f);

    float p[8];
#pragma unroll
    for (int h = 0; h < 8; h++)
        p[h] = h1 * w2[h * 512 + j1] + h2 * w2[h * 512 + j2];
#pragma unroll
    for (int h = 0; h < 8; h++)
#pragma unroll
        for (int off = 16; off; off >>= 1)
            p[h] += __shfl_xor_sync(0xffffffffu, p[h], off);

    int warp = t >> 5, lane = t & 31;
    if (lane == 0) {
#pragma unroll
        for (int h = 0; h < 8; h++) ws[warp][h] = p[h];
    }
    __syncthreads();
    if (t < 8) {
        float s = 0.f;
#pragma unroll
        for (int w = 0; w < 8; w++) s += ws[w][t];
        bv[t] = 16.f / (1.f + expf(-s));
    }
    __syncthreads();

    int da = a - 7, db = bcol - 7;
    int cntA = 8 - abs(da), cntB = 8 - abs(db);
    int rn0 = da > 0 ? da : 0, cn0 = db > 0 ? db : 0;
    int total = cntA * cntB * 32;
    for (int idx = t; idx < total; idx += 256) {
        int tmp = idx;
        int h = tmp & 7; tmp >>= 3;
        int wt_ = tmp & 3; tmp >>= 2;
        int pa = tmp / cntB, pb = tmp - pa * cntB;
        int rn = rn0 + pa, cn = cn0 + pb;
        int rm = rn - da, cm = cn - db;
        int wh = wt_ >> 1, ww = wt_ & 1;
        int ghn = wh * 8 + rn, gwn = ww * 8 + cn;
        int ghm = wh * 8 + rm, gwm = ww * 8 + cm;
        int gn = ((ghn < 8) ? 0 : (ghn < 12 ? 1 : 2)) * 3 + ((gwn < 8) ? 0 : (gwn < 12 ? 1 : 2));
        int gm = ((ghm < 8) ? 0 : (ghm < 12 ? 1 : 2)) * 3 + ((gwm < 8) ? 0 : (gwm < 12 ? 1 : 2));
        float val = (gn == gm) ? bv[h] : -1e30f;
        g_bias[((wt_ * 8 + h) * 64 + rn * 8 + cn) * 64 + rm * 8 + cm] = val;
    }
}

// ---------------------------------------------------------------------------
// Projection GEMM (2-term): out(64x256) = A(F4 smem) @ Whi^T.
// Warp tile 32x64. B via direct LDG.64 + prefetch. MMAs issued hi-sweep
// (16 independent) then lo-sweep (distance 16 to same acc). No barriers.
// ---------------------------------------------------------------------------
__device__ __forceinline__ void gemm_proj(
    const uint32_t* __restrict__ src, const uint32_t* __restrict__ gw,
    float acc[2][8][4], int rbase, int warpN, int gid, int tg)
{
#pragma unroll
    for (int s = 0; s < 2; s++)
#pragma unroll
        for (int nf = 0; nf < 8; nf++)
#pragma unroll
            for (int j = 0; j < 4; j++) acc[s][nf][j] = 0.f;

    const uint2* gb = reinterpret_cast<const uint2*>(gw) + (warpN * 64 + gid) * 4 + tg;
    const uint32_t* ap = src + (rbase + gid) * XSTR + tg * 4;

    uint2 B0[8], B1[8];
#pragma unroll
    for (int nf = 0; nf < 8; nf++) B0[nf] = __ldg(gb + nf * 32);

#pragma unroll 1
    for (int it = 0; it < 8; it++) {
        const uint2* g1 = gb + (2 * it + 1) * 1024;
#pragma unroll
        for (int nf = 0; nf < 8; nf++) B1[nf] = __ldg(g1 + nf * 32);
        {
            const uint32_t* a = ap + (2 * it) * 16;
            const uint4 A0 = *reinterpret_cast<const uint4*>(a);
            const uint4 A1 = *reinterpret_cast<const uint4*>(a + 8 * XSTR);
            const uint4 A2 = *reinterpret_cast<const uint4*>(a + 16 * XSTR);
            const uint4 A3 = *reinterpret_cast<const uint4*>(a + 24 * XSTR);
#pragma unroll
            for (int nf = 0; nf < 8; nf++)
                MMAH(acc[0][nf], A0.x, A1.x, A0.y, A1.y, B0[nf].x, B0[nf].y);
#pragma unroll
            for (int nf = 0; nf < 8; nf++)
                MMAH(acc[1][nf], A2.x, A3.x, A2.y, A3.y, B0[nf].x, B0[nf].y);
#pragma unroll
            for (int nf = 0; nf < 8; nf++)
                MMAH(acc[0][nf], A0.z, A1.z, A0.w, A1.w, B0[nf].x, B0[nf].y);
#pragma unroll
            for (int nf = 0; nf < 8; nf++)
                MMAH(acc[1][nf], A2.z, A3.z, A2.w, A3.w, B0[nf].x, B0[nf].y);
        }
        if (it < 7) {
            const uint2* g0 = gb + (2 * it + 2) * 1024;
#pragma unroll
            for (int nf = 0; nf < 8; nf++) B0[nf] = __ldg(g0 + nf * 32);
        }
        {
            const uint32_t* a = ap + (2 * it + 1) * 16;
            const uint4 A0 = *reinterpret_cast<const uint4*>(a);
            const uint4 A1 = *reinterpret_cast<const uint4*>(a + 8 * XSTR);
            const uint4 A2 = *reinterpret_cast<const uint4*>(a + 16 * XSTR);
            const uint4 A3 = *reinterpret_cast<const uint4*>(a + 24 * XSTR);
#pragma unroll
            for (int nf = 0; nf < 8; nf++)
                MMAH(acc[0][nf], A0.x, A1.x, A0.y, A1.y, B1[nf].x, B1[nf].y);
#pragma unroll
            for (int nf = 0; nf < 8; nf++)
                MMAH(acc[1][nf], A2.x, A3.x, A2.y, A3.y, B1[nf].x, B1[nf].y);
#pragma unroll
            for (int nf = 0; nf < 8; nf++)
                MMAH(acc[0][nf], A0.z, A1.z, A0.w, A1.w, B1[nf].x, B1[nf].y);
#pragma unroll
            for (int nf = 0; nf < 8; nf++)
                MMAH(acc[1][nf], A2.z, A3.z, A2.w, A3.w, B1[nf].x, B1[nf].y);
        }
    }
}

// ---------------------------------------------------------------------------
// VT GEMM (2-term): VT(256x64) = Wv_hi (A, direct LDG) @ x^T (B = x F4 hi+lo).
// nf pairs, term-major: same-acc distance 4. Ends with a barrier.
// ---------------------------------------------------------------------------
__device__ __forceinline__ void gemm_vt(
    const uint32_t* __restrict__ x, const uint32_t* __restrict__ gw,
    float av[2][8][4], int warp, int gid, int tg)
{
#pragma unroll
    for (int s = 0; s < 2; s++)
#pragma unroll
        for (int nf = 0; nf < 8; nf++)
#pragma unroll
            for (int j = 0; j < 4; j++) av[s][nf][j] = 0.f;

    const uint2* ga = reinterpret_cast<const uint2*>(gw) + (warp * 32 + gid) * 4 + tg;
    const uint32_t* xp0 = x + gid * XSTR + tg * 4;

    uint2 W0[4], W1[4];
#pragma unroll
    for (int i = 0; i < 4; i++) W0[i] = __ldg(ga + i * 32);

#pragma unroll 1
    for (int it = 0; it < 8; it++) {
        const uint2* g1 = ga + (2 * it + 1) * 1024;
#pragma unroll
        for (int i = 0; i < 4; i++) W1[i] = __ldg(g1 + i * 32);
        {
            const uint32_t* xp = xp0 + (2 * it) * 16;
#pragma unroll
            for (int p = 0; p < 4; p++) {
                const uint4 Xa = *reinterpret_cast<const uint4*>(xp + (2*p) * 8 * XSTR);
                const uint4 Xb = *reinterpret_cast<const uint4*>(xp + (2*p+1) * 8 * XSTR);
                MMAH(av[0][2*p],   W0[0].x, W0[1].x, W0[0].y, W0[1].y, Xa.x, Xa.y);
                MMAH(av[1][2*p],   W0[2].x, W0[3].x, W0[2].y, W0[3].y, Xa.x, Xa.y);
                MMAH(av[0][2*p+1], W0[0].x, W0[1].x, W0[0].y, W0[1].y, Xb.x, Xb.y);
                MMAH(av[1][2*p+1], W0[2].x, W0[3].x, W0[2].y, W0[3].y, Xb.x, Xb.y);
                MMAH(av[0][2*p],   W0[0].x, W0[1].x, W0[0].y, W0[1].y, Xa.z, Xa.w);
                MMAH(av[1][2*p],   W0[2].x, W0[3].x, W0[2].y, W0[3].y, Xa.z, Xa.w);
                MMAH(av[0][2*p+1], W0[0].x, W0[1].x, W0[0].y, W0[1].y, Xb.z, Xb.w);
                MMAH(av[1][2*p+1], W0[2].x, W0[3].x, W0[2].y, W0[3].y, Xb.z, Xb.w);
            }
        }
        if (it < 7) {
            const uint2* g0 = ga + (2 * it + 2) * 1024;
#pragma unroll
            for (int i = 0; i < 4; i++) W0[i] = __ldg(g0 + i * 32);
        }
        {
            const uint32_t* xp = xp0 + (2 * it + 1) * 16;
#pragma unroll
            for (int p = 0; p < 4; p++) {
                const uint4 Xa = *reinterpret_cast<const uint4*>(xp + (2*p) * 8 * XSTR);
                const uint4 Xb = *reinterpret_cast<const uint4*>(xp + (2*p+1) * 8 * XSTR);
                MMAH(av[0][2*p],   W1[0].x, W1[1].x, W1[0].y, W1[1].y, Xa.x, Xa.y);
                MMAH(av[1][2*p],   W1[2].x, W1[3].x, W1[2].y, W1[3].y, Xa.x, Xa.y);
                MMAH(av[0][2*p+1], W1[0].x, W1[1].x, W1[0].y, W1[1].y, Xb.x, Xb.y);
                MMAH(av[1][2*p+1], W1[2].x, W1[3].x, W1[2].y, W1[3].y, Xb.x, Xb.y);
                MMAH(av[0][2*p],   W1[0].x, W1[1].x, W1[0].y, W1[1].y, Xa.z, Xa.w);
                MMAH(av[1][2*p],   W1[2].x, W1[3].x, W1[2].y, W1[3].y, Xa.z, Xa.w);
                MMAH(av[0][2*p+1], W1[0].x, W1[1].x, W1[0].y, W1[1].y, Xb.z, Xb.w);
                MMAH(av[1][2*p+1], W1[2].x, W1[3].x, W1[2].y, W1[3].y, Xb.z, Xb.w);
            }
        }
    }
    __syncthreads();   // all X reads complete before VTS overwrite
}

// ---------------------------------------------------------------------------
__global__ __launch_bounds__(256, 1)
void swin_kernel(const float* __restrict__ img,
                 const float* __restrict__ bq, const float* __restrict__ bk,
                 const float* __restrict__ bv, const float* __restrict__ bo,
                 const float* __restrict__ ls,
                 float* __restrict__ out)
{
    extern __shared__ uint32_t smu[];
    uint32_t* X   = smu + OFF_X;
    uint32_t* QS  = smu + OFF_Q;
    uint32_t* KS  = smu + OFF_K;
    uint32_t* VTS = smu + OFF_X;        // overlays X after V gemm

    const int t    = threadIdx.x;
    const int lane = t & 31;
    const int warp = t >> 5;
    const int warpM = warp & 1, warpN = warp >> 1;
    const int gid = lane >> 2, tg = lane & 3;
    const int blk = blockIdx.x;
    const int b   = blk >> 2;
    const int wh  = (blk >> 1) & 1, ww = blk & 1;
    const int wtype = blk & 3;

    // ---- load shifted window -> x F4 split (fp16 hi/lo)
    const float* imgb = img + (size_t)b * (16 * 16 * 256);
#pragma unroll
    for (int i = 0; i < 16; i++) {
        int f = i * 256 + t;            // float4 index
        int tok = f >> 6, c4 = f & 63;
        int r = tok >> 3, c = tok & 7;
        int ih = (wh * 8 + r + 12) & 15;
        int iw = (ww * 8 + c + 12) & 15;
        float4 v = *reinterpret_cast<const float4*>(&imgb[(ih * 16 + iw) * 256 + c4 * 4]);
        uint32_t h0, l0, h1, l1;
        split2h(v.x, v.y, h0, l0);
        split2h(v.z, v.w, h1, l1);
        int p0 = 2 * c4;
        int g = p0 >> 3, pos = p0 & 7;
        int tgs = pos & 3, slot = pos >> 2;
        uint32_t* base = X + tok * XSTR + g * 16 + slot;
        base[tgs * 4]           = h0;
        base[(tgs + 1) * 4]     = h1;
        base[tgs * 4 + 2]       = l0;
        base[(tgs + 1) * 4 + 2] = l1;
    }
    __syncthreads();   // X visible to all warps

    float acc[2][8][4];
    const int rbase = warpM * 32;

    // ---- Q = x wq^T + bq, cosine-normalize * scale, split -> QS
    gemm_proj(X, g_wh + 0 * 32768, acc, rbase, warpN, gid, tg);
    {
#pragma unroll
        for (int sub = 0; sub < 2; sub++)
#pragma unroll
            for (int nf = 0; nf < 8; nf++) {
                float2 bb = *reinterpret_cast<const float2*>(bq + warpN * 64 + nf * 8 + 2 * tg);
                acc[sub][nf][0] += bb.x; acc[sub][nf][1] += bb.y;
                acc[sub][nf][2] += bb.x; acc[sub][nf][3] += bb.y;
            }
#pragma unroll
        for (int sub = 0; sub < 2; sub++) {
            int r0 = rbase + sub * 16 + gid, r1 = r0 + 8;
#pragma unroll
            for (int g = 0; g < 2; g++) {
                float ss0 = 0.f, ss1 = 0.f;
#pragma unroll
                for (int i = 0; i < 4; i++) {
                    float* C = acc[sub][4*g+i];
                    ss0 += C[0]*C[0] + C[1]*C[1];
                    ss1 += C[2]*C[2] + C[3]*C[3];
                }
                ss0 += __shfl_xor_sync(0xffffffffu, ss0, 1);
                ss0 += __shfl_xor_sync(0xffffffffu, ss0, 2);
                ss1 += __shfl_xor_sync(0xffffffffu, ss1, 1);
                ss1 += __shfl_xor_sync(0xffffffffu, ss1, 2);
                float sc = __expf(fminf(ls[warpN * 2 + g], 4.6051702f));
                float k0 = sc / fmaxf(sqrtf(ss0), 1e-12f);
                float k1 = sc / fmaxf(sqrtf(ss1), 1e-12f);
#pragma unroll
                for (int u = 0; u < 2; u++) {
                    int ne = 4*g + 2*u, no = ne + 1;
                    int ch = warpN * 4 + 2*g + u;
                    uint32_t He, Le, Ho, Lo;
                    split2h(acc[sub][ne][0]*k0, acc[sub][ne][1]*k0, He, Le);
                    split2h(acc[sub][no][0]*k0, acc[sub][no][1]*k0, Ho, Lo);
                    *reinterpret_cast<uint4*>(QS + r0*XSTR + ch*16 + tg*4) = make_uint4(He, Ho, Le, Lo);
                    split2h(acc[sub][ne][2]*k1, acc[sub][ne][3]*k1, He, Le);
                    split2h(acc[sub][no][2]*k1, acc[sub][no][3]*k1, Ho, Lo);
                    *reinterpret_cast<uint4*>(QS + r1*XSTR + ch*16 + tg*4) = make_uint4(He, Ho, Le, Lo);
                }
            }
        }
    }

    // ---- K = x wk^T + bk, normalize, split -> KS
    gemm_proj(X, g_wh + 1 * 32768, acc, rbase, warpN, gid, tg);
    {
#pragma unroll
        for (int sub = 0; sub < 2; sub++)
#pragma unroll
            for (int nf = 0; nf < 8; nf++) {
                float2 bb = *reinterpret_cast<const float2*>(bk + warpN * 64 + nf * 8 + 2 * tg);
                acc[sub][nf][0] += bb.x; acc[sub][nf][1] += bb.y;
                acc[sub][nf][2] += bb.x; acc[sub][nf][3] += bb.y;
            }
#pragma unroll
        for (int sub = 0; sub < 2; sub++) {
            int r0 = rbase + sub * 16 + gid, r1 = r0 + 8;
#pragma unroll
            for (int g = 0; g < 2; g++) {
                float ss0 = 0.f, ss1 = 0.f;
#pragma unroll
                for (int i = 0; i < 4; i++) {
                    float* C = acc[sub][4*g+i];
                    ss0 += C[0]*C[0] + C[1]*C[1];
                    ss1 += C[2]*C[2] + C[3]*C[3];
                }
                ss0 += __shfl_xor_sync(0xffffffffu, ss0, 1);
                ss0 += __shfl_xor_sync(0xffffffffu, ss0, 2);
                ss1 += __shfl_xor_sync(0xffffffffu, ss1, 1);
                ss1 += __shfl_xor_sync(0xffffffffu, ss1, 2);
                float k0 = 1.f / fmaxf(sqrtf(ss0), 1e-12f);
                float k1 = 1.f / fmaxf(sqrtf(ss1), 1e-12f);
#pragma unroll
                for (int u = 0; u < 2; u++) {
                    int ne = 4*g + 2*u, no = ne + 1;
                    int ch = warpN * 4 + 2*g + u;
                    uint32_t He, Le, Ho, Lo;
                    split2h(acc[sub][ne][0]*k0, acc[sub][ne][1]*k0, He, Le);
                    split2h(acc[sub][no][0]*k0, acc[sub][no][1]*k0, Ho, Lo);
                    *reinterpret_cast<uint4*>(KS + r0*XSTR + ch*16 + tg*4) = make_uint4(He, Ho, Le, Lo);
                    split2h(acc[sub][ne][2]*k1, acc[sub][ne][3]*k1, He, Le);
                    split2h(acc[sub][no][2]*k1, acc[sub][no][3]*k1, Ho, Lo);
                    *reinterpret_cast<uint4*>(KS + r1*XSTR + ch*16 + tg*4) = make_uint4(He, Ho, Le, Lo);
                }
            }
        }
    }

    // ---- VT = wv x^T + bv (transposed V), F4 split -> VTS (overlays X)
    {
        float av[2][8][4];
        gemm_vt(X, g_wh + 2 * 32768, av, warp, gid, tg);
#pragma unroll
        for (int sub = 0; sub < 2; sub++) {
            int d0 = warp * 32 + sub * 16 + gid, d1 = d0 + 8;
            float bv0 = bv[d0], bv1 = bv[d1];
#pragma unroll
            for (int kp = 0; kp < 4; kp++) {
                int ne = 2 * kp, no = ne + 1;
                uint32_t e0, f0, e1, f1;
                split2h(av[sub][ne][0] + bv0, av[sub][ne][1] + bv0, e0, f0);
                split2h(av[sub][no][0] + bv0, av[sub][no][1] + bv0, e1, f1);
                *reinterpret_cast<uint4*>(VTS + d0 * VSTR + ((kp + d0) & 3) * 16 + tg * 4) =
                    make_uint4(e0, e1, f0, f1);
                split2h(av[sub][ne][2] + bv1, av[sub][ne][3] + bv1, e0, f0);
                split2h(av[sub][no][2] + bv1, av[sub][no][3] + bv1, e1, f1);
                *reinterpret_cast<uint4*>(VTS + d1 * VSTR + ((kp + d1) & 3) * 16 + tg * 4) =
                    make_uint4(e0, e1, f0, f1);
            }
        }
    }
    __syncthreads();   // QS/KS/VTS all visible before attention

    // ---- attention: warp = head h. S via MMA (3-term, term-major groups);
    //      precomputed masked bias via LDG; softmax in regs; P chains to PV.
    {
        const int h = warp;
        const float NEG_INF = __int_as_float(0xff800000);
        const float* bias = g_bias + (wtype * 8 + h) * 4096;
#pragma unroll 1
        for (int mt = 0; mt < 4; mt++) {
            int r0 = mt * 16 + gid, r1 = r0 + 8;
            float2 B0[8], B1[8];
#pragma unroll
            for (int nt = 0; nt < 8; nt++) {
                B0[nt] = *reinterpret_cast<const float2*>(bias + r0 * 64 + nt * 8 + 2 * tg);
                B1[nt] = *reinterpret_cast<const float2*>(bias + r1 * 64 + nt * 8 + 2 * tg);
            }
            float S[8][4];
#pragma unroll
            for (int nt = 0; nt < 8; nt++)
#pragma unroll
                for (int j = 0; j < 4; j++) S[nt][j] = 0.f;
#pragma unroll
            for (int kc = 0; kc < 2; kc++) {
                const uint4 A0 = *reinterpret_cast<const uint4*>(
                    QS + r0 * XSTR + (2 * h + kc) * 16 + tg * 4);
                const uint4 A1 = *reinterpret_cast<const uint4*>(
                    QS + r1 * XSTR + (2 * h + kc) * 16 + tg * 4);
#pragma unroll
                for (int gq = 0; gq < 2; gq++) {
                    uint4 Bv[4];
#pragma unroll
                    for (int i = 0; i < 4; i++)
                        Bv[i] = *reinterpret_cast<const uint4*>(
                            KS + ((gq * 4 + i) * 8 + gid) * XSTR + (2 * h + kc) * 16 + tg * 4);
#pragma unroll
                    for (int i = 0; i < 4; i++)
                        MMAH(S[gq*4+i], A0.x, A1.x, A0.y, A1.y, Bv[i].x, Bv[i].y);
#pragma unroll
                    for (int i = 0; i < 4; i++)
                        MMAH(S[gq*4+i], A0.z, A1.z, A0.w, A1.w, Bv[i].x, Bv[i].y);
#pragma unroll
                    for (int i = 0; i < 4; i++)
                        MMAH(S[gq*4+i], A0.x, A1.x, A0.y, A1.y, Bv[i].z, Bv[i].w);
                }
            }
            float mx0 = NEG_INF, mx1 = NEG_INF;
#pragma unroll
            for (int nt = 0; nt < 8; nt++) {
                S[nt][0] += B0[nt].x;
                S[nt][1] += B0[nt].y;
                S[nt][2] += B1[nt].x;
                S[nt][3] += B1[nt].y;
                mx0 = fmaxf(mx0, fmaxf(S[nt][0], S[nt][1]));
                mx1 = fmaxf(mx1, fmaxf(S[nt][2], S[nt][3]));
            }
            mx0 = fmaxf(mx0, __shfl_xor_sync(0xffffffffu, mx0, 1));
            mx0 = fmaxf(mx0, __shfl_xor_sync(0xffffffffu, mx0, 2));
            mx1 = fmaxf(mx1, __shfl_xor_sync(0xffffffffu, mx1, 1));
            mx1 = fmaxf(mx1, __shfl_xor_sync(0xffffffffu, mx1, 2));
            float s0 = 0.f, s1 = 0.f;
#pragma unroll
            for (int nt = 0; nt < 8; nt++) {
                S[nt][0] = __expf(S[nt][0] - mx0); s0 += S[nt][0];
                S[nt][1] = __expf(S[nt][1] - mx0); s0 += S[nt][1];
                S[nt][2] = __expf(S[nt][2] - mx1); s1 += S[nt][2];
                S[nt][3] = __expf(S[nt][3] - mx1); s1 += S[nt][3];
            }
            s0 += __shfl_xor_sync(0xffffffffu, s0, 1);
            s0 += __shfl_xor_sync(0xffffffffu, s0, 2);
            s1 += __shfl_xor_sync(0xffffffffu, s1, 1);
            s1 += __shfl_xor_sync(0xffffffffu, s1, 2);
            float inv0 = 1.f / s0, inv1 = 1.f / s1;
            uint32_t ph0[8], ph1[8], pl0[8], pl1[8];
#pragma unroll
            for (int nt = 0; nt < 8; nt++) {
                split2h(S[nt][0] * inv0, S[nt][1] * inv0, ph0[nt], pl0[nt]);
                split2h(S[nt][2] * inv1, S[nt][3] * inv1, ph1[nt], pl1[nt]);
            }
            float O[4][4];
#pragma unroll
            for (int dt = 0; dt < 4; dt++)
#pragma unroll
                for (int j = 0; j < 4; j++) O[dt][j] = 0.f;
#pragma unroll
            for (int kp = 0; kp < 4; kp++) {
                uint32_t ah0 = ph0[2*kp], ah1 = ph1[2*kp], ah2 = ph0[2*kp+1], ah3 = ph1[2*kp+1];
                uint32_t al0 = pl0[2*kp], al1 = pl1[2*kp], al2 = pl0[2*kp+1], al3 = pl1[2*kp+1];
                uint4 Bv[4];
#pragma unroll
                for (int dt = 0; dt < 4; dt++) {
                    int d = h * 32 + dt * 8 + gid;
                    Bv[dt] = *reinterpret_cast<const uint4*>(
                        VTS + d * VSTR + ((kp + d) & 3) * 16 + tg * 4);
                }
#pragma unroll
                for (int dt = 0; dt < 4; dt++)
                    MMAH(O[dt], ah0, ah1, ah2, ah3, Bv[dt].x, Bv[dt].y);
#pragma unroll
                for (int dt = 0; dt < 4; dt++)
                    MMAH(O[dt], al0, al1, al2, al3, Bv[dt].x, Bv[dt].y);
#pragma unroll
                for (int dt = 0; dt < 4; dt++)
                    MMAH(O[dt], ah0, ah1, ah2, ah3, Bv[dt].z, Bv[dt].w);
            }
            // store O (F4) into QS chunks 2h/2h+1 (this warp's private cols)
#pragma unroll
            for (int gg = 0; gg < 2; gg++) {
                uint32_t e0, f0, e1, f1;
                split2h(O[2*gg][0], O[2*gg][1], e0, f0);
                split2h(O[2*gg+1][0], O[2*gg+1][1], e1, f1);
                *reinterpret_cast<uint4*>(QS + r0 * XSTR + (2*h + gg) * 16 + tg * 4) =
                    make_uint4(e0, e1, f0, f1);
                split2h(O[2*gg][2], O[2*gg][3], e0, f0);
                split2h(O[2*gg+1][2], O[2*gg+1][3], e1, f1);
                *reinterpret_cast<uint4*>(QS + r1 * XSTR + (2*h + gg) * 16 + tg * 4) =
                    make_uint4(e0, e1, f0, f1);
            }
        }
    }
    __syncthreads();   // O (in QS) visible before Z gemm

    // ---- Z = O wo^T + bo -> global with inverse cyclic shift
    gemm_proj(QS, g_wh + 3 * 32768, acc, rbase, warpN, gid, tg);
    {
#pragma unroll
        for (int i = 0; i < 4; i++) {
            int r = rbase + i * 8 + gid;
            int rr = r >> 3, cc = r & 7;
            int oh = (wh * 8 + rr + 12) & 15, ow = (ww * 8 + cc + 12) & 15;
            float* d = out + ((size_t)(b * 16 + oh) * 16 + ow) * 256;
            int sub = i >> 1, half = i & 1;
#pragma unroll
            for (int nf = 0; nf < 8; nf++) {
                int c = warpN * 64 + nf * 8 + 2 * tg;
                float2 bb = *reinterpret_cast<const float2*>(bo + c);
                float2 z = {acc[sub][nf][half*2] + bb.x, acc[sub][nf][half*2+1] + bb.y};
                *reinterpret_cast<float2*>(d + c) = z;
            }
        }
    }
}

// ---------------------------------------------------------------------------
extern "C" void kernel_launch(void* const* d_in, const int* in_sizes, int n_in,
                              void* d_out, int out_size)
{
    const float* img = (const float*)d_in[0];
    const float* wq  = (const float*)d_in[1];
    const float* bq  = (const float*)d_in[2];
    const float* wk  = (const float*)d_in[3];
    const float* bk  = (const float*)d_in[4];
    const float* wv  = (const float*)d_in[5];
    const float* bv  = (const float*)d_in[6];
    const float* wo  = (const float*)d_in[7];
    const float* bo  = (const float*)d_in[8];
    const float* ls  = (const float*)d_in[9];
    const float* cw1 = (const float*)d_in[10];
    const float* cb1 = (const float*)d_in[11];
    const float* cw2 = (const float*)d_in[12];
    (void)in_sizes; (void)n_in; (void)out_size;

    cudaFuncSetAttribute(swin_kernel,
                         cudaFuncAttributeMaxDynamicSharedMemorySize,
                         SMEM_U32 * 4);

    prep_kernel<<<289, 256>>>(cw1, cb1, cw2, wq, wk, wv, wo);
    swin_kernel<<<2048, 256, SMEM_U32 * 4>>>(img, bq, bk, bv, bo, ls,
                                             (float*)d_out);
}

// round 10
// speedup vs baseline: 3.0533x; 1.0450x over previous
#include <cuda_runtime.h>
#include <cuda_fp16.h>
#include <math.h>
#include <stdint.h>

// Swin-V2 shifted-window MHA: split-fp16 tensor-core (mma.m16n8k16.f16).
// One CTA (256 thr = 8 warps) per window; 2048 CTAs. Warp = head in attention.
// Projections: 2-term split (Ah*Bh + Al*Bh), W hi-only. Attention: 3-term.
// Weights read directly from global (L2-resident, fragment-ordered LDG.64,
// TWO-chunk-ahead register prefetch via 4-buffer rotation); no mainloop
// barriers. MMA order keeps same-accumulator terms >=4 apart.
//
// "F4" layout (x, Q, K, O): u32 rows of XSTR; chunk g (16 values), group tg:
//   uint4 at row*XSTR + g*16 + tg*4 = {hi(pair g8+tg), hi(pair g8+tg+4), lo, lo}

#define XSTR 272
#define VSTR 64

#define OFF_X   0        // x F4 (17408); VT F4 (16384) overlays after V gemm
#define OFF_Q   17408    // Q F4 -> O F4
#define OFF_K   34816    // K F4
#define SMEM_U32 52224   // 208896 bytes

__device__ uint32_t g_wh[4 * 16 * 256 * 8];   // [w][kc][n][8] fp16-hi pairs
__device__ float    g_bias[4 * 8 * 64 * 64];  // [wtype][h][n][m], masked=-1e30

__device__ __forceinline__ uint32_t pack2h(float x, float y) {
    uint32_t r;
    asm("cvt.rn.f16x2.f32 %0, %1, %2;" : "=r"(r) : "f"(y), "f"(x));  // y->hi, x->lo
    return r;
}
__device__ __forceinline__ void split2h(float x, float y, uint32_t& h, uint32_t& l) {
    uint32_t hh;
    asm("cvt.rn.f16x2.f32 %0, %1, %2;" : "=r"(hh) : "f"(y), "f"(x));
    __half2 h2 = *reinterpret_cast<__half2*>(&hh);
    float rx = x - __half2float(__low2half(h2));
    float ry = y - __half2float(__high2half(h2));
    uint32_t ll;
    asm("cvt.rn.f16x2.f32 %0, %1, %2;" : "=r"(ll) : "f"(ry), "f"(rx));
    h = hh; l = ll;
}

#define MMAH(C, A0, A1, A2, A3, B0, B1)                                       \
    asm volatile("mma.sync.aligned.m16n8k16.row.col.f32.f16.f16.f32 "         \
                 "{%0,%1,%2,%3}, {%4,%5,%6,%7}, {%8,%9}, {%0,%1,%2,%3};"      \
                 : "+f"(C[0]), "+f"(C[1]), "+f"(C[2]), "+f"(C[3])             \
                 : "r"(A0), "r"(A1), "r"(A2), "r"(A3), "r"(B0), "r"(B1))

// ---------------------------------------------------------------------------
// Prep: blocks 0..63 = weight split; blocks 64..288 = masked bias table.
// ---------------------------------------------------------------------------
__global__ void prep_kernel(const float* __restrict__ w1,
                            const float* __restrict__ b1,
                            const float* __restrict__ w2,
                            const float* __restrict__ wq,
                            const float* __restrict__ wk,
                            const float* __restrict__ wv,
                            const float* __restrict__ wo)
{
    __shared__ float ws[8][8];
    __shared__ float bv[8];
    int t = threadIdx.x;

    if (blockIdx.x < 64) {
        const float* wsrc[4] = {wq, wk, wv, wo};
        int w = blockIdx.x >> 4, kc = blockIdx.x & 15;
        const float* src = wsrc[w] + t * 256 + kc * 16;
        float v[16];
#pragma unroll
        for (int i = 0; i < 4; i++) {
            float4 q = *reinterpret_cast<const float4*>(src + i * 4);
            v[4*i] = q.x; v[4*i+1] = q.y; v[4*i+2] = q.z; v[4*i+3] = q.w;
        }
        uint32_t u[8];
#pragma unroll
        for (int tg = 0; tg < 4; tg++) {
            u[tg*2]   = pack2h(v[2*tg],   v[2*tg+1]);
            u[tg*2+1] = pack2h(v[8+2*tg], v[9+2*tg]);
        }
        uint32_t* dst = g_wh + (blockIdx.x * 256 + t) * 8;
        *reinterpret_cast<uint4*>(dst)     = make_uint4(u[0], u[1], u[2], u[3]);
        *reinterpret_cast<uint4*>(dst + 4) = make_uint4(u[4], u[5], u[6], u[7]);
        return;
    }

    // ---- bias cell: CPB MLP for one relative-position cell, scatter masked
    int cell = blockIdx.x - 64;           // 0..224
    int a = cell / 15, bcol = cell % 15;
    float ra = (a - 7) * (8.0f / 7.0f);
    float rb = (bcol - 7) * (8.0f / 7.0f);
    float va = (ra >= 0.f ? 1.f : -1.f) * log2f(fabsf(ra) + 1.f) * (1.f / 3.f);
    float vb = (rb >= 0.f ? 1.f : -1.f) * log2f(fabsf(rb) + 1.f) * (1.f / 3.f);

    int j1 = t, j2 = t + 256;
    float h1 = fmaxf(va * w1[j1 * 2] + vb * w1[j1 * 2 + 1] + b1[j1], 0.f);
    float h2 = fmaxf(va * w1[j2 * 2] + vb * w1[j2 * 2 + 1] + b1[j2], 0.f);

    float p[8];
#pragma unroll
    for (int h = 0; h < 8; h++)
        p[h] = h1 * w2[h * 512 + j1] + h2 * w2[h * 512 + j2];
#pragma unroll
    for (int h = 0; h < 8; h++)
#pragma unroll
        for (int off = 16; off; off >>= 1)
            p[h] += __shfl_xor_sync(0xffffffffu, p[h], off);

    int warp = t >> 5, lane = t & 31;
    if (lane == 0) {
#pragma unroll
        for (int h = 0; h < 8; h++) ws[warp][h] = p[h];
    }
    __syncthreads();
    if (t < 8) {
        float s = 0.f;
#pragma unroll
        for (int w = 0; w < 8; w++) s += ws[w][t];
        bv[t] = 16.f / (1.f + expf(-s));
    }
    __syncthreads();

    int da = a - 7, db = bcol - 7;
    int cntA = 8 - abs(da), cntB = 8 - abs(db);
    int rn0 = da > 0 ? da : 0, cn0 = db > 0 ? db : 0;
    int total = cntA * cntB * 32;
    for (int idx = t; idx < total; idx += 256) {
        int tmp = idx;
        int h = tmp & 7; tmp >>= 3;
        int wt_ = tmp & 3; tmp >>= 2;
        int pa = tmp / cntB, pb = tmp - pa * cntB;
        int rn = rn0 + pa, cn = cn0 + pb;
        int rm = rn - da, cm = cn - db;
        int wh = wt_ >> 1, ww = wt_ & 1;
        int ghn = wh * 8 + rn, gwn = ww * 8 + cn;
        int ghm = wh * 8 + rm, gwm = ww * 8 + cm;
        int gn = ((ghn < 8) ? 0 : (ghn < 12 ? 1 : 2)) * 3 + ((gwn < 8) ? 0 : (gwn < 12 ? 1 : 2));
        int gm = ((ghm < 8) ? 0 : (ghm < 12 ? 1 : 2)) * 3 + ((gwm < 8) ? 0 : (gwm < 12 ? 1 : 2));
        float val = (gn == gm) ? bv[h] : -1e30f;
        g_bias[((wt_ * 8 + h) * 64 + rn * 8 + cn) * 64 + rm * 8 + cm] = val;
    }
}

// ---- one 16-wide k-chunk of the projection GEMM (32 MMAs, hi/lo sweeps) ----
#define PROJ_CHUNK(B, kc)                                                     \
    do {                                                                      \
        const uint32_t* a_ = ap + (kc) * 16;                                  \
        const uint4 A0 = *reinterpret_cast<const uint4*>(a_);                 \
        const uint4 A1 = *reinterpret_cast<const uint4*>(a_ + 8 * XSTR);      \
        const uint4 A2 = *reinterpret_cast<const uint4*>(a_ + 16 * XSTR);     \
        const uint4 A3 = *reinterpret_cast<const uint4*>(a_ + 24 * XSTR);     \
        _Pragma("unroll")                                                     \
        for (int nf = 0; nf < 8; nf++)                                        \
            MMAH(acc[0][nf], A0.x, A1.x, A0.y, A1.y, B[nf].x, B[nf].y);       \
        _Pragma("unroll")                                                     \
        for (int nf = 0; nf < 8; nf++)                                        \
            MMAH(acc[1][nf], A2.x, A3.x, A2.y, A3.y, B[nf].x, B[nf].y);       \
        _Pragma("unroll")                                                     \
        for (int nf = 0; nf < 8; nf++)                                        \
            MMAH(acc[0][nf], A0.z, A1.z, A0.w, A1.w, B[nf].x, B[nf].y);       \
        _Pragma("unroll")                                                     \
        for (int nf = 0; nf < 8; nf++)                                        \
            MMAH(acc[1][nf], A2.z, A3.z, A2.w, A3.w, B[nf].x, B[nf].y);       \
    } while (0)

#define PROJ_LD(B, c)                                                         \
    do {                                                                      \
        _Pragma("unroll")                                                     \
        for (int nf = 0; nf < 8; nf++) B[nf] = __ldg(gb + (c) * 1024 + nf * 32); \
    } while (0)

// ---------------------------------------------------------------------------
// Projection GEMM (2-term): out(64x256) = A(F4 smem) @ Whi^T.
// Warp tile 32x64. B via direct LDG.64 with 2-chunk-ahead prefetch
// (4-buffer static rotation, outer loop = 4 chunks). No barriers.
// ---------------------------------------------------------------------------
__device__ __forceinline__ void gemm_proj(
    const uint32_t* __restrict__ src, const uint32_t* __restrict__ gw,
    float acc[2][8][4], int rbase, int warpN, int gid, int tg)
{
#pragma unroll
    for (int s = 0; s < 2; s++)
#pragma unroll
        for (int nf = 0; nf < 8; nf++)
#pragma unroll
            for (int j = 0; j < 4; j++) acc[s][nf][j] = 0.f;

    const uint2* gb = reinterpret_cast<const uint2*>(gw) + (warpN * 64 + gid) * 4 + tg;
    const uint32_t* ap = src + (rbase + gid) * XSTR + tg * 4;

    uint2 Ba[8], Bb[8], Bc[8], Bd[8];
    PROJ_LD(Ba, 0);
    PROJ_LD(Bb, 1);

#pragma unroll 1
    for (int it = 0; it < 4; it++) {
        const int c = 4 * it;
        PROJ_LD(Bc, c + 2);
        PROJ_CHUNK(Ba, c);
        PROJ_LD(Bd, c + 3);
        PROJ_CHUNK(Bb, c + 1);
        const int c4 = (c + 4 < 16) ? c + 4 : 15;
        PROJ_LD(Ba, c4);
        PROJ_CHUNK(Bc, c + 2);
        const int c5 = (c + 5 < 16) ? c + 5 : 15;
        PROJ_LD(Bb, c5);
        PROJ_CHUNK(Bd, c + 3);
    }
}

// ---- one 16-wide k-chunk of the VT GEMM (32 MMAs, term-major nf pairs) ----
#define VT_CHUNK(W, kc)                                                       \
    do {                                                                      \
        const uint32_t* xp = xp0 + (kc) * 16;                                 \
        _Pragma("unroll")                                                     \
        for (int p = 0; p < 4; p++) {                                         \
            const uint4 Xa = *reinterpret_cast<const uint4*>(xp + (2*p) * 8 * XSTR);   \
            const uint4 Xb = *reinterpret_cast<const uint4*>(xp + (2*p+1) * 8 * XSTR); \
            MMAH(av[0][2*p],   W[0].x, W[1].x, W[0].y, W[1].y, Xa.x, Xa.y);   \
            MMAH(av[1][2*p],   W[2].x, W[3].x, W[2].y, W[3].y, Xa.x, Xa.y);   \
            MMAH(av[0][2*p+1], W[0].x, W[1].x, W[0].y, W[1].y, Xb.x, Xb.y);   \
            MMAH(av[1][2*p+1], W[2].x, W[3].x, W[2].y, W[3].y, Xb.x, Xb.y);   \
            MMAH(av[0][2*p],   W[0].x, W[1].x, W[0].y, W[1].y, Xa.z, Xa.w);   \
            MMAH(av[1][2*p],   W[2].x, W[3].x, W[2].y, W[3].y, Xa.z, Xa.w);   \
            MMAH(av[0][2*p+1], W[0].x, W[1].x, W[0].y, W[1].y, Xb.z, Xb.w);   \
            MMAH(av[1][2*p+1], W[2].x, W[3].x, W[2].y, W[3].y, Xb.z, Xb.w);   \
        }                                                                     \
    } while (0)

#define VT_LD(W, c)                                                           \
    do {                                                                      \
        _Pragma("unroll")                                                     \
        for (int i = 0; i < 4; i++) W[i] = __ldg(ga + (c) * 1024 + i * 32);   \
    } while (0)

// ---------------------------------------------------------------------------
// VT GEMM (2-term): VT(256x64) = Wv_hi (A, direct LDG, 2-chunk prefetch)
// @ x^T (B = x F4 hi+lo). Warp: 32 d-rows. Ends with a barrier.
// ---------------------------------------------------------------------------
__device__ __forceinline__ void gemm_vt(
    const uint32_t* __restrict__ x, const uint32_t* __restrict__ gw,
    float av[2][8][4], int warp, int gid, int tg)
{
#pragma unroll
    for (int s = 0; s < 2; s++)
#pragma unroll
        for (int nf = 0; nf < 8; nf++)
#pragma unroll
            for (int j = 0; j < 4; j++) av[s][nf][j] = 0.f;

    const uint2* ga = reinterpret_cast<const uint2*>(gw) + (warp * 32 + gid) * 4 + tg;
    const uint32_t* xp0 = x + gid * XSTR + tg * 4;

    uint2 Wa[4], Wb[4], Wc[4], Wd[4];
    VT_LD(Wa, 0);
    VT_LD(Wb, 1);

#pragma unroll 1
    for (int it = 0; it < 4; it++) {
        const int c = 4 * it;
        VT_LD(Wc, c + 2);
        VT_CHUNK(Wa, c);
        VT_LD(Wd, c + 3);
        VT_CHUNK(Wb, c + 1);
        const int c4 = (c + 4 < 16) ? c + 4 : 15;
        VT_LD(Wa, c4);
        VT_CHUNK(Wc, c + 2);
        const int c5 = (c + 5 < 16) ? c + 5 : 15;
        VT_LD(Wb, c5);
        VT_CHUNK(Wd, c + 3);
    }
    __syncthreads();   // all X reads complete before VTS overwrite
}

// ---------------------------------------------------------------------------
__global__ __launch_bounds__(256, 1)
void swin_kernel(const float* __restrict__ img,
                 const float* __restrict__ bq, const float* __restrict__ bk,
                 const float* __restrict__ bv, const float* __restrict__ bo,
                 const float* __restrict__ ls,
                 float* __restrict__ out)
{
    extern __shared__ uint32_t smu[];
    uint32_t* X   = smu + OFF_X;
    uint32_t* QS  = smu + OFF_Q;
    uint32_t* KS  = smu + OFF_K;
    uint32_t* VTS = smu + OFF_X;        // overlays X after V gemm

    const int t    = threadIdx.x;
    const int lane = t & 31;
    const int warp = t >> 5;
    const int warpM = warp & 1, warpN = warp >> 1;
    const int gid = lane >> 2, tg = lane & 3;
    const int blk = blockIdx.x;
    const int b   = blk >> 2;
    const int wh  = (blk >> 1) & 1, ww = blk & 1;
    const int wtype = blk & 3;

    // ---- load shifted window -> x F4 split (fp16 hi/lo)
    const float* imgb = img + (size_t)b * (16 * 16 * 256);
#pragma unroll
    for (int i = 0; i < 16; i++) {
        int f = i * 256 + t;            // float4 index
        int tok = f >> 6, c4 = f & 63;
        int r = tok >> 3, c = tok & 7;
        int ih = (wh * 8 + r + 12) & 15;
        int iw = (ww * 8 + c + 12) & 15;
        float4 v = *reinterpret_cast<const float4*>(&imgb[(ih * 16 + iw) * 256 + c4 * 4]);
        uint32_t h0, l0, h1, l1;
        split2h(v.x, v.y, h0, l0);
        split2h(v.z, v.w, h1, l1);
        int p0 = 2 * c4;
        int g = p0 >> 3, pos = p0 & 7;
        int tgs = pos & 3, slot = pos >> 2;
        uint32_t* base = X + tok * XSTR + g * 16 + slot;
        base[tgs * 4]           = h0;
        base[(tgs + 1) * 4]     = h1;
        base[tgs * 4 + 2]       = l0;
        base[(tgs + 1) * 4 + 2] = l1;
    }
    __syncthreads();   // X visible to all warps

    float acc[2][8][4];
    const int rbase = warpM * 32;

    // ---- Q = x wq^T + bq, cosine-normalize * scale, split -> QS
    gemm_proj(X, g_wh + 0 * 32768, acc, rbase, warpN, gid, tg);
    {
#pragma unroll
        for (int sub = 0; sub < 2; sub++)
#pragma unroll
            for (int nf = 0; nf < 8; nf++) {
                float2 bb = *reinterpret_cast<const float2*>(bq + warpN * 64 + nf * 8 + 2 * tg);
                acc[sub][nf][0] += bb.x; acc[sub][nf][1] += bb.y;
                acc[sub][nf][2] += bb.x; acc[sub][nf][3] += bb.y;
            }
#pragma unroll
        for (int sub = 0; sub < 2; sub++) {
            int r0 = rbase + sub * 16 + gid, r1 = r0 + 8;
#pragma unroll
            for (int g = 0; g < 2; g++) {
                float ss0 = 0.f, ss1 = 0.f;
#pragma unroll
                for (int i = 0; i < 4; i++) {
                    float* C = acc[sub][4*g+i];
                    ss0 += C[0]*C[0] + C[1]*C[1];
                    ss1 += C[2]*C[2] + C[3]*C[3];
                }
                ss0 += __shfl_xor_sync(0xffffffffu, ss0, 1);
                ss0 += __shfl_xor_sync(0xffffffffu, ss0, 2);
                ss1 += __shfl_xor_sync(0xffffffffu, ss1, 1);
                ss1 += __shfl_xor_sync(0xffffffffu, ss1, 2);
                float sc = __expf(fminf(ls[warpN * 2 + g], 4.6051702f));
                float k0 = sc / fmaxf(sqrtf(ss0), 1e-12f);
                float k1 = sc / fmaxf(sqrtf(ss1), 1e-12f);
#pragma unroll
                for (int u = 0; u < 2; u++) {
                    int ne = 4*g + 2*u, no = ne + 1;
                    int ch = warpN * 4 + 2*g + u;
                    uint32_t He, Le, Ho, Lo;
                    split2h(acc[sub][ne][0]*k0, acc[sub][ne][1]*k0, He, Le);
                    split2h(acc[sub][no][0]*k0, acc[sub][no][1]*k0, Ho, Lo);
                    *reinterpret_cast<uint4*>(QS + r0*XSTR + ch*16 + tg*4) = make_uint4(He, Ho, Le, Lo);
                    split2h(acc[sub][ne][2]*k1, acc[sub][ne][3]*k1, He, Le);
                    split2h(acc[sub][no][2]*k1, acc[sub][no][3]*k1, Ho, Lo);
                    *reinterpret_cast<uint4*>(QS + r1*XSTR + ch*16 + tg*4) = make_uint4(He, Ho, Le, Lo);
                }
            }
        }
    }

    // ---- K = x wk^T + bk, normalize, split -> KS
    gemm_proj(X, g_wh + 1 * 32768, acc, rbase, warpN, gid, tg);
    {
#pragma unroll
        for (int sub = 0; sub < 2; sub++)
#pragma unroll
            for (int nf = 0; nf < 8; nf++) {
                float2 bb = *reinterpret_cast<const float2*>(bk + warpN * 64 + nf * 8 + 2 * tg);
                acc[sub][nf][0] += bb.x; acc[sub][nf][1] += bb.y;
                acc[sub][nf][2] += bb.x; acc[sub][nf][3] += bb.y;
            }
#pragma unroll
        for (int sub = 0; sub < 2; sub++) {
            int r0 = rbase + sub * 16 + gid, r1 = r0 + 8;
#pragma unroll
            for (int g = 0; g < 2; g++) {
                float ss0 = 0.f, ss1 = 0.f;
#pragma unroll
                for (int i = 0; i < 4; i++) {
                    float* C = acc[sub][4*g+i];
                    ss0 += C[0]*C[0] + C[1]*C[1];
                    ss1 += C[2]*C[2] + C[3]*C[3];
                }
                ss0 += __shfl_xor_sync(0xffffffffu, ss0, 1);
                ss0 += __shfl_xor_sync(0xffffffffu, ss0, 2);
                ss1 += __shfl_xor_sync(0xffffffffu, ss1, 1);
                ss1 += __shfl_xor_sync(0xffffffffu, ss1, 2);
                float k0 = 1.f / fmaxf(sqrtf(ss0), 1e-12f);
                float k1 = 1.f / fmaxf(sqrtf(ss1), 1e-12f);
#pragma unroll
                for (int u = 0; u < 2; u++) {
                    int ne = 4*g + 2*u, no = ne + 1;
                    int ch = warpN * 4 + 2*g + u;
                    uint32_t He, Le, Ho, Lo;
                    split2h(acc[sub][ne][0]*k0, acc[sub][ne][1]*k0, He, Le);
                    split2h(acc[sub][no][0]*k0, acc[sub][no][1]*k0, Ho, Lo);
                    *reinterpret_cast<uint4*>(KS + r0*XSTR + ch*16 + tg*4) = make_uint4(He, Ho, Le, Lo);
                    split2h(acc[sub][ne][2]*k1, acc[sub][ne][3]*k1, He, Le);
                    split2h(acc[sub][no][2]*k1, acc[sub][no][3]*k1, Ho, Lo);
                    *reinterpret_cast<uint4*>(KS + r1*XSTR + ch*16 + tg*4) = make_uint4(He, Ho, Le, Lo);
                }
            }
        }
    }

    // ---- VT = wv x^T + bv (transposed V), F4 split -> VTS (overlays X)
    {
        float av[2][8][4];
        gemm_vt(X, g_wh + 2 * 32768, av, warp, gid, tg);
#pragma unroll
        for (int sub = 0; sub < 2; sub++) {
            int d0 = warp * 32 + sub * 16 + gid, d1 = d0 + 8;
            float bv0 = bv[d0], bv1 = bv[d1];
#pragma unroll
            for (int kp = 0; kp < 4; kp++) {
                int ne = 2 * kp, no = ne + 1;
                uint32_t e0, f0, e1, f1;
                split2h(av[sub][ne][0] + bv0, av[sub][ne][1] + bv0, e0, f0);
                split2h(av[sub][no][0] + bv0, av[sub][no][1] + bv0, e1, f1);
                *reinterpret_cast<uint4*>(VTS + d0 * VSTR + ((kp + d0) & 3) * 16 + tg * 4) =
                    make_uint4(e0, e1, f0, f1);
                split2h(av[sub][ne][2] + bv1, av[sub][ne][3] + bv1, e0, f0);
                split2h(av[sub][no][2] + bv1, av[sub][no][3] + bv1, e1, f1);
                *reinterpret_cast<uint4*>(VTS + d1 * VSTR + ((kp + d1) & 3) * 16 + tg * 4) =
                    make_uint4(e0, e1, f0, f1);
            }
        }
    }
    __syncthreads();   // QS/KS/VTS all visible before attention

    // ---- attention: warp = head h. S via MMA (3-term, term-major groups);
    //      precomputed masked bias via LDG; softmax in regs; P chains to PV.
    {
        const int h = warp;
        const float NEG_INF = __int_as_float(0xff800000);
        const float* bias = g_bias + (wtype * 8 + h) * 4096;
#pragma unroll 1
        for (int mt = 0; mt < 4; mt++) {
            int r0 = mt * 16 + gid, r1 = r0 + 8;
            float2 B0[8], B1[8];
#pragma unroll
            for (int nt = 0; nt < 8; nt++) {
                B0[nt] = *reinterpret_cast<const float2*>(bias + r0 * 64 + nt * 8 + 2 * tg);
                B1[nt] = *reinterpret_cast<const float2*>(bias + r1 * 64 + nt * 8 + 2 * tg);
            }
            float S[8][4];
#pragma unroll
            for (int nt = 0; nt < 8; nt++)
#pragma unroll
                for (int j = 0; j < 4; j++) S[nt][j] = 0.f;
#pragma unroll
            for (int kc = 0; kc < 2; kc++) {
                const uint4 A0 = *reinterpret_cast<const uint4*>(
                    QS + r0 * XSTR + (2 * h + kc) * 16 + tg * 4);
                const uint4 A1 = *reinterpret_cast<const uint4*>(
                    QS + r1 * XSTR + (2 * h + kc) * 16 + tg * 4);
#pragma unroll
                for (int gq = 0; gq < 2; gq++) {
                    uint4 Bv[4];
#pragma unroll
                    for (int i = 0; i < 4; i++)
                        Bv[i] = *reinterpret_cast<const uint4*>(
                            KS + ((gq * 4 + i) * 8 + gid) * XSTR + (2 * h + kc) * 16 + tg * 4);
#pragma unroll
                    for (int i = 0; i < 4; i++)
                        MMAH(S[gq*4+i], A0.x, A1.x, A0.y, A1.y, Bv[i].x, Bv[i].y);
#pragma unroll
                    for (int i = 0; i < 4; i++)
                        MMAH(S[gq*4+i], A0.z, A1.z, A0.w, A1.w, Bv[i].x, Bv[i].y);
#pragma unroll
                    for (int i = 0; i < 4; i++)
                        MMAH(S[gq*4+i], A0.x, A1.x, A0.y, A1.y, Bv[i].z, Bv[i].w);
                }
            }
            float mx0 = NEG_INF, mx1 = NEG_INF;
#pragma unroll
            for (int nt = 0; nt < 8; nt++) {
                S[nt][0] += B0[nt].x;
                S[nt][1] += B0[nt].y;
                S[nt][2] += B1[nt].x;
                S[nt][3] += B1[nt].y;
                mx0 = fmaxf(mx0, fmaxf(S[nt][0], S[nt][1]));
                mx1 = fmaxf(mx1, fmaxf(S[nt][2], S[nt][3]));
            }
            mx0 = fmaxf(mx0, __shfl_xor_sync(0xffffffffu, mx0, 1));
            mx0 = fmaxf(mx0, __shfl_xor_sync(0xffffffffu, mx0, 2));
            mx1 = fmaxf(mx1, __shfl_xor_sync(0xffffffffu, mx1, 1));
            mx1 = fmaxf(mx1, __shfl_xor_sync(0xffffffffu, mx1, 2));
            float s0 = 0.f, s1 = 0.f;
#pragma unroll
            for (int nt = 0; nt < 8; nt++) {
                S[nt][0] = __expf(S[nt][0] - mx0); s0 += S[nt][0];
                S[nt][1] = __expf(S[nt][1] - mx0); s0 += S[nt][1];
                S[nt][2] = __expf(S[nt][2] - mx1); s1 += S[nt][2];
                S[nt][3] = __expf(S[nt][3] - mx1); s1 += S[nt][3];
            }
            s0 += __shfl_xor_sync(0xffffffffu, s0, 1);
            s0 += __shfl_xor_sync(0xffffffffu, s0, 2);
            s1 += __shfl_xor_sync(0xffffffffu, s1, 1);
            s1 += __shfl_xor_sync(0xffffffffu, s1, 2);
            float inv0 = 1.f / s0, inv1 = 1.f / s1;
            uint32_t ph0[8], ph1[8], pl0[8], pl1[8];
#pragma unroll
            for (int nt = 0; nt < 8; nt++) {
                split2h(S[nt][0] * inv0, S[nt][1] * inv0, ph0[nt], pl0[nt]);
                split2h(S[nt][2] * inv1, S[nt][3] * inv1, ph1[nt], pl1[nt]);
            }
            float O[4][4];
#pragma unroll
            for (int dt = 0; dt < 4; dt++)
#pragma unroll
                for (int j = 0; j < 4; j++) O[dt][j] = 0.f;
#pragma unroll
            for (int kp = 0; kp < 4; kp++) {
                uint32_t ah0 = ph0[2*kp], ah1 = ph1[2*kp], ah2 = ph0[2*kp+1], ah3 = ph1[2*kp+1];
                uint32_t al0 = pl0[2*kp], al1 = pl1[2*kp], al2 = pl0[2*kp+1], al3 = pl1[2*kp+1];
                uint4 Bv[4];
#pragma unroll
                for (int dt = 0; dt < 4; dt++) {
                    int d = h * 32 + dt * 8 + gid;
                    Bv[dt] = *reinterpret_cast<const uint4*>(
                        VTS + d * VSTR + ((kp + d) & 3) * 16 + tg * 4);
                }
#pragma unroll
                for (int dt = 0; dt < 4; dt++)
                    MMAH(O[dt], ah0, ah1, ah2, ah3, Bv[dt].x, Bv[dt].y);
#pragma unroll
                for (int dt = 0; dt < 4; dt++)
                    MMAH(O[dt], al0, al1, al2, al3, Bv[dt].x, Bv[dt].y);
#pragma unroll
                for (int dt = 0; dt < 4; dt++)
                    MMAH(O[dt], ah0, ah1, ah2, ah3, Bv[dt].z, Bv[dt].w);
            }
            // store O (F4) into QS chunks 2h/2h+1 (this warp's private cols)
#pragma unroll
            for (int gg = 0; gg < 2; gg++) {
                uint32_t e0, f0, e1, f1;
                split2h(O[2*gg][0], O[2*gg][1], e0, f0);
                split2h(O[2*gg+1][0], O[2*gg+1][1], e1, f1);
                *reinterpret_cast<uint4*>(QS + r0 * XSTR + (2*h + gg) * 16 + tg * 4) =
                    make_uint4(e0, e1, f0, f1);
                split2h(O[2*gg][2], O[2*gg][3], e0, f0);
                split2h(O[2*gg+1][2], O[2*gg+1][3], e1, f1);
                *reinterpret_cast<uint4*>(QS + r1 * XSTR + (2*h + gg) * 16 + tg * 4) =
                    make_uint4(e0, e1, f0, f1);
            }
        }
    }
    __syncthreads();   // O (in QS) visible before Z gemm

    // ---- Z = O wo^T + bo -> global with inverse cyclic shift
    gemm_proj(QS, g_wh + 3 * 32768, acc, rbase, warpN, gid, tg);
    {
#pragma unroll
        for (int i = 0; i < 4; i++) {
            int r = rbase + i * 8 + gid;
            int rr = r >> 3, cc = r & 7;
            int oh = (wh * 8 + rr + 12) & 15, ow = (ww * 8 + cc + 12) & 15;
            float* d = out + ((size_t)(b * 16 + oh) * 16 + ow) * 256;
            int sub = i >> 1, half = i & 1;
#pragma unroll
            for (int nf = 0; nf < 8; nf++) {
                int c = warpN * 64 + nf * 8 + 2 * tg;
                float2 bb = *reinterpret_cast<const float2*>(bo + c);
                float2 z = {acc[sub][nf][half*2] + bb.x, acc[sub][nf][half*2+1] + bb.y};
                *reinterpret_cast<float2*>(d + c) = z;
            }
        }
    }
}

// ---------------------------------------------------------------------------
extern "C" void kernel_launch(void* const* d_in, const int* in_sizes, int n_in,
                              void* d_out, int out_size)
{
    const float* img = (const float*)d_in[0];
    const float* wq  = (const float*)d_in[1];
    const float* bq  = (const float*)d_in[2];
    const float* wk  = (const float*)d_in[3];
    const float* bk  = (const float*)d_in[4];
    const float* wv  = (const float*)d_in[5];
    const float* bv  = (const float*)d_in[6];
    const float* wo  = (const float*)d_in[7];
    const float* bo  = (const float*)d_in[8];
    const float* ls  = (const float*)d_in[9];
    const float* cw1 = (const float*)d_in[10];
    const float* cb1 = (const float*)d_in[11];
    const float* cw2 = (const float*)d_in[12];
    (void)in_sizes; (void)n_in; (void)out_size;

    cudaFuncSetAttribute(swin_kernel,
                         cudaFuncAttributeMaxDynamicSharedMemorySize,
                         SMEM_U32 * 4);

    prep_kernel<<<289, 256>>>(cw1, cb1, cw2, wq, wk, wv, wo);
    swin_kernel<<<2048, 256, SMEM_U32 * 4>>>(img, bq, bk, bv, bo, ls,
                                             (float*)d_out);
}

// round 11
// speedup vs baseline: 3.1189x; 1.0215x over previous
#include <cuda_runtime.h>
#include <cuda_fp16.h>
#include <math.h>
#include <stdint.h>

// Swin-V2 shifted-window MHA: split-fp16 tensor-core (mma.m16n8k16.f16).
// One CTA (256 thr = 8 warps) per window; 2048 CTAs. Warp = head in attention.
// Projections: 2-term split (Ah*Bh + Al*Bh), W hi-only. Attention: 3-term.
// Weights read directly from global (L2-resident, fragment-ordered LDG.64,
// 2-chunk-ahead register prefetch); no mainloop barriers.
// Attention: bias double-buffer prefetch across mt; softmax normalization
// deferred past the PV MMAs (sum-reduce overlaps tensor work).
//
// "F4" layout (x, Q, K, O): u32 rows of XSTR; chunk g (16 values), group tg:
//   uint4 at row*XSTR + g*16 + tg*4 = {hi(pair g8+tg), hi(pair g8+tg+4), lo, lo}

#define XSTR 272
#define VSTR 64

#define OFF_X   0        // x F4 (17408); VT F4 (16384) overlays after V gemm
#define OFF_Q   17408    // Q F4 -> O F4
#define OFF_K   34816    // K F4
#define SMEM_U32 52224   // 208896 bytes

__device__ uint32_t g_wh[4 * 16 * 256 * 8];   // [w][kc][n][8] fp16-hi pairs
__device__ float    g_bias[4 * 8 * 64 * 64];  // [wtype][h][n][m], masked=-1e30

__device__ __forceinline__ uint32_t pack2h(float x, float y) {
    uint32_t r;
    asm("cvt.rn.f16x2.f32 %0, %1, %2;" : "=r"(r) : "f"(y), "f"(x));  // y->hi, x->lo
    return r;
}
__device__ __forceinline__ void split2h(float x, float y, uint32_t& h, uint32_t& l) {
    uint32_t hh;
    asm("cvt.rn.f16x2.f32 %0, %1, %2;" : "=r"(hh) : "f"(y), "f"(x));
    __half2 h2 = *reinterpret_cast<__half2*>(&hh);
    float rx = x - __half2float(__low2half(h2));
    float ry = y - __half2float(__high2half(h2));
    uint32_t ll;
    asm("cvt.rn.f16x2.f32 %0, %1, %2;" : "=r"(ll) : "f"(ry), "f"(rx));
    h = hh; l = ll;
}

#define MMAH(C, A0, A1, A2, A3, B0, B1)                                       \
    asm volatile("mma.sync.aligned.m16n8k16.row.col.f32.f16.f16.f32 "         \
                 "{%0,%1,%2,%3}, {%4,%5,%6,%7}, {%8,%9}, {%0,%1,%2,%3};"      \
                 : "+f"(C[0]), "+f"(C[1]), "+f"(C[2]), "+f"(C[3])             \
                 : "r"(A0), "r"(A1), "r"(A2), "r"(A3), "r"(B0), "r"(B1))

// ---------------------------------------------------------------------------
// Prep: blocks 0..63 = weight split; blocks 64..288 = masked bias table.
// ---------------------------------------------------------------------------
__global__ void prep_kernel(const float* __restrict__ w1,
                            const float* __restrict__ b1,
                            const float* __restrict__ w2,
                            const float* __restrict__ wq,
                            const float* __restrict__ wk,
                            const float* __restrict__ wv,
                            const float* __restrict__ wo)
{
    __shared__ float ws[8][8];
    __shared__ float bv[8];
    int t = threadIdx.x;

    if (blockIdx.x < 64) {
        const float* wsrc[4] = {wq, wk, wv, wo};
        int w = blockIdx.x >> 4, kc = blockIdx.x & 15;
        const float* src = wsrc[w] + t * 256 + kc * 16;
        float v[16];
#pragma unroll
        for (int i = 0; i < 4; i++) {
            float4 q = *reinterpret_cast<const float4*>(src + i * 4);
            v[4*i] = q.x; v[4*i+1] = q.y; v[4*i+2] = q.z; v[4*i+3] = q.w;
        }
        uint32_t u[8];
#pragma unroll
        for (int tg = 0; tg < 4; tg++) {
            u[tg*2]   = pack2h(v[2*tg],   v[2*tg+1]);
            u[tg*2+1] = pack2h(v[8+2*tg], v[9+2*tg]);
        }
        uint32_t* dst = g_wh + (blockIdx.x * 256 + t) * 8;
        *reinterpret_cast<uint4*>(dst)     = make_uint4(u[0], u[1], u[2], u[3]);
        *reinterpret_cast<uint4*>(dst + 4) = make_uint4(u[4], u[5], u[6], u[7]);
        return;
    }

    // ---- bias cell: CPB MLP for one relative-position cell, scatter masked
    int cell = blockIdx.x - 64;           // 0..224
    int a = cell / 15, bcol = cell % 15;
    float ra = (a - 7) * (8.0f / 7.0f);
    float rb = (bcol - 7) * (8.0f / 7.0f);
    float va = (ra >= 0.f ? 1.f : -1.f) * log2f(fabsf(ra) + 1.f) * (1.f / 3.f);
    float vb = (rb >= 0.f ? 1.f : -1.f) * log2f(fabsf(rb) + 1.f) * (1.f / 3.f);

    int j1 = t, j2 = t + 256;
    float h1 = fmaxf(va * w1[j1 * 2] + vb * w1[j1 * 2 + 1] + b1[j1], 0.f);
    float h2 = fmaxf(va * w1[j2 * 2] + vb * w1[j2 * 2 + 1] + b1[j2], 0.f);

    float p[8];
#pragma unroll
    for (int h = 0; h < 8; h++)
        p[h] = h1 * w2[h * 512 + j1] + h2 * w2[h * 512 + j2];
#pragma unroll
    for (int h = 0; h < 8; h++)
#pragma unroll
        for (int off = 16; off; off >>= 1)
            p[h] += __shfl_xor_sync(0xffffffffu, p[h], off);

    int warp = t >> 5, lane = t & 31;
    if (lane == 0) {
#pragma unroll
        for (int h = 0; h < 8; h++) ws[warp][h] = p[h];
    }
    __syncthreads();
    if (t < 8) {
        float s = 0.f;
#pragma unroll
        for (int w = 0; w < 8; w++) s += ws[w][t];
        bv[t] = 16.f / (1.f + expf(-s));
    }
    __syncthreads();

    int da = a - 7, db = bcol - 7;
    int cntA = 8 - abs(da), cntB = 8 - abs(db);
    int rn0 = da > 0 ? da : 0, cn0 = db > 0 ? db : 0;
    int total = cntA * cntB * 32;
    for (int idx = t; idx < total; idx += 256) {
        int tmp = idx;
        int h = tmp & 7; tmp >>= 3;
        int wt_ = tmp & 3; tmp >>= 2;
        int pa = tmp / cntB, pb = tmp - pa * cntB;
        int rn = rn0 + pa, cn = cn0 + pb;
        int rm = rn - da, cm = cn - db;
        int wh = wt_ >> 1, ww = wt_ & 1;
        int ghn = wh * 8 + rn, gwn = ww * 8 + cn;
        int ghm = wh * 8 + rm, gwm = ww * 8 + cm;
        int gn = ((ghn < 8) ? 0 : (ghn < 12 ? 1 : 2)) * 3 + ((gwn < 8) ? 0 : (gwn < 12 ? 1 : 2));
        int gm = ((ghm < 8) ? 0 : (ghm < 12 ? 1 : 2)) * 3 + ((gwm < 8) ? 0 : (gwm < 12 ? 1 : 2));
        float val = (gn == gm) ? bv[h] : -1e30f;
        g_bias[((wt_ * 8 + h) * 64 + rn * 8 + cn) * 64 + rm * 8 + cm] = val;
    }
}

// ---- one 16-wide k-chunk of the projection GEMM (32 MMAs, hi/lo sweeps) ----
#define PROJ_CHUNK(B, kc)                                                     \
    do {                                                                      \
        const uint32_t* a_ = ap + (kc) * 16;                                  \
        const uint4 A0 = *reinterpret_cast<const uint4*>(a_);                 \
        const uint4 A1 = *reinterpret_cast<const uint4*>(a_ + 8 * XSTR);      \
        const uint4 A2 = *reinterpret_cast<const uint4*>(a_ + 16 * XSTR);     \
        const uint4 A3 = *reinterpret_cast<const uint4*>(a_ + 24 * XSTR);     \
        _Pragma("unroll")                                                     \
        for (int nf = 0; nf < 8; nf++)                                        \
            MMAH(acc[0][nf], A0.x, A1.x, A0.y, A1.y, B[nf].x, B[nf].y);       \
        _Pragma("unroll")                                                     \
        for (int nf = 0; nf < 8; nf++)                                        \
            MMAH(acc[1][nf], A2.x, A3.x, A2.y, A3.y, B[nf].x, B[nf].y);       \
        _Pragma("unroll")                                                     \
        for (int nf = 0; nf < 8; nf++)                                        \
            MMAH(acc[0][nf], A0.z, A1.z, A0.w, A1.w, B[nf].x, B[nf].y);       \
        _Pragma("unroll")                                                     \
        for (int nf = 0; nf < 8; nf++)                                        \
            MMAH(acc[1][nf], A2.z, A3.z, A2.w, A3.w, B[nf].x, B[nf].y);       \
    } while (0)

#define PROJ_LD(B, c)                                                         \
    do {                                                                      \
        _Pragma("unroll")                                                     \
        for (int nf = 0; nf < 8; nf++) B[nf] = __ldg(gb + (c) * 1024 + nf * 32); \
    } while (0)

// ---------------------------------------------------------------------------
// Projection GEMM (2-term): out(64x256) = A(F4 smem) @ Whi^T.
// Warp tile 32x64. B via direct LDG.64 with 2-chunk-ahead prefetch.
// ---------------------------------------------------------------------------
__device__ __forceinline__ void gemm_proj(
    const uint32_t* __restrict__ src, const uint32_t* __restrict__ gw,
    float acc[2][8][4], int rbase, int warpN, int gid, int tg)
{
#pragma unroll
    for (int s = 0; s < 2; s++)
#pragma unroll
        for (int nf = 0; nf < 8; nf++)
#pragma unroll
            for (int j = 0; j < 4; j++) acc[s][nf][j] = 0.f;

    const uint2* gb = reinterpret_cast<const uint2*>(gw) + (warpN * 64 + gid) * 4 + tg;
    const uint32_t* ap = src + (rbase + gid) * XSTR + tg * 4;

    uint2 Ba[8], Bb[8], Bc[8], Bd[8];
    PROJ_LD(Ba, 0);
    PROJ_LD(Bb, 1);

#pragma unroll 1
    for (int it = 0; it < 4; it++) {
        const int c = 4 * it;
        PROJ_LD(Bc, c + 2);
        PROJ_CHUNK(Ba, c);
        PROJ_LD(Bd, c + 3);
        PROJ_CHUNK(Bb, c + 1);
        const int c4 = (c + 4 < 16) ? c + 4 : 15;
        PROJ_LD(Ba, c4);
        PROJ_CHUNK(Bc, c + 2);
        const int c5 = (c + 5 < 16) ? c + 5 : 15;
        PROJ_LD(Bb, c5);
        PROJ_CHUNK(Bd, c + 3);
    }
}

// ---- one 16-wide k-chunk of the VT GEMM (32 MMAs, term-major nf pairs) ----
#define VT_CHUNK(W, kc)                                                       \
    do {                                                                      \
        const uint32_t* xp = xp0 + (kc) * 16;                                 \
        _Pragma("unroll")                                                     \
        for (int p = 0; p < 4; p++) {                                         \
            const uint4 Xa = *reinterpret_cast<const uint4*>(xp + (2*p) * 8 * XSTR);   \
            const uint4 Xb = *reinterpret_cast<const uint4*>(xp + (2*p+1) * 8 * XSTR); \
            MMAH(av[0][2*p],   W[0].x, W[1].x, W[0].y, W[1].y, Xa.x, Xa.y);   \
            MMAH(av[1][2*p],   W[2].x, W[3].x, W[2].y, W[3].y, Xa.x, Xa.y);   \
            MMAH(av[0][2*p+1], W[0].x, W[1].x, W[0].y, W[1].y, Xb.x, Xb.y);   \
            MMAH(av[1][2*p+1], W[2].x, W[3].x, W[2].y, W[3].y, Xb.x, Xb.y);   \
            MMAH(av[0][2*p],   W[0].x, W[1].x, W[0].y, W[1].y, Xa.z, Xa.w);   \
            MMAH(av[1][2*p],   W[2].x, W[3].x, W[2].y, W[3].y, Xa.z, Xa.w);   \
            MMAH(av[0][2*p+1], W[0].x, W[1].x, W[0].y, W[1].y, Xb.z, Xb.w);   \
            MMAH(av[1][2*p+1], W[2].x, W[3].x, W[2].y, W[3].y, Xb.z, Xb.w);   \
        }                                                                     \
    } while (0)

#define VT_LD(W, c)                                                           \
    do {                                                                      \
        _Pragma("unroll")                                                     \
        for (int i = 0; i < 4; i++) W[i] = __ldg(ga + (c) * 1024 + i * 32);   \
    } while (0)

// ---------------------------------------------------------------------------
// VT GEMM (2-term): VT(256x64) = Wv_hi (A, direct LDG, 2-chunk prefetch)
// @ x^T (B = x F4 hi+lo). Warp: 32 d-rows. Ends with a barrier.
// ---------------------------------------------------------------------------
__device__ __forceinline__ void gemm_vt(
    const uint32_t* __restrict__ x, const uint32_t* __restrict__ gw,
    float av[2][8][4], int warp, int gid, int tg)
{
#pragma unroll
    for (int s = 0; s < 2; s++)
#pragma unroll
        for (int nf = 0; nf < 8; nf++)
#pragma unroll
            for (int j = 0; j < 4; j++) av[s][nf][j] = 0.f;

    const uint2* ga = reinterpret_cast<const uint2*>(gw) + (warp * 32 + gid) * 4 + tg;
    const uint32_t* xp0 = x + gid * XSTR + tg * 4;

    uint2 Wa[4], Wb[4], Wc[4], Wd[4];
    VT_LD(Wa, 0);
    VT_LD(Wb, 1);

#pragma unroll 1
    for (int it = 0; it < 4; it++) {
        const int c = 4 * it;
        VT_LD(Wc, c + 2);
        VT_CHUNK(Wa, c);
        VT_LD(Wd, c + 3);
        VT_CHUNK(Wb, c + 1);
        const int c4 = (c + 4 < 16) ? c + 4 : 15;
        VT_LD(Wa, c4);
        VT_CHUNK(Wc, c + 2);
        const int c5 = (c + 5 < 16) ? c + 5 : 15;
        VT_LD(Wb, c5);
        VT_CHUNK(Wd, c + 3);
    }
    __syncthreads();   // all X reads complete before VTS overwrite
}

// ---------------------------------------------------------------------------
__global__ __launch_bounds__(256, 1)
void swin_kernel(const float* __restrict__ img,
                 const float* __restrict__ bq, const float* __restrict__ bk,
                 const float* __restrict__ bv, const float* __restrict__ bo,
                 const float* __restrict__ ls,
                 float* __restrict__ out)
{
    extern __shared__ uint32_t smu[];
    uint32_t* X   = smu + OFF_X;
    uint32_t* QS  = smu + OFF_Q;
    uint32_t* KS  = smu + OFF_K;
    uint32_t* VTS = smu + OFF_X;        // overlays X after V gemm

    const int t    = threadIdx.x;
    const int lane = t & 31;
    const int warp = t >> 5;
    const int warpM = warp & 1, warpN = warp >> 1;
    const int gid = lane >> 2, tg = lane & 3;
    const int blk = blockIdx.x;
    const int b   = blk >> 2;
    const int wh  = (blk >> 1) & 1, ww = blk & 1;
    const int wtype = blk & 3;

    // ---- load shifted window -> x F4 split (fp16 hi/lo)
    const float* imgb = img + (size_t)b * (16 * 16 * 256);
#pragma unroll
    for (int i = 0; i < 16; i++) {
        int f = i * 256 + t;            // float4 index
        int tok = f >> 6, c4 = f & 63;
        int r = tok >> 3, c = tok & 7;
        int ih = (wh * 8 + r + 12) & 15;
        int iw = (ww * 8 + c + 12) & 15;
        float4 v = *reinterpret_cast<const float4*>(&imgb[(ih * 16 + iw) * 256 + c4 * 4]);
        uint32_t h0, l0, h1, l1;
        split2h(v.x, v.y, h0, l0);
        split2h(v.z, v.w, h1, l1);
        int p0 = 2 * c4;
        int g = p0 >> 3, pos = p0 & 7;
        int tgs = pos & 3, slot = pos >> 2;
        uint32_t* base = X + tok * XSTR + g * 16 + slot;
        base[tgs * 4]           = h0;
        base[(tgs + 1) * 4]     = h1;
        base[tgs * 4 + 2]       = l0;
        base[(tgs + 1) * 4 + 2] = l1;
    }
    __syncthreads();   // X visible to all warps

    float acc[2][8][4];
    const int rbase = warpM * 32;

    // ---- Q = x wq^T + bq, cosine-normalize * scale, split -> QS
    gemm_proj(X, g_wh + 0 * 32768, acc, rbase, warpN, gid, tg);
    {
#pragma unroll
        for (int sub = 0; sub < 2; sub++)
#pragma unroll
            for (int nf = 0; nf < 8; nf++) {
                float2 bb = *reinterpret_cast<const float2*>(bq + warpN * 64 + nf * 8 + 2 * tg);
                acc[sub][nf][0] += bb.x; acc[sub][nf][1] += bb.y;
                acc[sub][nf][2] += bb.x; acc[sub][nf][3] += bb.y;
            }
#pragma unroll
        for (int sub = 0; sub < 2; sub++) {
            int r0 = rbase + sub * 16 + gid, r1 = r0 + 8;
#pragma unroll
            for (int g = 0; g < 2; g++) {
                float ss0 = 0.f, ss1 = 0.f;
#pragma unroll
                for (int i = 0; i < 4; i++) {
                    float* C = acc[sub][4*g+i];
                    ss0 += C[0]*C[0] + C[1]*C[1];
                    ss1 += C[2]*C[2] + C[3]*C[3];
                }
                ss0 += __shfl_xor_sync(0xffffffffu, ss0, 1);
                ss0 += __shfl_xor_sync(0xffffffffu, ss0, 2);
                ss1 += __shfl_xor_sync(0xffffffffu, ss1, 1);
                ss1 += __shfl_xor_sync(0xffffffffu, ss1, 2);
                float sc = __expf(fminf(ls[warpN * 2 + g], 4.6051702f));
                float k0 = sc * rsqrtf(fmaxf(ss0, 1e-24f));
                float k1 = sc * rsqrtf(fmaxf(ss1, 1e-24f));
#pragma unroll
                for (int u = 0; u < 2; u++) {
                    int ne = 4*g + 2*u, no = ne + 1;
                    int ch = warpN * 4 + 2*g + u;
                    uint32_t He, Le, Ho, Lo;
                    split2h(acc[sub][ne][0]*k0, acc[sub][ne][1]*k0, He, Le);
                    split2h(acc[sub][no][0]*k0, acc[sub][no][1]*k0, Ho, Lo);
                    *reinterpret_cast<uint4*>(QS + r0*XSTR + ch*16 + tg*4) = make_uint4(He, Ho, Le, Lo);
                    split2h(acc[sub][ne][2]*k1, acc[sub][ne][3]*k1, He, Le);
                    split2h(acc[sub][no][2]*k1, acc[sub][no][3]*k1, Ho, Lo);
                    *reinterpret_cast<uint4*>(QS + r1*XSTR + ch*16 + tg*4) = make_uint4(He, Ho, Le, Lo);
                }
            }
        }
    }

    // ---- K = x wk^T + bk, normalize, split -> KS
    gemm_proj(X, g_wh + 1 * 32768, acc, rbase, warpN, gid, tg);
    {
#pragma unroll
        for (int sub = 0; sub < 2; sub++)
#pragma unroll
            for (int nf = 0; nf < 8; nf++) {
                float2 bb = *reinterpret_cast<const float2*>(bk + warpN * 64 + nf * 8 + 2 * tg);
                acc[sub][nf][0] += bb.x; acc[sub][nf][1] += bb.y;
                acc[sub][nf][2] += bb.x; acc[sub][nf][3] += bb.y;
            }
#pragma unroll
        for (int sub = 0; sub < 2; sub++) {
            int r0 = rbase + sub * 16 + gid, r1 = r0 + 8;
#pragma unroll
            for (int g = 0; g < 2; g++) {
                float ss0 = 0.f, ss1 = 0.f;
#pragma unroll
                for (int i = 0; i < 4; i++) {
                    float* C = acc[sub][4*g+i];
                    ss0 += C[0]*C[0] + C[1]*C[1];
                    ss1 += C[2]*C[2] + C[3]*C[3];
                }
                ss0 += __shfl_xor_sync(0xffffffffu, ss0, 1);
                ss0 += __shfl_xor_sync(0xffffffffu, ss0, 2);
                ss1 += __shfl_xor_sync(0xffffffffu, ss1, 1);
                ss1 += __shfl_xor_sync(0xffffffffu, ss1, 2);
                float k0 = rsqrtf(fmaxf(ss0, 1e-24f));
                float k1 = rsqrtf(fmaxf(ss1, 1e-24f));
#pragma unroll
                for (int u = 0; u < 2; u++) {
                    int ne = 4*g + 2*u, no = ne + 1;
                    int ch = warpN * 4 + 2*g + u;
                    uint32_t He, Le, Ho, Lo;
                    split2h(acc[sub][ne][0]*k0, acc[sub][ne][1]*k0, He, Le);
                    split2h(acc[sub][no][0]*k0, acc[sub][no][1]*k0, Ho, Lo);
                    *reinterpret_cast<uint4*>(KS + r0*XSTR + ch*16 + tg*4) = make_uint4(He, Ho, Le, Lo);
                    split2h(acc[sub][ne][2]*k1, acc[sub][ne][3]*k1, He, Le);
                    split2h(acc[sub][no][2]*k1, acc[sub][no][3]*k1, Ho, Lo);
                    *reinterpret_cast<uint4*>(KS + r1*XSTR + ch*16 + tg*4) = make_uint4(He, Ho, Le, Lo);
                }
            }
        }
    }

    // ---- VT = wv x^T + bv (transposed V), F4 split -> VTS (overlays X)
    {
        float av[2][8][4];
        gemm_vt(X, g_wh + 2 * 32768, av, warp, gid, tg);
#pragma unroll
        for (int sub = 0; sub < 2; sub++) {
            int d0 = warp * 32 + sub * 16 + gid, d1 = d0 + 8;
            float bv0 = bv[d0], bv1 = bv[d1];
#pragma unroll
            for (int kp = 0; kp < 4; kp++) {
                int ne = 2 * kp, no = ne + 1;
                uint32_t e0, f0, e1, f1;
                split2h(av[sub][ne][0] + bv0, av[sub][ne][1] + bv0, e0, f0);
                split2h(av[sub][no][0] + bv0, av[sub][no][1] + bv0, e1, f1);
                *reinterpret_cast<uint4*>(VTS + d0 * VSTR + ((kp + d0) & 3) * 16 + tg * 4) =
                    make_uint4(e0, e1, f0, f1);
                split2h(av[sub][ne][2] + bv1, av[sub][ne][3] + bv1, e0, f0);
                split2h(av[sub][no][2] + bv1, av[sub][no][3] + bv1, e1, f1);
                *reinterpret_cast<uint4*>(VTS + d1 * VSTR + ((kp + d1) & 3) * 16 + tg * 4) =
                    make_uint4(e0, e1, f0, f1);
            }
        }
    }
    __syncthreads();   // QS/KS/VTS all visible before attention

    // ---- attention: warp = head h. S via MMA (3-term, term-major groups);
    //      bias double-buffer prefetched; softmax normalization deferred
    //      past PV MMAs; P (split, unnormalized) chains into PV.
    {
        const int h = warp;
        const float NEG_INF = __int_as_float(0xff800000);
        const float* bias = g_bias + (wtype * 8 + h) * 4096;

        float2 PB0[2][8], PB1[2][8];
#pragma unroll
        for (int nt = 0; nt < 8; nt++) {
            PB0[0][nt] = *reinterpret_cast<const float2*>(bias + gid * 64 + nt * 8 + 2 * tg);
            PB1[0][nt] = *reinterpret_cast<const float2*>(bias + (gid + 8) * 64 + nt * 8 + 2 * tg);
        }

#pragma unroll 2
        for (int mt = 0; mt < 4; mt++) {
            const int par = mt & 1, nxt = par ^ 1;
            int r0 = mt * 16 + gid, r1 = r0 + 8;

            float S[8][4];
#pragma unroll
            for (int nt = 0; nt < 8; nt++)
#pragma unroll
                for (int j = 0; j < 4; j++) S[nt][j] = 0.f;
#pragma unroll
            for (int kc = 0; kc < 2; kc++) {
                const uint4 A0 = *reinterpret_cast<const uint4*>(
                    QS + r0 * XSTR + (2 * h + kc) * 16 + tg * 4);
                const uint4 A1 = *reinterpret_cast<const uint4*>(
                    QS + r1 * XSTR + (2 * h + kc) * 16 + tg * 4);
#pragma unroll
                for (int gq = 0; gq < 2; gq++) {
                    uint4 Bv[4];
#pragma unroll
                    for (int i = 0; i < 4; i++)
                        Bv[i] = *reinterpret_cast<const uint4*>(
                            KS + ((gq * 4 + i) * 8 + gid) * XSTR + (2 * h + kc) * 16 + tg * 4);
#pragma unroll
                    for (int i = 0; i < 4; i++)
                        MMAH(S[gq*4+i], A0.x, A1.x, A0.y, A1.y, Bv[i].x, Bv[i].y);
#pragma unroll
                    for (int i = 0; i < 4; i++)
                        MMAH(S[gq*4+i], A0.z, A1.z, A0.w, A1.w, Bv[i].x, Bv[i].y);
#pragma unroll
                    for (int i = 0; i < 4; i++)
                        MMAH(S[gq*4+i], A0.x, A1.x, A0.y, A1.y, Bv[i].z, Bv[i].w);
                }
            }
            // prefetch next mt's bias (overlaps softmax + PV below)
            if (mt < 3) {
#pragma unroll
                for (int nt = 0; nt < 8; nt++) {
                    PB0[nxt][nt] = *reinterpret_cast<const float2*>(
                        bias + (r0 + 16) * 64 + nt * 8 + 2 * tg);
                    PB1[nxt][nt] = *reinterpret_cast<const float2*>(
                        bias + (r1 + 16) * 64 + nt * 8 + 2 * tg);
                }
            }
            float mx0 = NEG_INF, mx1 = NEG_INF;
#pragma unroll
            for (int nt = 0; nt < 8; nt++) {
                S[nt][0] += PB0[par][nt].x;
                S[nt][1] += PB0[par][nt].y;
                S[nt][2] += PB1[par][nt].x;
                S[nt][3] += PB1[par][nt].y;
                mx0 = fmaxf(mx0, fmaxf(S[nt][0], S[nt][1]));
                mx1 = fmaxf(mx1, fmaxf(S[nt][2], S[nt][3]));
            }
            mx0 = fmaxf(mx0, __shfl_xor_sync(0xffffffffu, mx0, 1));
            mx0 = fmaxf(mx0, __shfl_xor_sync(0xffffffffu, mx0, 2));
            mx1 = fmaxf(mx1, __shfl_xor_sync(0xffffffffu, mx1, 1));
            mx1 = fmaxf(mx1, __shfl_xor_sync(0xffffffffu, mx1, 2));
            float s0 = 0.f, s1 = 0.f;
#pragma unroll
            for (int nt = 0; nt < 8; nt++) {
                S[nt][0] = __expf(S[nt][0] - mx0); s0 += S[nt][0];
                S[nt][1] = __expf(S[nt][1] - mx0); s0 += S[nt][1];
                S[nt][2] = __expf(S[nt][2] - mx1); s1 += S[nt][2];
                S[nt][3] = __expf(S[nt][3] - mx1); s1 += S[nt][3];
            }
            // split UNNORMALIZED P; PV proceeds while the sum reduces
            uint32_t ph0[8], ph1[8], pl0[8], pl1[8];
#pragma unroll
            for (int nt = 0; nt < 8; nt++) {
                split2h(S[nt][0], S[nt][1], ph0[nt], pl0[nt]);
                split2h(S[nt][2], S[nt][3], ph1[nt], pl1[nt]);
            }
            float O[4][4];
#pragma unroll
            for (int dt = 0; dt < 4; dt++)
#pragma unroll
                for (int j = 0; j < 4; j++) O[dt][j] = 0.f;
#pragma unroll
            for (int kp = 0; kp < 4; kp++) {
                uint32_t ah0 = ph0[2*kp], ah1 = ph1[2*kp], ah2 = ph0[2*kp+1], ah3 = ph1[2*kp+1];
                uint32_t al0 = pl0[2*kp], al1 = pl1[2*kp], al2 = pl0[2*kp+1], al3 = pl1[2*kp+1];
                uint4 Bv[4];
#pragma unroll
                for (int dt = 0; dt < 4; dt++) {
                    int d = h * 32 + dt * 8 + gid;
                    Bv[dt] = *reinterpret_cast<const uint4*>(
                        VTS + d * VSTR + ((kp + d) & 3) * 16 + tg * 4);
                }
#pragma unroll
                for (int dt = 0; dt < 4; dt++)
                    MMAH(O[dt], ah0, ah1, ah2, ah3, Bv[dt].x, Bv[dt].y);
#pragma unroll
                for (int dt = 0; dt < 4; dt++)
                    MMAH(O[dt], al0, al1, al2, al3, Bv[dt].x, Bv[dt].y);
#pragma unroll
                for (int dt = 0; dt < 4; dt++)
                    MMAH(O[dt], ah0, ah1, ah2, ah3, Bv[dt].z, Bv[dt].w);
            }
            s0 += __shfl_xor_sync(0xffffffffu, s0, 1);
            s0 += __shfl_xor_sync(0xffffffffu, s0, 2);
            s1 += __shfl_xor_sync(0xffffffffu, s1, 1);
            s1 += __shfl_xor_sync(0xffffffffu, s1, 2);
            float inv0 = 1.f / s0, inv1 = 1.f / s1;
#pragma unroll
            for (int dt = 0; dt < 4; dt++) {
                O[dt][0] *= inv0; O[dt][1] *= inv0;
                O[dt][2] *= inv1; O[dt][3] *= inv1;
            }
            // store O (F4) into QS chunks 2h/2h+1 (this warp's private cols)
#pragma unroll
            for (int gg = 0; gg < 2; gg++) {
                uint32_t e0, f0, e1, f1;
                split2h(O[2*gg][0], O[2*gg][1], e0, f0);
                split2h(O[2*gg+1][0], O[2*gg+1][1], e1, f1);
                *reinterpret_cast<uint4*>(QS + r0 * XSTR + (2*h + gg) * 16 + tg * 4) =
                    make_uint4(e0, e1, f0, f1);
                split2h(O[2*gg][2], O[2*gg][3], e0, f0);
                split2h(O[2*gg+1][2], O[2*gg+1][3], e1, f1);
                *reinterpret_cast<uint4*>(QS + r1 * XSTR + (2*h + gg) * 16 + tg * 4) =
                    make_uint4(e0, e1, f0, f1);
            }
        }
    }
    __syncthreads();   // O (in QS) visible before Z gemm

    // ---- Z = O wo^T + bo -> global with inverse cyclic shift
    gemm_proj(QS, g_wh + 3 * 32768, acc, rbase, warpN, gid, tg);
    {
#pragma unroll
        for (int i = 0; i < 4; i++) {
            int r = rbase + i * 8 + gid;
            int rr = r >> 3, cc = r & 7;
            int oh = (wh * 8 + rr + 12) & 15, ow = (ww * 8 + cc + 12) & 15;
            float* d = out + ((size_t)(b * 16 + oh) * 16 + ow) * 256;
            int sub = i >> 1, half = i & 1;
#pragma unroll
            for (int nf = 0; nf < 8; nf++) {
                int c = warpN * 64 + nf * 8 + 2 * tg;
                float2 bb = *reinterpret_cast<const float2*>(bo + c);
                float2 z = {acc[sub][nf][half*2] + bb.x, acc[sub][nf][half*2+1] + bb.y};
                *reinterpret_cast<float2*>(d + c) = z;
            }
        }
    }
}

// ---------------------------------------------------------------------------
extern "C" void kernel_launch(void* const* d_in, const int* in_sizes, int n_in,
                              void* d_out, int out_size)
{
    const float* img = (const float*)d_in[0];
    const float* wq  = (const float*)d_in[1];
    const float* bq  = (const float*)d_in[2];
    const float* wk  = (const float*)d_in[3];
    const float* bk  = (const float*)d_in[4];
    const float* wv  = (const float*)d_in[5];
    const float* bv  = (const float*)d_in[6];
    const float* wo  = (const float*)d_in[7];
    const float* bo  = (const float*)d_in[8];
    const float* ls  = (const float*)d_in[9];
    const float* cw1 = (const float*)d_in[10];
    const float* cb1 = (const float*)d_in[11];
    const float* cw2 = (const float*)d_in[12];
    (void)in_sizes; (void)n_in; (void)out_size;

    cudaFuncSetAttribute(swin_kernel,
                         cudaFuncAttributeMaxDynamicSharedMemorySize,
                         SMEM_U32 * 4);

    prep_kernel<<<289, 256>>>(cw1, cb1, cw2, wq, wk, wv, wo);
    swin_kernel<<<2048, 256, SMEM_U32 * 4>>>(img, bq, bk, bv, bo, ls,
                                             (float*)d_out);
}

// round 12
// speedup vs baseline: 3.1369x; 1.0058x over previous
#include <cuda_runtime.h>
#include <cuda_fp16.h>
#include <math.h>
#include <stdint.h>

// Swin-V2 shifted-window MHA: split-fp16 tensor-core (mma.m16n8k16.f16).
// One CTA (256 thr = 8 warps) per window; 2048 CTAs. Warp = head in attention.
// Projections: 2-term split (Ah*Bh + Al*Bh), W hi-only. Attention: 3-term.
// Weights read directly from global (L2-resident, fragment-ordered LDG.64,
// 2-chunk-ahead prefetch + CROSS-PHASE prefetch: next GEMM's first chunks
// load before the previous epilogue). Attention S(mt+1) MMAs issue before
// softmax(mt) so the tensor pipe never drains (parity-indexed S buffers).
//
// "F4" layout (x, Q, K, O): u32 rows of XSTR; chunk g (16 values), group tg:
//   uint4 at row*XSTR + g*16 + tg*4 = {hi(pair g8+tg), hi(pair g8+tg+4), lo, lo}

#define XSTR 272
#define VSTR 64

#define OFF_X   0        // x F4 (17408); VT F4 (16384) overlays after V gemm
#define OFF_Q   17408    // Q F4 -> O F4
#define OFF_K   34816    // K F4
#define SMEM_U32 52224   // 208896 bytes

__device__ uint32_t g_wh[4 * 16 * 256 * 8];   // [w][kc][n][8] fp16-hi pairs
__device__ float    g_bias[4 * 8 * 64 * 64];  // [wtype][h][n][m], masked=-1e30

__device__ __forceinline__ uint32_t pack2h(float x, float y) {
    uint32_t r;
    asm("cvt.rn.f16x2.f32 %0, %1, %2;" : "=r"(r) : "f"(y), "f"(x));  // y->hi, x->lo
    return r;
}
__device__ __forceinline__ void split2h(float x, float y, uint32_t& h, uint32_t& l) {
    uint32_t hh;
    asm("cvt.rn.f16x2.f32 %0, %1, %2;" : "=r"(hh) : "f"(y), "f"(x));
    __half2 h2 = *reinterpret_cast<__half2*>(&hh);
    float rx = x - __half2float(__low2half(h2));
    float ry = y - __half2float(__high2half(h2));
    uint32_t ll;
    asm("cvt.rn.f16x2.f32 %0, %1, %2;" : "=r"(ll) : "f"(ry), "f"(rx));
    h = hh; l = ll;
}

#define MMAH(C, A0, A1, A2, A3, B0, B1)                                       \
    asm volatile("mma.sync.aligned.m16n8k16.row.col.f32.f16.f16.f32 "         \
                 "{%0,%1,%2,%3}, {%4,%5,%6,%7}, {%8,%9}, {%0,%1,%2,%3};"      \
                 : "+f"(C[0]), "+f"(C[1]), "+f"(C[2]), "+f"(C[3])             \
                 : "r"(A0), "r"(A1), "r"(A2), "r"(A3), "r"(B0), "r"(B1))

// ---------------------------------------------------------------------------
// Prep: blocks 0..63 = weight split; blocks 64..288 = masked bias table.
// ---------------------------------------------------------------------------
__global__ void prep_kernel(const float* __restrict__ w1,
                            const float* __restrict__ b1,
                            const float* __restrict__ w2,
                            const float* __restrict__ wq,
                            const float* __restrict__ wk,
                            const float* __restrict__ wv,
                            const float* __restrict__ wo)
{
    __shared__ float ws[8][8];
    __shared__ float bv[8];
    int t = threadIdx.x;

    if (blockIdx.x < 64) {
        const float* wsrc[4] = {wq, wk, wv, wo};
        int w = blockIdx.x >> 4, kc = blockIdx.x & 15;
        const float* src = wsrc[w] + t * 256 + kc * 16;
        float v[16];
#pragma unroll
        for (int i = 0; i < 4; i++) {
            float4 q = *reinterpret_cast<const float4*>(src + i * 4);
            v[4*i] = q.x; v[4*i+1] = q.y; v[4*i+2] = q.z; v[4*i+3] = q.w;
        }
        uint32_t u[8];
#pragma unroll
        for (int tg = 0; tg < 4; tg++) {
            u[tg*2]   = pack2h(v[2*tg],   v[2*tg+1]);
            u[tg*2+1] = pack2h(v[8+2*tg], v[9+2*tg]);
        }
        uint32_t* dst = g_wh + (blockIdx.x * 256 + t) * 8;
        *reinterpret_cast<uint4*>(dst)     = make_uint4(u[0], u[1], u[2], u[3]);
        *reinterpret_cast<uint4*>(dst + 4) = make_uint4(u[4], u[5], u[6], u[7]);
        return;
    }

    int cell = blockIdx.x - 64;           // 0..224
    int a = cell / 15, bcol = cell % 15;
    float ra = (a - 7) * (8.0f / 7.0f);
    float rb = (bcol - 7) * (8.0f / 7.0f);
    float va = (ra >= 0.f ? 1.f : -1.f) * log2f(fabsf(ra) + 1.f) * (1.f / 3.f);
    float vb = (rb >= 0.f ? 1.f : -1.f) * log2f(fabsf(rb) + 1.f) * (1.f / 3.f);

    int j1 = t, j2 = t + 256;
    float h1 = fmaxf(va * w1[j1 * 2] + vb * w1[j1 * 2 + 1] + b1[j1], 0.f);
    float h2 = fmaxf(va * w1[j2 * 2] + vb * w1[j2 * 2 + 1] + b1[j2], 0.f);

    float p[8];
#pragma unroll
    for (int h = 0; h < 8; h++)
        p[h] = h1 * w2[h * 512 + j1] + h2 * w2[h * 512 + j2];
#pragma unroll
    for (int h = 0; h < 8; h++)
#pragma unroll
        for (int off = 16; off; off >>= 1)
            p[h] += __shfl_xor_sync(0xffffffffu, p[h], off);

    int warp = t >> 5, lane = t & 31;
    if (lane == 0) {
#pragma unroll
        for (int h = 0; h < 8; h++) ws[warp][h] = p[h];
    }
    __syncthreads();
    if (t < 8) {
        float s = 0.f;
#pragma unroll
        for (int w = 0; w < 8; w++) s += ws[w][t];
        bv[t] = 16.f / (1.f + expf(-s));
    }
    __syncthreads();

    int da = a - 7, db = bcol - 7;
    int cntA = 8 - abs(da), cntB = 8 - abs(db);
    int rn0 = da > 0 ? da : 0, cn0 = db > 0 ? db : 0;
    int total = cntA * cntB * 32;
    for (int idx = t; idx < total; idx += 256) {
        int tmp = idx;
        int h = tmp & 7; tmp >>= 3;
        int wt_ = tmp & 3; tmp >>= 2;
        int pa = tmp / cntB, pb = tmp - pa * cntB;
        int rn = rn0 + pa, cn = cn0 + pb;
        int rm = rn - da, cm = cn - db;
        int wh = wt_ >> 1, ww = wt_ & 1;
        int ghn = wh * 8 + rn, gwn = ww * 8 + cn;
        int ghm = wh * 8 + rm, gwm = ww * 8 + cm;
        int gn = ((ghn < 8) ? 0 : (ghn < 12 ? 1 : 2)) * 3 + ((gwn < 8) ? 0 : (gwn < 12 ? 1 : 2));
        int gm = ((ghm < 8) ? 0 : (ghm < 12 ? 1 : 2)) * 3 + ((gwm < 8) ? 0 : (gwm < 12 ? 1 : 2));
        float val = (gn == gm) ? bv[h] : -1e30f;
        g_bias[((wt_ * 8 + h) * 64 + rn * 8 + cn) * 64 + rm * 8 + cm] = val;
    }
}

// ---- one 16-wide k-chunk of the projection GEMM (32 MMAs, hi/lo sweeps) ----
#define PROJ_CHUNK(B, kc)                                                     \
    do {                                                                      \
        const uint32_t* a_ = ap + (kc) * 16;                                  \
        const uint4 A0 = *reinterpret_cast<const uint4*>(a_);                 \
        const uint4 A1 = *reinterpret_cast<const uint4*>(a_ + 8 * XSTR);      \
        const uint4 A2 = *reinterpret_cast<const uint4*>(a_ + 16 * XSTR);     \
        const uint4 A3 = *reinterpret_cast<const uint4*>(a_ + 24 * XSTR);     \
        _Pragma("unroll")                                                     \
        for (int nf = 0; nf < 8; nf++)                                        \
            MMAH(acc[0][nf], A0.x, A1.x, A0.y, A1.y, B[nf].x, B[nf].y);       \
        _Pragma("unroll")                                                     \
        for (int nf = 0; nf < 8; nf++)                                        \
            MMAH(acc[1][nf], A2.x, A3.x, A2.y, A3.y, B[nf].x, B[nf].y);       \
        _Pragma("unroll")                                                     \
        for (int nf = 0; nf < 8; nf++)                                        \
            MMAH(acc[0][nf], A0.z, A1.z, A0.w, A1.w, B[nf].x, B[nf].y);       \
        _Pragma("unroll")                                                     \
        for (int nf = 0; nf < 8; nf++)                                        \
            MMAH(acc[1][nf], A2.z, A3.z, A2.w, A3.w, B[nf].x, B[nf].y);       \
    } while (0)

#define PROJ_LD(B, c)                                                         \
    do {                                                                      \
        _Pragma("unroll")                                                     \
        for (int nf = 0; nf < 8; nf++) B[nf] = __ldg(gb + (c) * 1024 + nf * 32); \
    } while (0)

// caller-side prefetch of a projection GEMM's first two chunks
#define PROJ_PRE(gw)                                                          \
    do {                                                                      \
        gb = reinterpret_cast<const uint2*>(gw) + (warpN * 64 + gid) * 4 + tg; \
        PROJ_LD(Ba, 0);                                                       \
        PROJ_LD(Bb, 1);                                                       \
    } while (0)

// ---------------------------------------------------------------------------
// Projection GEMM (2-term): out(64x256) = A(F4 smem) @ Whi^T.
// Warp tile 32x64. First two B chunks preloaded by caller (Ba/Bb).
// ---------------------------------------------------------------------------
__device__ __forceinline__ void gemm_proj(
    const uint32_t* __restrict__ src, const uint2* __restrict__ gb,
    uint2 Ba[8], uint2 Bb[8],
    float acc[2][8][4], int rbase, int gid, int tg)
{
#pragma unroll
    for (int s = 0; s < 2; s++)
#pragma unroll
        for (int nf = 0; nf < 8; nf++)
#pragma unroll
            for (int j = 0; j < 4; j++) acc[s][nf][j] = 0.f;

    const uint32_t* ap = src + (rbase + gid) * XSTR + tg * 4;
    uint2 Bc[8], Bd[8];

#pragma unroll 1
    for (int it = 0; it < 4; it++) {
        const int c = 4 * it;
        PROJ_LD(Bc, c + 2);
        PROJ_CHUNK(Ba, c);
        PROJ_LD(Bd, c + 3);
        PROJ_CHUNK(Bb, c + 1);
        const int c4 = (c + 4 < 16) ? c + 4 : 15;
        PROJ_LD(Ba, c4);
        PROJ_CHUNK(Bc, c + 2);
        const int c5 = (c + 5 < 16) ? c + 5 : 15;
        PROJ_LD(Bb, c5);
        PROJ_CHUNK(Bd, c + 3);
    }
}

// ---- one 16-wide k-chunk of the VT GEMM (32 MMAs, term-major nf pairs) ----
#define VT_CHUNK(W, kc)                                                       \
    do {                                                                      \
        const uint32_t* xp = xp0 + (kc) * 16;                                 \
        _Pragma("unroll")                                                     \
        for (int p = 0; p < 4; p++) {                                         \
            const uint4 Xa = *reinterpret_cast<const uint4*>(xp + (2*p) * 8 * XSTR);   \
            const uint4 Xb = *reinterpret_cast<const uint4*>(xp + (2*p+1) * 8 * XSTR); \
            MMAH(av[0][2*p],   W[0].x, W[1].x, W[0].y, W[1].y, Xa.x, Xa.y);   \
            MMAH(av[1][2*p],   W[2].x, W[3].x, W[2].y, W[3].y, Xa.x, Xa.y);   \
            MMAH(av[0][2*p+1], W[0].x, W[1].x, W[0].y, W[1].y, Xb.x, Xb.y);   \
            MMAH(av[1][2*p+1], W[2].x, W[3].x, W[2].y, W[3].y, Xb.x, Xb.y);   \
            MMAH(av[0][2*p],   W[0].x, W[1].x, W[0].y, W[1].y, Xa.z, Xa.w);   \
            MMAH(av[1][2*p],   W[2].x, W[3].x, W[2].y, W[3].y, Xa.z, Xa.w);   \
            MMAH(av[0][2*p+1], W[0].x, W[1].x, W[0].y, W[1].y, Xb.z, Xb.w);   \
            MMAH(av[1][2*p+1], W[2].x, W[3].x, W[2].y, W[3].y, Xb.z, Xb.w);   \
        }                                                                     \
    } while (0)

#define VT_LD(W, c)                                                           \
    do {                                                                      \
        _Pragma("unroll")                                                     \
        for (int i = 0; i < 4; i++) W[i] = __ldg(ga + (c) * 1024 + i * 32);   \
    } while (0)

#define VT_PRE(gw)                                                            \
    do {                                                                      \
        ga = reinterpret_cast<const uint2*>(gw) + (warp * 32 + gid) * 4 + tg; \
        VT_LD(Wa, 0);                                                         \
        VT_LD(Wb, 1);                                                         \
    } while (0)

// ---------------------------------------------------------------------------
// VT GEMM (2-term): VT(256x64) = Wv_hi (A, direct LDG, caller-preloaded
// first chunks) @ x^T. Warp: 32 d-rows. Ends with a barrier.
// ---------------------------------------------------------------------------
__device__ __forceinline__ void gemm_vt(
    const uint32_t* __restrict__ x, const uint2* __restrict__ ga,
    uint2 Wa[4], uint2 Wb[4],
    float av[2][8][4], int gid, int tg)
{
#pragma unroll
    for (int s = 0; s < 2; s++)
#pragma unroll
        for (int nf = 0; nf < 8; nf++)
#pragma unroll
            for (int j = 0; j < 4; j++) av[s][nf][j] = 0.f;

    const uint32_t* xp0 = x + gid * XSTR + tg * 4;
    uint2 Wc[4], Wd[4];

#pragma unroll 1
    for (int it = 0; it < 4; it++) {
        const int c = 4 * it;
        VT_LD(Wc, c + 2);
        VT_CHUNK(Wa, c);
        VT_LD(Wd, c + 3);
        VT_CHUNK(Wb, c + 1);
        const int c4 = (c + 4 < 16) ? c + 4 : 15;
        VT_LD(Wa, c4);
        VT_CHUNK(Wc, c + 2);
        const int c5 = (c + 5 < 16) ? c + 5 : 15;
        VT_LD(Wb, c5);
        VT_CHUNK(Wd, c + 3);
    }
    __syncthreads();   // all X reads complete before VTS overwrite
}

// ---- attention S block for one mt: 24 MMAs into Sd ----
#define ATT_S(Sd, r0_, r1_)                                                   \
    do {                                                                      \
        _Pragma("unroll")                                                     \
        for (int nt = 0; nt < 8; nt++)                                        \
            _Pragma("unroll")                                                 \
            for (int j = 0; j < 4; j++) Sd[nt][j] = 0.f;                      \
        _Pragma("unroll")                                                     \
        for (int kc = 0; kc < 2; kc++) {                                      \
            const uint4 A0 = *reinterpret_cast<const uint4*>(                 \
                QS + (r0_) * XSTR + (2 * h + kc) * 16 + tg * 4);              \
            const uint4 A1 = *reinterpret_cast<const uint4*>(                 \
                QS + (r1_) * XSTR + (2 * h + kc) * 16 + tg * 4);              \
            _Pragma("unroll")                                                 \
            for (int gq = 0; gq < 2; gq++) {                                  \
                uint4 Bv[4];                                                  \
                _Pragma("unroll")                                             \
                for (int i = 0; i < 4; i++)                                   \
                    Bv[i] = *reinterpret_cast<const uint4*>(                  \
                        KS + ((gq * 4 + i) * 8 + gid) * XSTR + (2 * h + kc) * 16 + tg * 4); \
                _Pragma("unroll")                                             \
                for (int i = 0; i < 4; i++)                                   \
                    MMAH(Sd[gq*4+i], A0.x, A1.x, A0.y, A1.y, Bv[i].x, Bv[i].y); \
                _Pragma("unroll")                                             \
                for (int i = 0; i < 4; i++)                                   \
                    MMAH(Sd[gq*4+i], A0.z, A1.z, A0.w, A1.w, Bv[i].x, Bv[i].y); \
                _Pragma("unroll")                                             \
                for (int i = 0; i < 4; i++)                                   \
                    MMAH(Sd[gq*4+i], A0.x, A1.x, A0.y, A1.y, Bv[i].z, Bv[i].w); \
            }                                                                 \
        }                                                                     \
    } while (0)

// ---------------------------------------------------------------------------
__global__ __launch_bounds__(256, 1)
void swin_kernel(const float* __restrict__ img,
                 const float* __restrict__ bq, const float* __restrict__ bk,
                 const float* __restrict__ bv, const float* __restrict__ bo,
                 const float* __restrict__ ls,
                 float* __restrict__ out)
{
    extern __shared__ uint32_t smu[];
    uint32_t* X   = smu + OFF_X;
    uint32_t* QS  = smu + OFF_Q;
    uint32_t* KS  = smu + OFF_K;
    uint32_t* VTS = smu + OFF_X;        // overlays X after V gemm

    const int t    = threadIdx.x;
    const int lane = t & 31;
    const int warp = t >> 5;
    const int warpM = warp & 1, warpN = warp >> 1;
    const int gid = lane >> 2, tg = lane & 3;
    const int blk = blockIdx.x;
    const int b   = blk >> 2;
    const int wh  = (blk >> 1) & 1, ww = blk & 1;
    const int wtype = blk & 3;

    const uint2* gb;  uint2 Ba[8], Bb[8];   // projection prefetch state
    const uint2* ga;  uint2 Wa[4], Wb[4];   // VT prefetch state

    // ---- load shifted window -> x F4 split (fp16 hi/lo)
    const float* imgb = img + (size_t)b * (16 * 16 * 256);
#pragma unroll
    for (int i = 0; i < 16; i++) {
        int f = i * 256 + t;            // float4 index
        int tok = f >> 6, c4 = f & 63;
        int r = tok >> 3, c = tok & 7;
        int ih = (wh * 8 + r + 12) & 15;
        int iw = (ww * 8 + c + 12) & 15;
        float4 v = *reinterpret_cast<const float4*>(&imgb[(ih * 16 + iw) * 256 + c4 * 4]);
        uint32_t h0, l0, h1, l1;
        split2h(v.x, v.y, h0, l0);
        split2h(v.z, v.w, h1, l1);
        int p0 = 2 * c4;
        int g = p0 >> 3, pos = p0 & 7;
        int tgs = pos & 3, slot = pos >> 2;
        uint32_t* base = X + tok * XSTR + g * 16 + slot;
        base[tgs * 4]           = h0;
        base[(tgs + 1) * 4]     = h1;
        base[tgs * 4 + 2]       = l0;
        base[(tgs + 1) * 4 + 2] = l1;
    }
    PROJ_PRE(g_wh + 0 * 32768);    // Q weights in flight across the barrier
    __syncthreads();               // X visible to all warps

    float acc[2][8][4];
    const int rbase = warpM * 32;

    // ---- Q = x wq^T + bq, cosine-normalize * scale, split -> QS
    gemm_proj(X, gb, Ba, Bb, acc, rbase, gid, tg);
    PROJ_PRE(g_wh + 1 * 32768);    // K weights load under the Q epilogue
    {
#pragma unroll
        for (int sub = 0; sub < 2; sub++)
#pragma unroll
            for (int nf = 0; nf < 8; nf++) {
                float2 bb = *reinterpret_cast<const float2*>(bq + warpN * 64 + nf * 8 + 2 * tg);
                acc[sub][nf][0] += bb.x; acc[sub][nf][1] += bb.y;
                acc[sub][nf][2] += bb.x; acc[sub][nf][3] += bb.y;
            }
#pragma unroll
        for (int sub = 0; sub < 2; sub++) {
            int r0 = rbase + sub * 16 + gid, r1 = r0 + 8;
#pragma unroll
            for (int g = 0; g < 2; g++) {
                float ss0 = 0.f, ss1 = 0.f;
#pragma unroll
                for (int i = 0; i < 4; i++) {
                    float* C = acc[sub][4*g+i];
                    ss0 += C[0]*C[0] + C[1]*C[1];
                    ss1 += C[2]*C[2] + C[3]*C[3];
                }
                ss0 += __shfl_xor_sync(0xffffffffu, ss0, 1);
                ss0 += __shfl_xor_sync(0xffffffffu, ss0, 2);
                ss1 += __shfl_xor_sync(0xffffffffu, ss1, 1);
                ss1 += __shfl_xor_sync(0xffffffffu, ss1, 2);
                float sc = __expf(fminf(ls[warpN * 2 + g], 4.6051702f));
                float k0 = sc * rsqrtf(fmaxf(ss0, 1e-24f));
                float k1 = sc * rsqrtf(fmaxf(ss1, 1e-24f));
#pragma unroll
                for (int u = 0; u < 2; u++) {
                    int ne = 4*g + 2*u, no = ne + 1;
                    int ch = warpN * 4 + 2*g + u;
                    uint32_t He, Le, Ho, Lo;
                    split2h(acc[sub][ne][0]*k0, acc[sub][ne][1]*k0, He, Le);
                    split2h(acc[sub][no][0]*k0, acc[sub][no][1]*k0, Ho, Lo);
                    *reinterpret_cast<uint4*>(QS + r0*XSTR + ch*16 + tg*4) = make_uint4(He, Ho, Le, Lo);
                    split2h(acc[sub][ne][2]*k1, acc[sub][ne][3]*k1, He, Le);
                    split2h(acc[sub][no][2]*k1, acc[sub][no][3]*k1, Ho, Lo);
                    *reinterpret_cast<uint4*>(QS + r1*XSTR + ch*16 + tg*4) = make_uint4(He, Ho, Le, Lo);
                }
            }
        }
    }

    // ---- K = x wk^T + bk, normalize, split -> KS
    gemm_proj(X, gb, Ba, Bb, acc, rbase, gid, tg);
    VT_PRE(g_wh + 2 * 32768);      // V weights load under the K epilogue
    {
#pragma unroll
        for (int sub = 0; sub < 2; sub++)
#pragma unroll
            for (int nf = 0; nf < 8; nf++) {
                float2 bb = *reinterpret_cast<const float2*>(bk + warpN * 64 + nf * 8 + 2 * tg);
                acc[sub][nf][0] += bb.x; acc[sub][nf][1] += bb.y;
                acc[sub][nf][2] += bb.x; acc[sub][nf][3] += bb.y;
            }
#pragma unroll
        for (int sub = 0; sub < 2; sub++) {
            int r0 = rbase + sub * 16 + gid, r1 = r0 + 8;
#pragma unroll
            for (int g = 0; g < 2; g++) {
                float ss0 = 0.f, ss1 = 0.f;
#pragma unroll
                for (int i = 0; i < 4; i++) {
                    float* C = acc[sub][4*g+i];
                    ss0 += C[0]*C[0] + C[1]*C[1];
                    ss1 += C[2]*C[2] + C[3]*C[3];
                }
                ss0 += __shfl_xor_sync(0xffffffffu, ss0, 1);
                ss0 += __shfl_xor_sync(0xffffffffu, ss0, 2);
                ss1 += __shfl_xor_sync(0xffffffffu, ss1, 1);
                ss1 += __shfl_xor_sync(0xffffffffu, ss1, 2);
                float k0 = rsqrtf(fmaxf(ss0, 1e-24f));
                float k1 = rsqrtf(fmaxf(ss1, 1e-24f));
#pragma unroll
                for (int u = 0; u < 2; u++) {
                    int ne = 4*g + 2*u, no = ne + 1;
                    int ch = warpN * 4 + 2*g + u;
                    uint32_t He, Le, Ho, Lo;
                    split2h(acc[sub][ne][0]*k0, acc[sub][ne][1]*k0, He, Le);
                    split2h(acc[sub][no][0]*k0, acc[sub][no][1]*k0, Ho, Lo);
                    *reinterpret_cast<uint4*>(KS + r0*XSTR + ch*16 + tg*4) = make_uint4(He, Ho, Le, Lo);
                    split2h(acc[sub][ne][2]*k1, acc[sub][ne][3]*k1, He, Le);
                    split2h(acc[sub][no][2]*k1, acc[sub][no][3]*k1, Ho, Lo);
                    *reinterpret_cast<uint4*>(KS + r1*XSTR + ch*16 + tg*4) = make_uint4(He, Ho, Le, Lo);
                }
            }
        }
    }

    // ---- VT = wv x^T + bv (transposed V), F4 split -> VTS (overlays X)
    {
        float av[2][8][4];
        gemm_vt(X, ga, Wa, Wb, av, gid, tg);
#pragma unroll
        for (int sub = 0; sub < 2; sub++) {
            int d0 = warp * 32 + sub * 16 + gid, d1 = d0 + 8;
            float bv0 = bv[d0], bv1 = bv[d1];
#pragma unroll
            for (int kp = 0; kp < 4; kp++) {
                int ne = 2 * kp, no = ne + 1;
                uint32_t e0, f0, e1, f1;
                split2h(av[sub][ne][0] + bv0, av[sub][ne][1] + bv0, e0, f0);
                split2h(av[sub][no][0] + bv0, av[sub][no][1] + bv0, e1, f1);
                *reinterpret_cast<uint4*>(VTS + d0 * VSTR + ((kp + d0) & 3) * 16 + tg * 4) =
                    make_uint4(e0, e1, f0, f1);
                split2h(av[sub][ne][2] + bv1, av[sub][ne][3] + bv1, e0, f0);
                split2h(av[sub][no][2] + bv1, av[sub][no][3] + bv1, e1, f1);
                *reinterpret_cast<uint4*>(VTS + d1 * VSTR + ((kp + d1) & 3) * 16 + tg * 4) =
                    make_uint4(e0, e1, f0, f1);
            }
        }
    }
    __syncthreads();   // QS/KS/VTS all visible before attention

    // ---- attention: warp = head h. S(mt+1) MMAs issue BEFORE softmax(mt)
    //      (parity S buffers); bias double-buffer prefetched; softmax
    //      normalization deferred past PV MMAs.
    {
        const int h = warp;
        const float NEG_INF = __int_as_float(0xff800000);
        const float* bias = g_bias + (wtype * 8 + h) * 4096;

        float S[2][8][4];
        float2 PB0[2][8], PB1[2][8];
#pragma unroll
        for (int nt = 0; nt < 8; nt++) {
            PB0[0][nt] = *reinterpret_cast<const float2*>(bias + gid * 64 + nt * 8 + 2 * tg);
            PB1[0][nt] = *reinterpret_cast<const float2*>(bias + (gid + 8) * 64 + nt * 8 + 2 * tg);
        }
        ATT_S(S[0], gid, gid + 8);

#pragma unroll
        for (int mt = 0; mt < 4; mt++) {
            const int par = mt & 1, nxt = par ^ 1;
            int r0 = mt * 16 + gid, r1 = r0 + 8;

            // next tile's S MMAs + bias loads go first: tensor pipe stays
            // busy while this tile's softmax runs on fma/mufu.
            if (mt < 3) {
                ATT_S(S[nxt], r0 + 16, r1 + 16);
#pragma unroll
                for (int nt = 0; nt < 8; nt++) {
                    PB0[nxt][nt] = *reinterpret_cast<const float2*>(
                        bias + (r0 + 16) * 64 + nt * 8 + 2 * tg);
                    PB1[nxt][nt] = *reinterpret_cast<const float2*>(
                        bias + (r1 + 16) * 64 + nt * 8 + 2 * tg);
                }
            }
            float (*Sc)[4] = S[par];
            float mx0 = NEG_INF, mx1 = NEG_INF;
#pragma unroll
            for (int nt = 0; nt < 8; nt++) {
                Sc[nt][0] += PB0[par][nt].x;
                Sc[nt][1] += PB0[par][nt].y;
                Sc[nt][2] += PB1[par][nt].x;
                Sc[nt][3] += PB1[par][nt].y;
                mx0 = fmaxf(mx0, fmaxf(Sc[nt][0], Sc[nt][1]));
                mx1 = fmaxf(mx1, fmaxf(Sc[nt][2], Sc[nt][3]));
            }
            mx0 = fmaxf(mx0, __shfl_xor_sync(0xffffffffu, mx0, 1));
            mx0 = fmaxf(mx0, __shfl_xor_sync(0xffffffffu, mx0, 2));
            mx1 = fmaxf(mx1, __shfl_xor_sync(0xffffffffu, mx1, 1));
            mx1 = fmaxf(mx1, __shfl_xor_sync(0xffffffffu, mx1, 2));
            float s0 = 0.f, s1 = 0.f;
#pragma unroll
            for (int nt = 0; nt < 8; nt++) {
                Sc[nt][0] = __expf(Sc[nt][0] - mx0); s0 += Sc[nt][0];
                Sc[nt][1] = __expf(Sc[nt][1] - mx0); s0 += Sc[nt][1];
                Sc[nt][2] = __expf(Sc[nt][2] - mx1); s1 += Sc[nt][2];
                Sc[nt][3] = __expf(Sc[nt][3] - mx1); s1 += Sc[nt][3];
            }
            // split UNNORMALIZED P; PV proceeds while the sum reduces
            uint32_t ph0[8], ph1[8], pl0[8], pl1[8];
#pragma unroll
            for (int nt = 0; nt < 8; nt++) {
                split2h(Sc[nt][0], Sc[nt][1], ph0[nt], pl0[nt]);
                split2h(Sc[nt][2], Sc[nt][3], ph1[nt], pl1[nt]);
            }
            float O[4][4];
#pragma unroll
            for (int dt = 0; dt < 4; dt++)
#pragma unroll
                for (int j = 0; j < 4; j++) O[dt][j] = 0.f;
#pragma unroll
            for (int kp = 0; kp < 4; kp++) {
                uint32_t ah0 = ph0[2*kp], ah1 = ph1[2*kp], ah2 = ph0[2*kp+1], ah3 = ph1[2*kp+1];
                uint32_t al0 = pl0[2*kp], al1 = pl1[2*kp], al2 = pl0[2*kp+1], al3 = pl1[2*kp+1];
                uint4 Bv[4];
#pragma unroll
                for (int dt = 0; dt < 4; dt++) {
                    int d = h * 32 + dt * 8 + gid;
                    Bv[dt] = *reinterpret_cast<const uint4*>(
                        VTS + d * VSTR + ((kp + d) & 3) * 16 + tg * 4);
                }
#pragma unroll
                for (int dt = 0; dt < 4; dt++)
                    MMAH(O[dt], ah0, ah1, ah2, ah3, Bv[dt].x, Bv[dt].y);
#pragma unroll
                for (int dt = 0; dt < 4; dt++)
                    MMAH(O[dt], al0, al1, al2, al3, Bv[dt].x, Bv[dt].y);
#pragma unroll
                for (int dt = 0; dt < 4; dt++)
                    MMAH(O[dt], ah0, ah1, ah2, ah3, Bv[dt].z, Bv[dt].w);
            }
            s0 += __shfl_xor_sync(0xffffffffu, s0, 1);
            s0 += __shfl_xor_sync(0xffffffffu, s0, 2);
            s1 += __shfl_xor_sync(0xffffffffu, s1, 1);
            s1 += __shfl_xor_sync(0xffffffffu, s1, 2);
            float inv0 = 1.f / s0, inv1 = 1.f / s1;
#pragma unroll
            for (int dt = 0; dt < 4; dt++) {
                O[dt][0] *= inv0; O[dt][1] *= inv0;
                O[dt][2] *= inv1; O[dt][3] *= inv1;
            }
            // store O (F4) into QS chunks 2h/2h+1 (this warp's private cols)
#pragma unroll
            for (int gg = 0; gg < 2; gg++) {
                uint32_t e0, f0, e1, f1;
                split2h(O[2*gg][0], O[2*gg][1], e0, f0);
                split2h(O[2*gg+1][0], O[2*gg+1][1], e1, f1);
                *reinterpret_cast<uint4*>(QS + r0 * XSTR + (2*h + gg) * 16 + tg * 4) =
                    make_uint4(e0, e1, f0, f1);
                split2h(O[2*gg][2], O[2*gg][3], e0, f0);
                split2h(O[2*gg+1][2], O[2*gg+1][3], e1, f1);
                *reinterpret_cast<uint4*>(QS + r1 * XSTR + (2*h + gg) * 16 + tg * 4) =
                    make_uint4(e0, e1, f0, f1);
            }
        }
    }
    PROJ_PRE(g_wh + 3 * 32768);    // Z weights load across the barrier
    __syncthreads();               // O (in QS) visible before Z gemm

    // ---- Z = O wo^T + bo -> global with inverse cyclic shift
    gemm_proj(QS, gb, Ba, Bb, acc, rbase, gid, tg);
    {
#pragma unroll
        for (int i = 0; i < 4; i++) {
            int r = rbase + i * 8 + gid;
            int rr = r >> 3, cc = r & 7;
            int oh = (wh * 8 + rr + 12) & 15, ow = (ww * 8 + cc + 12) & 15;
            float* d = out + ((size_t)(b * 16 + oh) * 16 + ow) * 256;
            int sub = i >> 1, half = i & 1;
#pragma unroll
            for (int nf = 0; nf < 8; nf++) {
                int c = warpN * 64 + nf * 8 + 2 * tg;
                float2 bb = *reinterpret_cast<const float2*>(bo + c);
                float2 z = {acc[sub][nf][half*2] + bb.x, acc[sub][nf][half*2+1] + bb.y};
                *reinterpret_cast<float2*>(d + c) = z;
            }
        }
    }
}

// ---------------------------------------------------------------------------
extern "C" void kernel_launch(void* const* d_in, const int* in_sizes, int n_in,
                              void* d_out, int out_size)
{
    const float* img = (const float*)d_in[0];
    const float* wq  = (const float*)d_in[1];
    const float* bq  = (const float*)d_in[2];
    const float* wk  = (const float*)d_in[3];
    const float* bk  = (const float*)d_in[4];
    const float* wv  = (const float*)d_in[5];
    const float* bv  = (const float*)d_in[6];
    const float* wo  = (const float*)d_in[7];
    const float* bo  = (const float*)d_in[8];
    const float* ls  = (const float*)d_in[9];
    const float* cw1 = (const float*)d_in[10];
    const float* cb1 = (const float*)d_in[11];
    const float* cw2 = (const float*)d_in[12];
    (void)in_sizes; (void)n_in; (void)out_size;

    cudaFuncSetAttribute(swin_kernel,
                         cudaFuncAttributeMaxDynamicSharedMemorySize,
                         SMEM_U32 * 4);

    prep_kernel<<<289, 256>>>(cw1, cb1, cw2, wq, wk, wv, wo);
    swin_kernel<<<2048, 256, SMEM_U32 * 4>>>(img, bq, bk, bv, bo, ls,
                                             (float*)d_out);
}

// round 13
// speedup vs baseline: 3.1873x; 1.0161x over previous
#include <cuda_runtime.h>
#include <cuda_fp16.h>
#include <math.h>
#include <stdint.h>

// Swin-V2 shifted-window MHA: split-fp16 tensor-core (mma.m16n8k16.f16).
// One CTA (512 thr = 16 warps) per window; 2048 CTAs; 4 warps/SMSP.
// Projections: 2-term split (Ah*Bh + Al*Bh), W hi-only. Attention: 3-term.
// Weights read directly from global (L2-resident, fragment-ordered LDG.64,
// 1-chunk-ahead prefetch; cross-warp overlap hides the rest).
//
// "F4" layout (x, Q, K, O): u32 rows of XSTR; chunk g (16 values), group tg:
//   uint4 at row*XSTR + g*16 + tg*4 = {hi(pair g8+tg), hi(pair g8+tg+4), lo, lo}

#define XSTR 272
#define VSTR 64

#define OFF_X   0        // x F4 (17408); VT F4 (16384) overlays after V gemm
#define OFF_Q   17408    // Q F4 -> O F4
#define OFF_K   34816    // K F4
#define SMEM_U32 52224   // 208896 bytes

__device__ uint32_t g_wh[4 * 16 * 256 * 8];   // [w][kc][n][8] fp16-hi pairs
__device__ float    g_bias[4 * 8 * 64 * 64];  // [wtype][h][n][m], masked=-1e30

__device__ __forceinline__ uint32_t pack2h(float x, float y) {
    uint32_t r;
    asm("cvt.rn.f16x2.f32 %0, %1, %2;" : "=r"(r) : "f"(y), "f"(x));  // y->hi, x->lo
    return r;
}
__device__ __forceinline__ void split2h(float x, float y, uint32_t& h, uint32_t& l) {
    uint32_t hh;
    asm("cvt.rn.f16x2.f32 %0, %1, %2;" : "=r"(hh) : "f"(y), "f"(x));
    __half2 h2 = *reinterpret_cast<__half2*>(&hh);
    float rx = x - __half2float(__low2half(h2));
    float ry = y - __half2float(__high2half(h2));
    uint32_t ll;
    asm("cvt.rn.f16x2.f32 %0, %1, %2;" : "=r"(ll) : "f"(ry), "f"(rx));
    h = hh; l = ll;
}

#define MMAH(C, A0, A1, A2, A3, B0, B1)                                       \
    asm volatile("mma.sync.aligned.m16n8k16.row.col.f32.f16.f16.f32 "         \
                 "{%0,%1,%2,%3}, {%4,%5,%6,%7}, {%8,%9}, {%0,%1,%2,%3};"      \
                 : "+f"(C[0]), "+f"(C[1]), "+f"(C[2]), "+f"(C[3])             \
                 : "r"(A0), "r"(A1), "r"(A2), "r"(A3), "r"(B0), "r"(B1))

// ---------------------------------------------------------------------------
// Prep: blocks 0..63 = weight split; blocks 64..288 = masked bias table.
// ---------------------------------------------------------------------------
__global__ void prep_kernel(const float* __restrict__ w1,
                            const float* __restrict__ b1,
                            const float* __restrict__ w2,
                            const float* __restrict__ wq,
                            const float* __restrict__ wk,
                            const float* __restrict__ wv,
                            const float* __restrict__ wo)
{
    __shared__ float ws[8][8];
    __shared__ float bv[8];
    int t = threadIdx.x;

    if (blockIdx.x < 64) {
        const float* wsrc[4] = {wq, wk, wv, wo};
        int w = blockIdx.x >> 4, kc = blockIdx.x & 15;
        const float* src = wsrc[w] + t * 256 + kc * 16;
        float v[16];
#pragma unroll
        for (int i = 0; i < 4; i++) {
            float4 q = *reinterpret_cast<const float4*>(src + i * 4);
            v[4*i] = q.x; v[4*i+1] = q.y; v[4*i+2] = q.z; v[4*i+3] = q.w;
        }
        uint32_t u[8];
#pragma unroll
        for (int tg = 0; tg < 4; tg++) {
            u[tg*2]   = pack2h(v[2*tg],   v[2*tg+1]);
            u[tg*2+1] = pack2h(v[8+2*tg], v[9+2*tg]);
        }
        uint32_t* dst = g_wh + (blockIdx.x * 256 + t) * 8;
        *reinterpret_cast<uint4*>(dst)     = make_uint4(u[0], u[1], u[2], u[3]);
        *reinterpret_cast<uint4*>(dst + 4) = make_uint4(u[4], u[5], u[6], u[7]);
        return;
    }

    int cell = blockIdx.x - 64;           // 0..224
    int a = cell / 15, bcol = cell % 15;
    float ra = (a - 7) * (8.0f / 7.0f);
    float rb = (bcol - 7) * (8.0f / 7.0f);
    float va = (ra >= 0.f ? 1.f : -1.f) * log2f(fabsf(ra) + 1.f) * (1.f / 3.f);
    float vb = (rb >= 0.f ? 1.f : -1.f) * log2f(fabsf(rb) + 1.f) * (1.f / 3.f);

    int j1 = t, j2 = t + 256;
    float h1 = fmaxf(va * w1[j1 * 2] + vb * w1[j1 * 2 + 1] + b1[j1], 0.f);
    float h2 = fmaxf(va * w1[j2 * 2] + vb * w1[j2 * 2 + 1] + b1[j2], 0.f);

    float p[8];
#pragma unroll
    for (int h = 0; h < 8; h++)
        p[h] = h1 * w2[h * 512 + j1] + h2 * w2[h * 512 + j2];
#pragma unroll
    for (int h = 0; h < 8; h++)
#pragma unroll
        for (int off = 16; off; off >>= 1)
            p[h] += __shfl_xor_sync(0xffffffffu, p[h], off);

    int warp = t >> 5, lane = t & 31;
    if (lane == 0) {
#pragma unroll
        for (int h = 0; h < 8; h++) ws[warp][h] = p[h];
    }
    __syncthreads();
    if (t < 8) {
        float s = 0.f;
#pragma unroll
        for (int w = 0; w < 8; w++) s += ws[w][t];
        bv[t] = 16.f / (1.f + expf(-s));
    }
    __syncthreads();

    int da = a - 7, db = bcol - 7;
    int cntA = 8 - abs(da), cntB = 8 - abs(db);
    int rn0 = da > 0 ? da : 0, cn0 = db > 0 ? db : 0;
    int total = cntA * cntB * 32;
    for (int idx = t; idx < total; idx += 256) {
        int tmp = idx;
        int h = tmp & 7; tmp >>= 3;
        int wt_ = tmp & 3; tmp >>= 2;
        int pa = tmp / cntB, pb = tmp - pa * cntB;
        int rn = rn0 + pa, cn = cn0 + pb;
        int rm = rn - da, cm = cn - db;
        int wh = wt_ >> 1, ww = wt_ & 1;
        int ghn = wh * 8 + rn, gwn = ww * 8 + cn;
        int ghm = wh * 8 + rm, gwm = ww * 8 + cm;
        int gn = ((ghn < 8) ? 0 : (ghn < 12 ? 1 : 2)) * 3 + ((gwn < 8) ? 0 : (gwn < 12 ? 1 : 2));
        int gm = ((ghm < 8) ? 0 : (ghm < 12 ? 1 : 2)) * 3 + ((gwm < 8) ? 0 : (gwm < 12 ? 1 : 2));
        float val = (gn == gm) ? bv[h] : -1e30f;
        g_bias[((wt_ * 8 + h) * 64 + rn * 8 + cn) * 64 + rm * 8 + cm] = val;
    }
}

// ---- one 16-wide k-chunk, 16x64 warp tile (16 MMAs, hi then lo sweep) ----
#define PROJ_CHUNK(B, kc)                                                     \
    do {                                                                      \
        const uint32_t* a_ = ap + (kc) * 16;                                  \
        const uint4 A0 = *reinterpret_cast<const uint4*>(a_);                 \
        const uint4 A1 = *reinterpret_cast<const uint4*>(a_ + 8 * XSTR);      \
        _Pragma("unroll")                                                     \
        for (int nf = 0; nf < 8; nf++)                                        \
            MMAH(acc[nf], A0.x, A1.x, A0.y, A1.y, B[nf].x, B[nf].y);          \
        _Pragma("unroll")                                                     \
        for (int nf = 0; nf < 8; nf++)                                        \
            MMAH(acc[nf], A0.z, A1.z, A0.w, A1.w, B[nf].x, B[nf].y);          \
    } while (0)

#define PROJ_LD(B, c)                                                         \
    do {                                                                      \
        _Pragma("unroll")                                                     \
        for (int nf = 0; nf < 8; nf++) B[nf] = __ldg(gb + (c) * 1024 + nf * 32); \
    } while (0)

// ---------------------------------------------------------------------------
// Projection GEMM (2-term): out(64x256) = A(F4 smem) @ Whi^T. Warp 16x64.
// ---------------------------------------------------------------------------
__device__ __forceinline__ void gemm_proj(
    const uint32_t* __restrict__ src, const uint32_t* __restrict__ gw,
    float acc[8][4], int rbase, int warpN, int gid, int tg)
{
#pragma unroll
    for (int nf = 0; nf < 8; nf++)
#pragma unroll
        for (int j = 0; j < 4; j++) acc[nf][j] = 0.f;

    const uint2* gb = reinterpret_cast<const uint2*>(gw) + (warpN * 64 + gid) * 4 + tg;
    const uint32_t* ap = src + (rbase + gid) * XSTR + tg * 4;

    uint2 Ba[8], Bb[8];
    PROJ_LD(Ba, 0);

#pragma unroll 1
    for (int it = 0; it < 8; it++) {
        PROJ_LD(Bb, 2 * it + 1);
        PROJ_CHUNK(Ba, 2 * it);
        if (it < 7) PROJ_LD(Ba, 2 * it + 2);
        PROJ_CHUNK(Bb, 2 * it + 1);
    }
}

// ---- VT chunk: 16 d-rows x 64 tokens, 16 MMAs (hi sweep then lo sweep) ----
#define VT_CHUNK(W, kc)                                                       \
    do {                                                                      \
        const uint32_t* xp = xp0 + (kc) * 16;                                 \
        uint4 Xv[8];                                                          \
        _Pragma("unroll")                                                     \
        for (int nf = 0; nf < 8; nf++)                                        \
            Xv[nf] = *reinterpret_cast<const uint4*>(xp + nf * 8 * XSTR);     \
        _Pragma("unroll")                                                     \
        for (int nf = 0; nf < 8; nf++)                                        \
            MMAH(av[nf], W[0].x, W[1].x, W[0].y, W[1].y, Xv[nf].x, Xv[nf].y); \
        _Pragma("unroll")                                                     \
        for (int nf = 0; nf < 8; nf++)                                        \
            MMAH(av[nf], W[0].x, W[1].x, W[0].y, W[1].y, Xv[nf].z, Xv[nf].w); \
    } while (0)

#define VT_LD(W, c)                                                           \
    do {                                                                      \
        W[0] = __ldg(ga + (c) * 1024);                                        \
        W[1] = __ldg(ga + (c) * 1024 + 32);                                   \
    } while (0)

// ---------------------------------------------------------------------------
// VT GEMM (2-term): VT(256x64) = Wv_hi @ x^T. Warp: 16 d-rows. Ends barrier.
// ---------------------------------------------------------------------------
__device__ __forceinline__ void gemm_vt(
    const uint32_t* __restrict__ x, const uint32_t* __restrict__ gw,
    float av[8][4], int warp, int gid, int tg)
{
#pragma unroll
    for (int nf = 0; nf < 8; nf++)
#pragma unroll
        for (int j = 0; j < 4; j++) av[nf][j] = 0.f;

    const uint2* ga = reinterpret_cast<const uint2*>(gw) + (warp * 16 + gid) * 4 + tg;
    const uint32_t* xp0 = x + gid * XSTR + tg * 4;

    uint2 Wa[2], Wb[2];
    VT_LD(Wa, 0);

#pragma unroll 1
    for (int it = 0; it < 8; it++) {
        VT_LD(Wb, 2 * it + 1);
        VT_CHUNK(Wa, 2 * it);
        if (it < 7) VT_LD(Wa, 2 * it + 2);
        VT_CHUNK(Wb, 2 * it + 1);
    }
    __syncthreads();   // all X reads complete before VTS overwrite
}

// ---------------------------------------------------------------------------
__global__ __launch_bounds__(512, 1)
void swin_kernel(const float* __restrict__ img,
                 const float* __restrict__ bq, const float* __restrict__ bk,
                 const float* __restrict__ bv, const float* __restrict__ bo,
                 const float* __restrict__ ls,
                 float* __restrict__ out)
{
    extern __shared__ uint32_t smu[];
    uint32_t* X   = smu + OFF_X;
    uint32_t* QS  = smu + OFF_Q;
    uint32_t* KS  = smu + OFF_K;
    uint32_t* VTS = smu + OFF_X;        // overlays X after V gemm

    const int t    = threadIdx.x;
    const int lane = t & 31;
    const int warp = t >> 5;            // 0..15
    const int warpM = warp & 3, warpN = warp >> 2;
    const int gid = lane >> 2, tg = lane & 3;
    const int blk = blockIdx.x;
    const int b   = blk >> 2;
    const int wh  = (blk >> 1) & 1, ww = blk & 1;
    const int wtype = blk & 3;

    // ---- load shifted window -> x F4 split (fp16 hi/lo)
    const float* imgb = img + (size_t)b * (16 * 16 * 256);
#pragma unroll
    for (int i = 0; i < 8; i++) {
        int f = i * 512 + t;            // float4 index
        int tok = f >> 6, c4 = f & 63;
        int r = tok >> 3, c = tok & 7;
        int ih = (wh * 8 + r + 12) & 15;
        int iw = (ww * 8 + c + 12) & 15;
        float4 v = *reinterpret_cast<const float4*>(&imgb[(ih * 16 + iw) * 256 + c4 * 4]);
        uint32_t h0, l0, h1, l1;
        split2h(v.x, v.y, h0, l0);
        split2h(v.z, v.w, h1, l1);
        int p0 = 2 * c4;
        int g = p0 >> 3, pos = p0 & 7;
        int tgs = pos & 3, slot = pos >> 2;
        uint32_t* base = X + tok * XSTR + g * 16 + slot;
        base[tgs * 4]           = h0;
        base[(tgs + 1) * 4]     = h1;
        base[tgs * 4 + 2]       = l0;
        base[(tgs + 1) * 4 + 2] = l1;
    }
    __syncthreads();   // X visible to all warps

    float acc[8][4];
    const int rbase = warpM * 16;
    const int r0w = rbase + gid, r1w = r0w + 8;

    // ---- Q = x wq^T + bq, cosine-normalize * scale, split -> QS
    gemm_proj(X, g_wh + 0 * 32768, acc, rbase, warpN, gid, tg);
    {
#pragma unroll
        for (int nf = 0; nf < 8; nf++) {
            float2 bb = *reinterpret_cast<const float2*>(bq + warpN * 64 + nf * 8 + 2 * tg);
            acc[nf][0] += bb.x; acc[nf][1] += bb.y;
            acc[nf][2] += bb.x; acc[nf][3] += bb.y;
        }
#pragma unroll
        for (int g = 0; g < 2; g++) {
            float ss0 = 0.f, ss1 = 0.f;
#pragma unroll
            for (int i = 0; i < 4; i++) {
                float* C = acc[4*g+i];
                ss0 += C[0]*C[0] + C[1]*C[1];
                ss1 += C[2]*C[2] + C[3]*C[3];
            }
            ss0 += __shfl_xor_sync(0xffffffffu, ss0, 1);
            ss0 += __shfl_xor_sync(0xffffffffu, ss0, 2);
            ss1 += __shfl_xor_sync(0xffffffffu, ss1, 1);
            ss1 += __shfl_xor_sync(0xffffffffu, ss1, 2);
            float sc = __expf(fminf(ls[warpN * 2 + g], 4.6051702f));
            float k0 = sc * rsqrtf(fmaxf(ss0, 1e-24f));
            float k1 = sc * rsqrtf(fmaxf(ss1, 1e-24f));
#pragma unroll
            for (int u = 0; u < 2; u++) {
                int ne = 4*g + 2*u, no = ne + 1;
                int ch = warpN * 4 + 2*g + u;
                uint32_t He, Le, Ho, Lo;
                split2h(acc[ne][0]*k0, acc[ne][1]*k0, He, Le);
                split2h(acc[no][0]*k0, acc[no][1]*k0, Ho, Lo);
                *reinterpret_cast<uint4*>(QS + r0w*XSTR + ch*16 + tg*4) = make_uint4(He, Ho, Le, Lo);
                split2h(acc[ne][2]*k1, acc[ne][3]*k1, He, Le);
                split2h(acc[no][2]*k1, acc[no][3]*k1, Ho, Lo);
                *reinterpret_cast<uint4*>(QS + r1w*XSTR + ch*16 + tg*4) = make_uint4(He, Ho, Le, Lo);
            }
        }
    }

    // ---- K = x wk^T + bk, normalize, split -> KS
    gemm_proj(X, g_wh + 1 * 32768, acc, rbase, warpN, gid, tg);
    {
#pragma unroll
        for (int nf = 0; nf < 8; nf++) {
            float2 bb = *reinterpret_cast<const float2*>(bk + warpN * 64 + nf * 8 + 2 * tg);
            acc[nf][0] += bb.x; acc[nf][1] += bb.y;
            acc[nf][2] += bb.x; acc[nf][3] += bb.y;
        }
#pragma unroll
        for (int g = 0; g < 2; g++) {
            float ss0 = 0.f, ss1 = 0.f;
#pragma unroll
            for (int i = 0; i < 4; i++) {
                float* C = acc[4*g+i];
                ss0 += C[0]*C[0] + C[1]*C[1];
                ss1 += C[2]*C[2] + C[3]*C[3];
            }
            ss0 += __shfl_xor_sync(0xffffffffu, ss0, 1);
            ss0 += __shfl_xor_sync(0xffffffffu, ss0, 2);
            ss1 += __shfl_xor_sync(0xffffffffu, ss1, 1);
            ss1 += __shfl_xor_sync(0xffffffffu, ss1, 2);
            float k0 = rsqrtf(fmaxf(ss0, 1e-24f));
            float k1 = rsqrtf(fmaxf(ss1, 1e-24f));
#pragma unroll
            for (int u = 0; u < 2; u++) {
                int ne = 4*g + 2*u, no = ne + 1;
                int ch = warpN * 4 + 2*g + u;
                uint32_t He, Le, Ho, Lo;
                split2h(acc[ne][0]*k0, acc[ne][1]*k0, He, Le);
                split2h(acc[no][0]*k0, acc[no][1]*k0, Ho, Lo);
                *reinterpret_cast<uint4*>(KS + r0w*XSTR + ch*16 + tg*4) = make_uint4(He, Ho, Le, Lo);
                split2h(acc[ne][2]*k1, acc[ne][3]*k1, He, Le);
                split2h(acc[no][2]*k1, acc[no][3]*k1, Ho, Lo);
                *reinterpret_cast<uint4*>(KS + r1w*XSTR + ch*16 + tg*4) = make_uint4(He, Ho, Le, Lo);
            }
        }
    }

    // ---- VT = wv x^T + bv (transposed V), F4 split -> VTS (overlays X)
    {
        float av[8][4];
        gemm_vt(X, g_wh + 2 * 32768, av, warp, gid, tg);
        int d0 = warp * 16 + gid, d1 = d0 + 8;
        float bv0 = bv[d0], bv1 = bv[d1];
#pragma unroll
        for (int kp = 0; kp < 4; kp++) {
            int ne = 2 * kp, no = ne + 1;
            uint32_t e0, f0, e1, f1;
            split2h(av[ne][0] + bv0, av[ne][1] + bv0, e0, f0);
            split2h(av[no][0] + bv0, av[no][1] + bv0, e1, f1);
            *reinterpret_cast<uint4*>(VTS + d0 * VSTR + ((kp + d0) & 3) * 16 + tg * 4) =
                make_uint4(e0, e1, f0, f1);
            split2h(av[ne][2] + bv1, av[ne][3] + bv1, e0, f0);
            split2h(av[no][2] + bv1, av[no][3] + bv1, e1, f1);
            *reinterpret_cast<uint4*>(VTS + d1 * VSTR + ((kp + d1) & 3) * 16 + tg * 4) =
                make_uint4(e0, e1, f0, f1);
        }
    }
    __syncthreads();   // QS/KS/VTS all visible before attention

    // ---- attention: warp = (half, head). Each warp: 2 mt tiles of 16 rows.
    //      S via MMA (3-term); precomputed masked bias LDG; softmax norm
    //      deferred past PV MMAs.
    {
        const int h = warp & 7;
        const int half = warp >> 3;
        const float NEG_INF = __int_as_float(0xff800000);
        const float* bias = g_bias + (wtype * 8 + h) * 4096;

#pragma unroll 1
        for (int i = 0; i < 2; i++) {
            const int mt = half * 2 + i;
            int r0 = mt * 16 + gid, r1 = r0 + 8;
            float2 PB0[8], PB1[8];
#pragma unroll
            for (int nt = 0; nt < 8; nt++) {
                PB0[nt] = *reinterpret_cast<const float2*>(bias + r0 * 64 + nt * 8 + 2 * tg);
                PB1[nt] = *reinterpret_cast<const float2*>(bias + r1 * 64 + nt * 8 + 2 * tg);
            }
            float S[8][4];
#pragma unroll
            for (int nt = 0; nt < 8; nt++)
#pragma unroll
                for (int j = 0; j < 4; j++) S[nt][j] = 0.f;
#pragma unroll
            for (int kc = 0; kc < 2; kc++) {
                const uint4 A0 = *reinterpret_cast<const uint4*>(
                    QS + r0 * XSTR + (2 * h + kc) * 16 + tg * 4);
                const uint4 A1 = *reinterpret_cast<const uint4*>(
                    QS + r1 * XSTR + (2 * h + kc) * 16 + tg * 4);
#pragma unroll
                for (int gq = 0; gq < 2; gq++) {
                    uint4 Bv[4];
#pragma unroll
                    for (int j = 0; j < 4; j++)
                        Bv[j] = *reinterpret_cast<const uint4*>(
                            KS + ((gq * 4 + j) * 8 + gid) * XSTR + (2 * h + kc) * 16 + tg * 4);
#pragma unroll
                    for (int j = 0; j < 4; j++)
                        MMAH(S[gq*4+j], A0.x, A1.x, A0.y, A1.y, Bv[j].x, Bv[j].y);
#pragma unroll
                    for (int j = 0; j < 4; j++)
                        MMAH(S[gq*4+j], A0.z, A1.z, A0.w, A1.w, Bv[j].x, Bv[j].y);
#pragma unroll
                    for (int j = 0; j < 4; j++)
                        MMAH(S[gq*4+j], A0.x, A1.x, A0.y, A1.y, Bv[j].z, Bv[j].w);
                }
            }
            float mx0 = NEG_INF, mx1 = NEG_INF;
#pragma unroll
            for (int nt = 0; nt < 8; nt++) {
                S[nt][0] += PB0[nt].x;
                S[nt][1] += PB0[nt].y;
                S[nt][2] += PB1[nt].x;
                S[nt][3] += PB1[nt].y;
                mx0 = fmaxf(mx0, fmaxf(S[nt][0], S[nt][1]));
                mx1 = fmaxf(mx1, fmaxf(S[nt][2], S[nt][3]));
            }
            mx0 = fmaxf(mx0, __shfl_xor_sync(0xffffffffu, mx0, 1));
            mx0 = fmaxf(mx0, __shfl_xor_sync(0xffffffffu, mx0, 2));
            mx1 = fmaxf(mx1, __shfl_xor_sync(0xffffffffu, mx1, 1));
            mx1 = fmaxf(mx1, __shfl_xor_sync(0xffffffffu, mx1, 2));
            float s0 = 0.f, s1 = 0.f;
#pragma unroll
            for (int nt = 0; nt < 8; nt++) {
                S[nt][0] = __expf(S[nt][0] - mx0); s0 += S[nt][0];
                S[nt][1] = __expf(S[nt][1] - mx0); s0 += S[nt][1];
                S[nt][2] = __expf(S[nt][2] - mx1); s1 += S[nt][2];
                S[nt][3] = __expf(S[nt][3] - mx1); s1 += S[nt][3];
            }
            // split UNNORMALIZED P; PV proceeds while the sum reduces
            uint32_t ph0[8], ph1[8], pl0[8], pl1[8];
#pragma unroll
            for (int nt = 0; nt < 8; nt++) {
                split2h(S[nt][0], S[nt][1], ph0[nt], pl0[nt]);
                split2h(S[nt][2], S[nt][3], ph1[nt], pl1[nt]);
            }
            float O[4][4];
#pragma unroll
            for (int dt = 0; dt < 4; dt++)
#pragma unroll
                for (int j = 0; j < 4; j++) O[dt][j] = 0.f;
#pragma unroll
            for (int kp = 0; kp < 4; kp++) {
                uint32_t ah0 = ph0[2*kp], ah1 = ph1[2*kp], ah2 = ph0[2*kp+1], ah3 = ph1[2*kp+1];
                uint32_t al0 = pl0[2*kp], al1 = pl1[2*kp], al2 = pl0[2*kp+1], al3 = pl1[2*kp+1];
                uint4 Bv[4];
#pragma unroll
                for (int dt = 0; dt < 4; dt++) {
                    int d = h * 32 + dt * 8 + gid;
                    Bv[dt] = *reinterpret_cast<const uint4*>(
                        VTS + d * VSTR + ((kp + d) & 3) * 16 + tg * 4);
                }
#pragma unroll
                for (int dt = 0; dt < 4; dt++)
                    MMAH(O[dt], ah0, ah1, ah2, ah3, Bv[dt].x, Bv[dt].y);
#pragma unroll
                for (int dt = 0; dt < 4; dt++)
                    MMAH(O[dt], al0, al1, al2, al3, Bv[dt].x, Bv[dt].y);
#pragma unroll
                for (int dt = 0; dt < 4; dt++)
                    MMAH(O[dt], ah0, ah1, ah2, ah3, Bv[dt].z, Bv[dt].w);
            }
            s0 += __shfl_xor_sync(0xffffffffu, s0, 1);
            s0 += __shfl_xor_sync(0xffffffffu, s0, 2);
            s1 += __shfl_xor_sync(0xffffffffu, s1, 1);
            s1 += __shfl_xor_sync(0xffffffffu, s1, 2);
            float inv0 = 1.f / s0, inv1 = 1.f / s1;
#pragma unroll
            for (int dt = 0; dt < 4; dt++) {
                O[dt][0] *= inv0; O[dt][1] *= inv0;
                O[dt][2] *= inv1; O[dt][3] *= inv1;
            }
            // store O (F4) into QS chunks 2h/2h+1 (head-private cols, rows r0/r1)
#pragma unroll
            for (int gg = 0; gg < 2; gg++) {
                uint32_t e0, f0, e1, f1;
                split2h(O[2*gg][0], O[2*gg][1], e0, f0);
                split2h(O[2*gg+1][0], O[2*gg+1][1], e1, f1);
                *reinterpret_cast<uint4*>(QS + r0 * XSTR + (2*h + gg) * 16 + tg * 4) =
                    make_uint4(e0, e1, f0, f1);
                split2h(O[2*gg][2], O[2*gg][3], e0, f0);
                split2h(O[2*gg+1][2], O[2*gg+1][3], e1, f1);
                *reinterpret_cast<uint4*>(QS + r1 * XSTR + (2*h + gg) * 16 + tg * 4) =
                    make_uint4(e0, e1, f0, f1);
            }
        }
    }
    __syncthreads();   // O (in QS) visible before Z gemm

    // ---- Z = O wo^T + bo -> global with inverse cyclic shift
    gemm_proj(QS, g_wh + 3 * 32768, acc, rbase, warpN, gid, tg);
    {
#pragma unroll
        for (int i = 0; i < 2; i++) {
            int r = rbase + i * 8 + gid;
            int rr = r >> 3, cc = r & 7;
            int oh = (wh * 8 + rr + 12) & 15, ow = (ww * 8 + cc + 12) & 15;
            float* d = out + ((size_t)(b * 16 + oh) * 16 + ow) * 256;
#pragma unroll
            for (int nf = 0; nf < 8; nf++) {
                int c = warpN * 64 + nf * 8 + 2 * tg;
                float2 bb = *reinterpret_cast<const float2*>(bo + c);
                float2 z = {acc[nf][i*2] + bb.x, acc[nf][i*2+1] + bb.y};
                *reinterpret_cast<float2*>(d + c) = z;
            }
        }
    }
}

// ---------------------------------------------------------------------------
extern "C" void kernel_launch(void* const* d_in, const int* in_sizes, int n_in,
                              void* d_out, int out_size)
{
    const float* img = (const float*)d_in[0];
    const float* wq  = (const float*)d_in[1];
    const float* bq  = (const float*)d_in[2];
    const float* wk  = (const float*)d_in[3];
    const float* bk  = (const float*)d_in[4];
    const float* wv  = (const float*)d_in[5];
    const float* bv  = (const float*)d_in[6];
    const float* wo  = (const float*)d_in[7];
    const float* bo  = (const float*)d_in[8];
    const float* ls  = (const float*)d_in[9];
    const float* cw1 = (const float*)d_in[10];
    const float* cb1 = (const float*)d_in[11];
    const float* cw2 = (const float*)d_in[12];
    (void)in_sizes; (void)n_in; (void)out_size;

    cudaFuncSetAttribute(swin_kernel,
                         cudaFuncAttributeMaxDynamicSharedMemorySize,
                         SMEM_U32 * 4);

    prep_kernel<<<289, 256>>>(cw1, cb1, cw2, wq, wk, wv, wo);
    swin_kernel<<<2048, 512, SMEM_U32 * 4>>>(img, bq, bk, bv, bo, ls,
                                             (float*)d_out);
}